// round 8
// baseline (speedup 1.0000x reference)
#include <cuda_runtime.h>
#include <cuda_bf16.h>

#define Bb 8
#define Nn 1024
#define Ee 512
#define Hh 8
#define Dd 64
#define NEGV -1000000000.0f
#define SCL2 0.1803368801111204f   // 0.125 * log2(e)

typedef unsigned long long u64;
typedef unsigned int u32;

// ---------------------------------------------------------------------------
// Scratch (device globals; referenced only from device code)
// ---------------------------------------------------------------------------
__device__ unsigned char g_code[Bb*Nn*Nn];

__device__ __nv_bfloat16 gXh[3][Bb*Nn*Ee];
__device__ __nv_bfloat16 gXl[3][Bb*Nn*Ee];
__device__ __nv_bfloat16 gWh[4][Ee*Ee];
__device__ __nv_bfloat16 gWl[4][Ee*Ee];

__device__ __nv_bfloat16 gQh[Bb*Hh*Nn*Dd];
__device__ __nv_bfloat16 gQl[Bb*Hh*Nn*Dd];
__device__ __nv_bfloat16 gKh[Bb*Hh*Nn*Dd];
__device__ __nv_bfloat16 gKl[Bb*Hh*Nn*Dd];
__device__ __nv_bfloat16 gVth[Bb*Hh*Dd*Nn];  // V transposed [b,h,d,n]
__device__ __nv_bfloat16 gVtl[Bb*Hh*Dd*Nn];
__device__ __nv_bfloat16 gAh[Bb*Nn*Ee];
__device__ __nv_bfloat16 gAl[Bb*Nn*Ee];

// ---------------------------------------------------------------------------
// PTX helpers
// ---------------------------------------------------------------------------
__device__ __forceinline__ unsigned smem_u32(const void* p) {
    unsigned a;
    asm("{ .reg .u64 t; cvta.to.shared.u64 t, %1; cvt.u32.u64 %0, t; }"
        : "=r"(a) : "l"(p));
    return a;
}
__device__ __forceinline__ void cpasync16(unsigned dst, const void* src) {
    asm volatile("cp.async.ca.shared.global [%0], [%1], 16;" :: "r"(dst), "l"(src));
}
__device__ __forceinline__ void cpcommit() {
    asm volatile("cp.async.commit_group;" ::: "memory");
}
template<int N> __device__ __forceinline__ void cpwait() {
    asm volatile("cp.async.wait_group %0;" :: "n"(N) : "memory");
}
__device__ __forceinline__ void mma16816(float* c, const u32* a, const u32* b) {
    asm volatile("mma.sync.aligned.m16n8k16.row.col.f32.bf16.bf16.f32 "
        "{%0,%1,%2,%3}, {%4,%5,%6,%7}, {%8,%9}, {%0,%1,%2,%3};"
        : "+f"(c[0]), "+f"(c[1]), "+f"(c[2]), "+f"(c[3])
        : "r"(a[0]), "r"(a[1]), "r"(a[2]), "r"(a[3]), "r"(b[0]), "r"(b[1]));
}
__device__ __forceinline__ void ldsm_x4(u32* r, unsigned addr) {
    asm volatile("ldmatrix.sync.aligned.m8n8.x4.shared.b16 {%0,%1,%2,%3}, [%4];"
        : "=r"(r[0]), "=r"(r[1]), "=r"(r[2]), "=r"(r[3]) : "r"(addr));
}
__device__ __forceinline__ float ex2(float x) {
    float y; asm("ex2.approx.f32 %0, %1;" : "=f"(y) : "f"(x)); return y;
}
__device__ __forceinline__ u32 packbf(float lo, float hi) {
    __nv_bfloat162 t = __floats2bfloat162_rn(lo, hi);
    return *(u32*)&t;
}
__device__ __forceinline__ float lo_f(u32 v) { return __uint_as_float(v << 16); }
__device__ __forceinline__ float hi_f(u32 v) { return __uint_as_float(v & 0xffff0000u); }

// ---------------------------------------------------------------------------
// Mask precompute
// ---------------------------------------------------------------------------
__device__ __forceinline__ unsigned char code_one(float d, int mk, int i, int j) {
    if (mk == 0) return (unsigned char)255;
    if (i == 0 || j == 0) return (unsigned char)0;
    unsigned char c = 0;
    c += (d >= 0.2f); c += (d >= 0.3f); c += (d >= 0.4f); c += (d >= 0.5f);
    c += (d >= 0.6f); c += (d >= 0.7f); c += (d >= 0.8f); c += (d >= 0.9f);
    return c;
}

__global__ __launch_bounds__(256) void code_kernel(const float* __restrict__ dist,
                                                   const int* __restrict__ mask) {
    int t = blockIdx.x * blockDim.x + threadIdx.x;
    int base = t * 4;
    int rem = base & (Nn*Nn - 1);
    int i = rem >> 10;
    int j0 = rem & (Nn - 1);
    float4 dv = *(const float4*)(dist + base);
    int4  mv = *(const int4*)(mask + base);
    uchar4 o;
    o.x = code_one(dv.x, mv.x, i, j0 + 0);
    o.y = code_one(dv.y, mv.y, i, j0 + 1);
    o.z = code_one(dv.z, mv.z, i, j0 + 2);
    o.w = code_one(dv.w, mv.w, i, j0 + 3);
    *(uchar4*)(g_code + base) = o;
}

// ---------------------------------------------------------------------------
// fp32 -> bf16 hi/lo splits
// ---------------------------------------------------------------------------
__device__ __forceinline__ void split_store(float4 v, __nv_bfloat16* hp,
                                            __nv_bfloat16* lp, int t) {
    u32* h2 = (u32*)hp;
    u32* l2 = (u32*)lp;
    u32 hxy = packbf(v.x, v.y), hzw = packbf(v.z, v.w);
    h2[2*t+0] = hxy;
    h2[2*t+1] = hzw;
    l2[2*t+0] = packbf(v.x - lo_f(hxy), v.y - hi_f(hxy));
    l2[2*t+1] = packbf(v.z - lo_f(hzw), v.w - hi_f(hzw));
}

__global__ __launch_bounds__(256) void split_x_kernel(const float* __restrict__ s0,
                                                      const float* __restrict__ s1,
                                                      const float* __restrict__ s2) {
    int which = blockIdx.y;
    const float* src = (which == 0) ? s0 : (which == 1) ? s1 : s2;
    int t = blockIdx.x * blockDim.x + threadIdx.x;
    float4 v = ((const float4*)src)[t];
    split_store(v, gXh[which], gXl[which], t);
}

__global__ __launch_bounds__(256) void split_w_kernel(const float* __restrict__ s0,
                                                      const float* __restrict__ s1,
                                                      const float* __restrict__ s2,
                                                      const float* __restrict__ s3) {
    int which = blockIdx.y;
    const float* src = (which == 0) ? s0 : (which == 1) ? s1
                      : (which == 2) ? s2 : s3;
    int t = blockIdx.x * blockDim.x + threadIdx.x;
    float4 v = ((const float4*)src)[t];
    split_store(v, gWh[which], gWl[which], t);
}

// ---------------------------------------------------------------------------
// HMMA split-bf16 GEMM (single-sync 2-stage pipeline, x4 ldsm for W)
// ---------------------------------------------------------------------------
#define TSTRIDE 40
#define TILE_US (128 * TSTRIDE)
#define WOFF_US (4 * TILE_US)
#define GEMM_SMEM_BYTES (8 * TILE_US * 2)

__global__ __launch_bounds__(256, 2) void gemm_mma(const float* __restrict__ bias0,
                                                   const float* __restrict__ bias1,
                                                   const float* __restrict__ bias2,
                                                   float* __restrict__ outext,
                                                   int fused) {
    extern __shared__ unsigned short gsm[];
    unsigned sbase = smem_u32(gsm);

    int sel = fused ? blockIdx.z : 3;
    const __nv_bfloat16* Ahg = (sel < 3) ? gXh[sel] : gAh;
    const __nv_bfloat16* Alg = (sel < 3) ? gXl[sel] : gAl;
    const __nv_bfloat16* Whg = gWh[sel];
    const __nv_bfloat16* Wlg = gWl[sel];
    const float* bias = (sel == 0 || sel == 3) ? bias0 : (sel == 1) ? bias1 : bias2;
    int out_mode = sel;

    int tid = threadIdx.x;
    int wid = tid >> 5, lane = tid & 31;
    int wr = wid >> 2, wc = wid & 3;
    int gid = lane >> 2, tig = lane & 3;
    int m0 = blockIdx.x * 128, n0 = blockIdx.y * 128;

    int id0 = tid, id1 = 256 + tid;
    int r0 = id0 >> 2, c80 = (id0 & 3) * 8;
    int r1 = id1 >> 2, c81 = (id1 & 3) * 8;

    // ldmatrix lane address components
    int rA   = lane & 15, kA = (lane >> 4) * 8;            // A x4
    int ntl8 = ((lane >> 4) & 1) * 8 + (lane & 7);         // B x4 (nt-pair)
    int kB4  = ((lane >> 3) & 1) * 8;

    float c[4][4][4];
    #pragma unroll
    for (int mt = 0; mt < 4; mt++)
        #pragma unroll
        for (int nt = 0; nt < 4; nt++)
            #pragma unroll
            for (int q = 0; q < 4; q++) c[mt][nt][q] = 0.0f;

    auto load_chunk = [&](int kc, int buf) {
        int kb = kc * 32;
        {
            int a0 = (m0 + r0) * Ee + kb + c80;
            int a1 = (m0 + r1) * Ee + kb + c81;
            unsigned d0 = sbase + ((buf * 2 + 0) * TILE_US + r0 * TSTRIDE + c80) * 2;
            unsigned d1 = sbase + ((buf * 2 + 0) * TILE_US + r1 * TSTRIDE + c81) * 2;
            unsigned e0 = sbase + ((buf * 2 + 1) * TILE_US + r0 * TSTRIDE + c80) * 2;
            unsigned e1 = sbase + ((buf * 2 + 1) * TILE_US + r1 * TSTRIDE + c81) * 2;
            cpasync16(d0, Ahg + a0); cpasync16(d1, Ahg + a1);
            cpasync16(e0, Alg + a0); cpasync16(e1, Alg + a1);
        }
        {
            int w0 = (n0 + r0) * Ee + kb + c80;
            int w1 = (n0 + r1) * Ee + kb + c81;
            unsigned d0 = sbase + (WOFF_US + (buf * 2 + 0) * TILE_US + r0 * TSTRIDE + c80) * 2;
            unsigned d1 = sbase + (WOFF_US + (buf * 2 + 0) * TILE_US + r1 * TSTRIDE + c81) * 2;
            unsigned e0 = sbase + (WOFF_US + (buf * 2 + 1) * TILE_US + r0 * TSTRIDE + c80) * 2;
            unsigned e1 = sbase + (WOFF_US + (buf * 2 + 1) * TILE_US + r1 * TSTRIDE + c81) * 2;
            cpasync16(d0, Whg + w0); cpasync16(d1, Whg + w1);
            cpasync16(e0, Wlg + w0); cpasync16(e1, Wlg + w1);
        }
        cpcommit();
    };

    load_chunk(0, 0);

    for (int kc = 0; kc < 16; kc++) {
        int buf = kc & 1;
        cpwait<0>();
        __syncthreads();
        if (kc < 15) load_chunk(kc + 1, buf ^ 1);   // overlaps compute below

        unsigned ah_b = sbase + ((buf * 2 + 0) * TILE_US) * 2;
        unsigned al_b = sbase + ((buf * 2 + 1) * TILE_US) * 2;
        unsigned wh_b = sbase + ((WOFF_US + (buf * 2 + 0) * TILE_US)) * 2;
        unsigned wl_b = sbase + ((WOFF_US + (buf * 2 + 1) * TILE_US)) * 2;

        #pragma unroll
        for (int ks = 0; ks < 2; ks++) {
            int k0 = ks * 16;
            u32 bh[4][2], bl[4][2];
            #pragma unroll
            for (int p = 0; p < 2; p++) {
                unsigned boff = ((wc * 32 + p * 16 + ntl8) * TSTRIDE + k0 + kB4) * 2;
                u32 t4[4];
                ldsm_x4(t4, wh_b + boff);
                bh[2*p][0] = t4[0]; bh[2*p][1] = t4[1];
                bh[2*p+1][0] = t4[2]; bh[2*p+1][1] = t4[3];
                ldsm_x4(t4, wl_b + boff);
                bl[2*p][0] = t4[0]; bl[2*p][1] = t4[1];
                bl[2*p+1][0] = t4[2]; bl[2*p+1][1] = t4[3];
            }
            #pragma unroll
            for (int mt = 0; mt < 4; mt++) {
                unsigned aoff = ((wr * 64 + mt * 16 + rA) * TSTRIDE + k0 + kA) * 2;
                u32 ah[4], al[4];
                ldsm_x4(ah, ah_b + aoff);
                ldsm_x4(al, al_b + aoff);
                #pragma unroll
                for (int nt = 0; nt < 4; nt++) {
                    mma16816(c[mt][nt], ah, bh[nt]);
                    mma16816(c[mt][nt], ah, bl[nt]);
                    mma16816(c[mt][nt], al, bh[nt]);
                }
            }
        }
    }

    // Epilogue
    #pragma unroll
    for (int mt = 0; mt < 4; mt++) {
        #pragma unroll
        for (int nt = 0; nt < 4; nt++) {
            int row = m0 + wr * 64 + mt * 16 + gid;
            int col = n0 + wc * 32 + nt * 8 + tig * 2;
            float b0v = bias[col], b1v = bias[col + 1];
            float v00 = c[mt][nt][0] + b0v, v01 = c[mt][nt][1] + b1v;
            float v10 = c[mt][nt][2] + b0v, v11 = c[mt][nt][3] + b1v;
            int b_ = row >> 10, n = row & (Nn - 1);
            int hh = col >> 6, d = col & 63;
            if (out_mode <= 1) {
                __nv_bfloat16* Hp = (out_mode == 0) ? gQh : gKh;
                __nv_bfloat16* Lp = (out_mode == 0) ? gQl : gKl;
                int a0 = (((b_ << 3) + hh) * Nn + n) * Dd + d;
                int a1 = a0 + 8 * Dd;
                u32 h0 = packbf(v00, v01), h1 = packbf(v10, v11);
                *(u32*)(Hp + a0) = h0;
                *(u32*)(Hp + a1) = h1;
                *(u32*)(Lp + a0) = packbf(v00 - lo_f(h0), v01 - hi_f(h0));
                *(u32*)(Lp + a1) = packbf(v10 - lo_f(h1), v11 - hi_f(h1));
            } else if (out_mode == 2) {
                int base = ((b_ << 3) + hh) * Dd;
                int i00 = (base + d) * Nn + n;
                int i01 = (base + d + 1) * Nn + n;
                __nv_bfloat16 h00 = __float2bfloat16(v00);
                __nv_bfloat16 h01 = __float2bfloat16(v01);
                __nv_bfloat16 h10 = __float2bfloat16(v10);
                __nv_bfloat16 h11 = __float2bfloat16(v11);
                gVth[i00]     = h00;
                gVth[i01]     = h01;
                gVth[i00 + 8] = h10;
                gVth[i01 + 8] = h11;
                gVtl[i00]     = __float2bfloat16(v00 - __bfloat162float(h00));
                gVtl[i01]     = __float2bfloat16(v01 - __bfloat162float(h01));
                gVtl[i00 + 8] = __float2bfloat16(v10 - __bfloat162float(h10));
                gVtl[i01 + 8] = __float2bfloat16(v11 - __bfloat162float(h11));
            } else {
                *(float2*)(outext + row * Ee + col) = make_float2(v00, v01);
                *(float2*)(outext + (row + 8) * Ee + col) = make_float2(v10, v11);
            }
        }
    }
}

// ---------------------------------------------------------------------------
// HMMA flash attention (single-sync 2-stage pipeline, x4 ldsm for K/V, exp2)
// ---------------------------------------------------------------------------
#define FTS 72
#define FQ_H 0
#define FQ_L (128 * FTS)
#define FSTG0 (2 * 128 * FTS)
#define FSTG_SZ (4 * 64 * FTS)
#define FK_L_OFF (64 * FTS)
#define FV_H_OFF (2 * 64 * FTS)
#define FV_L_OFF (3 * 64 * FTS)
#define FLASH_SMEM ((FSTG0 + 2 * FSTG_SZ) * 2)

__global__ __launch_bounds__(256, 2) void flash_mma() {
    extern __shared__ unsigned short fsm[];
    unsigned sbase = smem_u32(fsm);

    int rb = blockIdx.x, h = blockIdx.y, b = blockIdx.z;
    int tid = threadIdx.x, wid = tid >> 5, lane = tid & 31;
    int gid = lane >> 2, tig = lane & 3;
    int bh = b * Hh + h;

    const __nv_bfloat16* Qhg = gQh + (bh * Nn + rb * 128) * Dd;
    const __nv_bfloat16* Qlg = gQl + (bh * Nn + rb * 128) * Dd;
    const __nv_bfloat16* Khg = gKh + bh * Nn * Dd;
    const __nv_bfloat16* Klg = gKl + bh * Nn * Dd;
    const __nv_bfloat16* Vhg = gVth + bh * Dd * Nn;
    const __nv_bfloat16* Vlg = gVtl + bh * Dd * Nn;
    const unsigned char* codeg = g_code + (b * Nn + rb * 128) * Nn;

    int rA   = lane & 15, kA = (lane >> 4) * 8;
    int ntl8 = ((lane >> 4) & 1) * 8 + (lane & 7);
    int kB4  = ((lane >> 3) & 1) * 8;

    auto load_kv = [&](int kb, int s) {
        unsigned stg = (unsigned)(FSTG0 + s * FSTG_SZ);
        #pragma unroll
        for (int l = 0; l < 2; l++) {
            int idx = tid + l * 256;
            int row = idx >> 3, c8 = (idx & 7) * 8;
            unsigned so = (row * FTS + c8) * 2;
            cpasync16(sbase + stg * 2 + so, Khg + (kb * 64 + row) * Dd + c8);
            cpasync16(sbase + (stg + FK_L_OFF) * 2 + so, Klg + (kb * 64 + row) * Dd + c8);
            cpasync16(sbase + (stg + FV_H_OFF) * 2 + so, Vhg + row * Nn + kb * 64 + c8);
            cpasync16(sbase + (stg + FV_L_OFF) * 2 + so, Vlg + row * Nn + kb * 64 + c8);
        }
        cpcommit();
    };

    // Q tiles + stage 0 (one group)
    #pragma unroll
    for (int l = 0; l < 4; l++) {
        int idx = tid + l * 256;
        int row = idx >> 3, c8 = (idx & 7) * 8;
        cpasync16(sbase + (FQ_H + row * FTS + c8) * 2, Qhg + row * Dd + c8);
        cpasync16(sbase + (FQ_L + row * FTS + c8) * 2, Qlg + row * Dd + c8);
    }
    {
        unsigned stg = (unsigned)FSTG0;
        #pragma unroll
        for (int l = 0; l < 2; l++) {
            int idx = tid + l * 256;
            int row = idx >> 3, c8 = (idx & 7) * 8;
            unsigned so = (row * FTS + c8) * 2;
            cpasync16(sbase + stg * 2 + so, Khg + row * Dd + c8);
            cpasync16(sbase + (stg + FK_L_OFF) * 2 + so, Klg + row * Dd + c8);
            cpasync16(sbase + (stg + FV_H_OFF) * 2 + so, Vhg + row * Nn + c8);
            cpasync16(sbase + (stg + FV_L_OFF) * 2 + so, Vlg + row * Nn + c8);
        }
        cpcommit();
    }

    unsigned qh_base = sbase + ((FQ_H + (wid * 16 + rA) * FTS + kA) * 2);
    unsigned ql_base = sbase + ((FQ_L + (wid * 16 + rA) * FTS + kA) * 2);

    float co[8][4];
    #pragma unroll
    for (int dt = 0; dt < 8; dt++)
        #pragma unroll
        for (int q = 0; q < 4; q++) co[dt][q] = 0.0f;
    float m0r = -1e30f, m1r = -1e30f, l0r = 0.0f, l1r = 0.0f;

    int crow0 = wid * 16 + gid;
    const unsigned char* cp0 = codeg + crow0 * Nn + tig * 2;
    const unsigned char* cp1 = codeg + (crow0 + 8) * Nn + tig * 2;

    for (int kb = 0; kb < 16; kb++) {
        int buf = kb & 1;
        cpwait<0>();
        __syncthreads();
        if (kb < 15) load_kv(kb + 1, buf ^ 1);   // overlaps compute below

        // mask codes via direct LDG (L2)
        unsigned short cw0[8], cw1[8];
        #pragma unroll
        for (int nt = 0; nt < 8; nt++) {
            cw0[nt] = *(const unsigned short*)(cp0 + kb * 64 + nt * 8);
            cw1[nt] = *(const unsigned short*)(cp1 + kb * 64 + nt * 8);
        }

        unsigned stg = (unsigned)(FSTG0 + buf * FSTG_SZ);
        unsigned kh_b = sbase + stg * 2;
        unsigned kl_b = sbase + (stg + FK_L_OFF) * 2;
        unsigned vh_b = sbase + (stg + FV_H_OFF) * 2;
        unsigned vl_b = sbase + (stg + FV_L_OFF) * 2;

        // ---- S = Q.K^T (3-term) ----
        float sc[8][4];
        #pragma unroll
        for (int nt = 0; nt < 8; nt++)
            #pragma unroll
            for (int q = 0; q < 4; q++) sc[nt][q] = 0.0f;

        #pragma unroll
        for (int ks = 0; ks < 4; ks++) {
            u32 ah[4], al[4];
            ldsm_x4(ah, qh_base + ks * 32);
            ldsm_x4(al, ql_base + ks * 32);
            #pragma unroll
            for (int p = 0; p < 4; p++) {
                unsigned koff = ((p * 16 + ntl8) * FTS + ks * 16 + kB4) * 2;
                u32 th[4], tl[4];
                ldsm_x4(th, kh_b + koff);
                ldsm_x4(tl, kl_b + koff);
                mma16816(sc[2*p],   ah, th);
                mma16816(sc[2*p],   ah, tl);
                mma16816(sc[2*p],   al, th);
                mma16816(sc[2*p+1], ah, th + 2);
                mma16816(sc[2*p+1], ah, tl + 2);
                mma16816(sc[2*p+1], al, th + 2);
            }
        }

        // ---- mask + scale (log2 domain) ----
        #pragma unroll
        for (int nt = 0; nt < 8; nt++) {
            sc[nt][0] = ((unsigned)h >= (cw0[nt] & 255u)) ? sc[nt][0] * SCL2 : NEGV;
            sc[nt][1] = ((unsigned)h >= (cw0[nt] >> 8))   ? sc[nt][1] * SCL2 : NEGV;
            sc[nt][2] = ((unsigned)h >= (cw1[nt] & 255u)) ? sc[nt][2] * SCL2 : NEGV;
            sc[nt][3] = ((unsigned)h >= (cw1[nt] >> 8))   ? sc[nt][3] * SCL2 : NEGV;
        }

        // ---- online softmax (base 2) ----
        float rm0 = -1e30f, rm1 = -1e30f;
        #pragma unroll
        for (int nt = 0; nt < 8; nt++) {
            rm0 = fmaxf(rm0, fmaxf(sc[nt][0], sc[nt][1]));
            rm1 = fmaxf(rm1, fmaxf(sc[nt][2], sc[nt][3]));
        }
        rm0 = fmaxf(rm0, __shfl_xor_sync(0xffffffffu, rm0, 1));
        rm0 = fmaxf(rm0, __shfl_xor_sync(0xffffffffu, rm0, 2));
        rm1 = fmaxf(rm1, __shfl_xor_sync(0xffffffffu, rm1, 1));
        rm1 = fmaxf(rm1, __shfl_xor_sync(0xffffffffu, rm1, 2));
        float mn0 = fmaxf(m0r, rm0), mn1 = fmaxf(m1r, rm1);
        float corr0 = ex2(m0r - mn0), corr1 = ex2(m1r - mn1);
        m0r = mn0; m1r = mn1;

        float ps0 = 0.0f, ps1 = 0.0f;
        #pragma unroll
        for (int nt = 0; nt < 8; nt++) {
            sc[nt][0] = ex2(sc[nt][0] - mn0);
            sc[nt][1] = ex2(sc[nt][1] - mn0);
            sc[nt][2] = ex2(sc[nt][2] - mn1);
            sc[nt][3] = ex2(sc[nt][3] - mn1);
            ps0 += sc[nt][0] + sc[nt][1];
            ps1 += sc[nt][2] + sc[nt][3];
        }
        ps0 += __shfl_xor_sync(0xffffffffu, ps0, 1);
        ps0 += __shfl_xor_sync(0xffffffffu, ps0, 2);
        ps1 += __shfl_xor_sync(0xffffffffu, ps1, 1);
        ps1 += __shfl_xor_sync(0xffffffffu, ps1, 2);
        l0r = l0r * corr0 + ps0;
        l1r = l1r * corr1 + ps1;

        #pragma unroll
        for (int dt = 0; dt < 8; dt++) {
            co[dt][0] *= corr0; co[dt][1] *= corr0;
            co[dt][2] *= corr1; co[dt][3] *= corr1;
        }

        // ---- O += P.V (P split in registers, x4 V frags) ----
        #pragma unroll
        for (int kc = 0; kc < 4; kc++) {
            u32 pah[4], pal[4];
            pah[0] = packbf(sc[2*kc][0],   sc[2*kc][1]);
            pah[1] = packbf(sc[2*kc][2],   sc[2*kc][3]);
            pah[2] = packbf(sc[2*kc+1][0], sc[2*kc+1][1]);
            pah[3] = packbf(sc[2*kc+1][2], sc[2*kc+1][3]);
            pal[0] = packbf(sc[2*kc][0]   - lo_f(pah[0]), sc[2*kc][1]   - hi_f(pah[0]));
            pal[1] = packbf(sc[2*kc][2]   - lo_f(pah[1]), sc[2*kc][3]   - hi_f(pah[1]));
            pal[2] = packbf(sc[2*kc+1][0] - lo_f(pah[2]), sc[2*kc+1][1] - hi_f(pah[2]));
            pal[3] = packbf(sc[2*kc+1][2] - lo_f(pah[3]), sc[2*kc+1][3] - hi_f(pah[3]));
            #pragma unroll
            for (int p = 0; p < 4; p++) {
                unsigned voff = ((p * 16 + ntl8) * FTS + kc * 16 + kB4) * 2;
                u32 th[4], tl[4];
                ldsm_x4(th, vh_b + voff);
                ldsm_x4(tl, vl_b + voff);
                mma16816(co[2*p],   pah, th);
                mma16816(co[2*p],   pah, tl);
                mma16816(co[2*p],   pal, th);
                mma16816(co[2*p+1], pah, th + 2);
                mma16816(co[2*p+1], pah, tl + 2);
                mma16816(co[2*p+1], pal, th + 2);
            }
        }
    }

    // ---- epilogue ----
    float inv0 = 1.0f / l0r, inv1 = 1.0f / l1r;
    int nrow = rb * 128 + wid * 16 + gid;
    int a0base = ((b << 10) + nrow) * Ee + (h << 6);
    int a1base = a0base + 8 * Ee;
    #pragma unroll
    for (int dt = 0; dt < 8; dt++) {
        int d = dt * 8 + tig * 2;
        float v00 = co[dt][0] * inv0, v01 = co[dt][1] * inv0;
        float v10 = co[dt][2] * inv1, v11 = co[dt][3] * inv1;
        u32 h0 = packbf(v00, v01), h1 = packbf(v10, v11);
        *(u32*)(gAh + a0base + d) = h0;
        *(u32*)(gAh + a1base + d) = h1;
        *(u32*)(gAl + a0base + d) = packbf(v00 - lo_f(h0), v01 - hi_f(h0));
        *(u32*)(gAl + a1base + d) = packbf(v10 - lo_f(h1), v11 - hi_f(h1));
    }
}

// ---------------------------------------------------------------------------
extern "C" void kernel_launch(void* const* d_in, const int* in_sizes, int n_in,
                              void* d_out, int out_size) {
    const float* query = (const float*)d_in[0];
    const float* key   = (const float*)d_in[1];
    const float* value = (const float*)d_in[2];
    const float* dist  = (const float*)d_in[3];
    const int*   mask  = (const int*)d_in[4];
    const float* Wq = (const float*)d_in[5];
    const float* bq = (const float*)d_in[6];
    const float* Wk = (const float*)d_in[7];
    const float* bk = (const float*)d_in[8];
    const float* Wv = (const float*)d_in[9];
    const float* bv = (const float*)d_in[10];
    const float* Wo = (const float*)d_in[11];
    const float* bo = (const float*)d_in[12];
    float* out = (float*)d_out;

    cudaFuncSetAttribute(gemm_mma, cudaFuncAttributeMaxDynamicSharedMemorySize, GEMM_SMEM_BYTES);
    cudaFuncSetAttribute(flash_mma, cudaFuncAttributeMaxDynamicSharedMemorySize, FLASH_SMEM);

    code_kernel<<<(Bb * Nn * Nn) / (4 * 256), 256>>>(dist, mask);

    const int NX4 = (Bb * Nn * Ee) / 4;
    const int NW4 = (Ee * Ee) / 4;
    split_x_kernel<<<dim3(NX4 / 256, 3), 256>>>(query, key, value);
    split_w_kernel<<<dim3(NW4 / 256, 4), 256>>>(Wq, Wk, Wv, Wo);

    gemm_mma<<<dim3((Bb * Nn) / 128, Ee / 128, 3), 256, GEMM_SMEM_BYTES>>>(
        bq, bk, bv, nullptr, 1);

    flash_mma<<<dim3(Nn / 128, Hh, Bb), 256, FLASH_SMEM>>>();

    gemm_mma<<<dim3((Bb * Nn) / 128, Ee / 128, 1), 256, GEMM_SMEM_BYTES>>>(
        bo, nullptr, nullptr, out, 0);
}

// round 9
// speedup vs baseline: 1.6277x; 1.6277x over previous
#include <cuda_runtime.h>
#include <cuda_bf16.h>
#include <cuda_fp16.h>

#define Bb 8
#define Nn 1024
#define Ee 512
#define Hh 8
#define Dd 64
#define NEGV -1000000000.0f

typedef unsigned long long u64;
typedef unsigned int u32;

// ---------------------------------------------------------------------------
// Scratch (device globals; referenced only from device code)
// ---------------------------------------------------------------------------
__device__ unsigned char g_code[Bb*Nn*Nn];

__device__ __nv_bfloat16 gXh[3][Bb*Nn*Ee];   // inputs hi (bf16, 3-term GEMM)
__device__ __nv_bfloat16 gXl[3][Bb*Nn*Ee];
__device__ __nv_bfloat16 gWh[4][Ee*Ee];
__device__ __nv_bfloat16 gWl[4][Ee*Ee];

__device__ __half gQh[Bb*Hh*Nn*Dd];          // Q split fp16 [b,h,n,d]
__device__ __half gQl[Bb*Hh*Nn*Dd];
__device__ __half gKh[Bb*Hh*Nn*Dd];          // K single fp16 [b,h,n,d]
__device__ __half gVth[Bb*Hh*Dd*Nn];         // V single fp16 transposed [b,h,d,n]
__device__ __nv_bfloat16 gAh[Bb*Nn*Ee];      // attn out split bf16 (for oproj)
__device__ __nv_bfloat16 gAl[Bb*Nn*Ee];

// ---------------------------------------------------------------------------
// PTX helpers
// ---------------------------------------------------------------------------
__device__ __forceinline__ unsigned smem_u32(const void* p) {
    unsigned a;
    asm("{ .reg .u64 t; cvta.to.shared.u64 t, %1; cvt.u32.u64 %0, t; }"
        : "=r"(a) : "l"(p));
    return a;
}
__device__ __forceinline__ void cpasync16(unsigned dst, const void* src) {
    asm volatile("cp.async.ca.shared.global [%0], [%1], 16;" :: "r"(dst), "l"(src));
}
__device__ __forceinline__ void cpcommit() {
    asm volatile("cp.async.commit_group;" ::: "memory");
}
template<int N> __device__ __forceinline__ void cpwait() {
    asm volatile("cp.async.wait_group %0;" :: "n"(N) : "memory");
}
__device__ __forceinline__ void mma16816(float* c, const u32* a, const u32* b) {
    asm volatile("mma.sync.aligned.m16n8k16.row.col.f32.bf16.bf16.f32 "
        "{%0,%1,%2,%3}, {%4,%5,%6,%7}, {%8,%9}, {%0,%1,%2,%3};"
        : "+f"(c[0]), "+f"(c[1]), "+f"(c[2]), "+f"(c[3])
        : "r"(a[0]), "r"(a[1]), "r"(a[2]), "r"(a[3]), "r"(b[0]), "r"(b[1]));
}
__device__ __forceinline__ void mma16816h(float* c, const u32* a, const u32* b) {
    asm volatile("mma.sync.aligned.m16n8k16.row.col.f32.f16.f16.f32 "
        "{%0,%1,%2,%3}, {%4,%5,%6,%7}, {%8,%9}, {%0,%1,%2,%3};"
        : "+f"(c[0]), "+f"(c[1]), "+f"(c[2]), "+f"(c[3])
        : "r"(a[0]), "r"(a[1]), "r"(a[2]), "r"(a[3]), "r"(b[0]), "r"(b[1]));
}
__device__ __forceinline__ void ldsm_x4(u32* r, unsigned addr) {
    asm volatile("ldmatrix.sync.aligned.m8n8.x4.shared.b16 {%0,%1,%2,%3}, [%4];"
        : "=r"(r[0]), "=r"(r[1]), "=r"(r[2]), "=r"(r[3]) : "r"(addr));
}
__device__ __forceinline__ void ldsm_x2(u32* r, unsigned addr) {
    asm volatile("ldmatrix.sync.aligned.m8n8.x2.shared.b16 {%0,%1}, [%2];"
        : "=r"(r[0]), "=r"(r[1]) : "r"(addr));
}
__device__ __forceinline__ u32 packbf(float lo, float hi) {
    __nv_bfloat162 t = __floats2bfloat162_rn(lo, hi);
    return *(u32*)&t;
}
__device__ __forceinline__ float lo_f(u32 v) { return __uint_as_float(v << 16); }
__device__ __forceinline__ float hi_f(u32 v) { return __uint_as_float(v & 0xffff0000u); }
__device__ __forceinline__ u32 packhf(float lo, float hi) {
    __half2 t = __floats2half2_rn(lo, hi);
    return *(u32*)&t;
}
__device__ __forceinline__ float2 h2ff(u32 v) {
    __half2 t; *(u32*)&t = v;
    return __half22float2(t);
}

// ---------------------------------------------------------------------------
// Mask precompute
// ---------------------------------------------------------------------------
__device__ __forceinline__ unsigned char code_one(float d, int mk, int i, int j) {
    if (mk == 0) return (unsigned char)255;
    if (i == 0 || j == 0) return (unsigned char)0;
    unsigned char c = 0;
    c += (d >= 0.2f); c += (d >= 0.3f); c += (d >= 0.4f); c += (d >= 0.5f);
    c += (d >= 0.6f); c += (d >= 0.7f); c += (d >= 0.8f); c += (d >= 0.9f);
    return c;
}

__global__ __launch_bounds__(256) void code_kernel(const float* __restrict__ dist,
                                                   const int* __restrict__ mask) {
    int t = blockIdx.x * blockDim.x + threadIdx.x;
    int base = t * 4;
    int rem = base & (Nn*Nn - 1);
    int i = rem >> 10;
    int j0 = rem & (Nn - 1);
    float4 dv = *(const float4*)(dist + base);
    int4  mv = *(const int4*)(mask + base);
    uchar4 o;
    o.x = code_one(dv.x, mv.x, i, j0 + 0);
    o.y = code_one(dv.y, mv.y, i, j0 + 1);
    o.z = code_one(dv.z, mv.z, i, j0 + 2);
    o.w = code_one(dv.w, mv.w, i, j0 + 3);
    *(uchar4*)(g_code + base) = o;
}

// ---------------------------------------------------------------------------
// fp32 -> bf16 hi/lo splits
// ---------------------------------------------------------------------------
__device__ __forceinline__ void split_store(float4 v, __nv_bfloat16* hp,
                                            __nv_bfloat16* lp, int t) {
    u32* h2 = (u32*)hp;
    u32* l2 = (u32*)lp;
    u32 hxy = packbf(v.x, v.y), hzw = packbf(v.z, v.w);
    h2[2*t+0] = hxy;
    h2[2*t+1] = hzw;
    l2[2*t+0] = packbf(v.x - lo_f(hxy), v.y - hi_f(hxy));
    l2[2*t+1] = packbf(v.z - lo_f(hzw), v.w - hi_f(hzw));
}

__global__ __launch_bounds__(256) void split_x_kernel(const float* __restrict__ s0,
                                                      const float* __restrict__ s1,
                                                      const float* __restrict__ s2) {
    int which = blockIdx.y;
    const float* src = (which == 0) ? s0 : (which == 1) ? s1 : s2;
    int t = blockIdx.x * blockDim.x + threadIdx.x;
    float4 v = ((const float4*)src)[t];
    split_store(v, gXh[which], gXl[which], t);
}

__global__ __launch_bounds__(256) void split_w_kernel(const float* __restrict__ s0,
                                                      const float* __restrict__ s1,
                                                      const float* __restrict__ s2,
                                                      const float* __restrict__ s3) {
    int which = blockIdx.y;
    const float* src = (which == 0) ? s0 : (which == 1) ? s1
                      : (which == 2) ? s2 : s3;
    int t = blockIdx.x * blockDim.x + threadIdx.x;
    float4 v = ((const float4*)src)[t];
    split_store(v, gWh[which], gWl[which], t);
}

// ---------------------------------------------------------------------------
// HMMA split-bf16 GEMM (R7 structure verbatim; epilogues emit fp16 for Q/K/V)
// ---------------------------------------------------------------------------
#define TSTRIDE 40
#define TILE_US (128 * TSTRIDE)
#define WOFF_US (4 * TILE_US)
#define GEMM_SMEM_BYTES (8 * TILE_US * 2)

__global__ __launch_bounds__(256, 2) void gemm_mma(const float* __restrict__ bias0,
                                                   const float* __restrict__ bias1,
                                                   const float* __restrict__ bias2,
                                                   float* __restrict__ outext,
                                                   int fused) {
    extern __shared__ unsigned short gsm[];
    unsigned sbase = smem_u32(gsm);

    int sel = fused ? blockIdx.z : 3;
    const __nv_bfloat16* Ahg = (sel < 3) ? gXh[sel] : gAh;
    const __nv_bfloat16* Alg = (sel < 3) ? gXl[sel] : gAl;
    const __nv_bfloat16* Whg = gWh[sel];
    const __nv_bfloat16* Wlg = gWl[sel];
    const float* bias = (sel == 0 || sel == 3) ? bias0 : (sel == 1) ? bias1 : bias2;
    int out_mode = sel;

    int tid = threadIdx.x;
    int wid = tid >> 5, lane = tid & 31;
    int wr = wid >> 2, wc = wid & 3;
    int gid = lane >> 2, tig = lane & 3;
    int m0 = blockIdx.x * 128, n0 = blockIdx.y * 128;

    int id0 = tid, id1 = 256 + tid;
    int r0 = id0 >> 2, c80 = (id0 & 3) * 8;
    int r1 = id1 >> 2, c81 = (id1 & 3) * 8;

    int rA = lane & 15, kA = (lane >> 4) * 8;
    int rB = lane & 7,  kB = ((lane >> 3) & 1) * 8;

    float c[4][4][4];
    #pragma unroll
    for (int mt = 0; mt < 4; mt++)
        #pragma unroll
        for (int nt = 0; nt < 4; nt++)
            #pragma unroll
            for (int q = 0; q < 4; q++) c[mt][nt][q] = 0.0f;

    auto load_chunk = [&](int kc, int buf) {
        int kb = kc * 32;
        {
            int a0 = (m0 + r0) * Ee + kb + c80;
            int a1 = (m0 + r1) * Ee + kb + c81;
            unsigned d0 = sbase + ((buf * 2 + 0) * TILE_US + r0 * TSTRIDE + c80) * 2;
            unsigned d1 = sbase + ((buf * 2 + 0) * TILE_US + r1 * TSTRIDE + c81) * 2;
            unsigned e0 = sbase + ((buf * 2 + 1) * TILE_US + r0 * TSTRIDE + c80) * 2;
            unsigned e1 = sbase + ((buf * 2 + 1) * TILE_US + r1 * TSTRIDE + c81) * 2;
            cpasync16(d0, Ahg + a0); cpasync16(d1, Ahg + a1);
            cpasync16(e0, Alg + a0); cpasync16(e1, Alg + a1);
        }
        {
            int w0 = (n0 + r0) * Ee + kb + c80;
            int w1 = (n0 + r1) * Ee + kb + c81;
            unsigned d0 = sbase + (WOFF_US + (buf * 2 + 0) * TILE_US + r0 * TSTRIDE + c80) * 2;
            unsigned d1 = sbase + (WOFF_US + (buf * 2 + 0) * TILE_US + r1 * TSTRIDE + c81) * 2;
            unsigned e0 = sbase + (WOFF_US + (buf * 2 + 1) * TILE_US + r0 * TSTRIDE + c80) * 2;
            unsigned e1 = sbase + (WOFF_US + (buf * 2 + 1) * TILE_US + r1 * TSTRIDE + c81) * 2;
            cpasync16(d0, Whg + w0); cpasync16(d1, Whg + w1);
            cpasync16(e0, Wlg + w0); cpasync16(e1, Wlg + w1);
        }
        cpcommit();
    };

    load_chunk(0, 0);

    for (int kc = 0; kc < 16; kc++) {
        int buf = kc & 1;
        if (kc < 15) load_chunk(kc + 1, buf ^ 1);
        if (kc < 15) cpwait<1>(); else cpwait<0>();
        __syncthreads();

        unsigned ah_b = sbase + ((buf * 2 + 0) * TILE_US) * 2;
        unsigned al_b = sbase + ((buf * 2 + 1) * TILE_US) * 2;
        unsigned wh_b = sbase + ((WOFF_US + (buf * 2 + 0) * TILE_US)) * 2;
        unsigned wl_b = sbase + ((WOFF_US + (buf * 2 + 1) * TILE_US)) * 2;

        #pragma unroll
        for (int ks = 0; ks < 2; ks++) {
            int k0 = ks * 16;
            u32 bh[4][2], bl[4][2];
            #pragma unroll
            for (int nt = 0; nt < 4; nt++) {
                unsigned boff = ((wc * 32 + nt * 8 + rB) * TSTRIDE + k0 + kB) * 2;
                ldsm_x2(bh[nt], wh_b + boff);
                ldsm_x2(bl[nt], wl_b + boff);
            }
            #pragma unroll
            for (int mt = 0; mt < 4; mt++) {
                unsigned aoff = ((wr * 64 + mt * 16 + rA) * TSTRIDE + k0 + kA) * 2;
                u32 ah[4], al[4];
                ldsm_x4(ah, ah_b + aoff);
                ldsm_x4(al, al_b + aoff);
                #pragma unroll
                for (int nt = 0; nt < 4; nt++) {
                    mma16816(c[mt][nt], ah, bh[nt]);
                    mma16816(c[mt][nt], ah, bl[nt]);
                    mma16816(c[mt][nt], al, bh[nt]);
                }
            }
        }
        __syncthreads();
    }

    // Epilogue
    #pragma unroll
    for (int mt = 0; mt < 4; mt++) {
        #pragma unroll
        for (int nt = 0; nt < 4; nt++) {
            int row = m0 + wr * 64 + mt * 16 + gid;
            int col = n0 + wc * 32 + nt * 8 + tig * 2;
            float b0v = bias[col], b1v = bias[col + 1];
            float v00 = c[mt][nt][0] + b0v, v01 = c[mt][nt][1] + b1v;
            float v10 = c[mt][nt][2] + b0v, v11 = c[mt][nt][3] + b1v;
            int b_ = row >> 10, n = row & (Nn - 1);
            int hh = col >> 6, d = col & 63;
            if (out_mode == 0) {
                // Q: fp16 hi + lo
                int a0 = (((b_ << 3) + hh) * Nn + n) * Dd + d;
                int a1 = a0 + 8 * Dd;
                u32 h0 = packhf(v00, v01), h1 = packhf(v10, v11);
                float2 f0 = h2ff(h0), f1 = h2ff(h1);
                *(u32*)(gQh + a0) = h0;
                *(u32*)(gQh + a1) = h1;
                *(u32*)(gQl + a0) = packhf(v00 - f0.x, v01 - f0.y);
                *(u32*)(gQl + a1) = packhf(v10 - f1.x, v11 - f1.y);
            } else if (out_mode == 1) {
                // K: fp16 single
                int a0 = (((b_ << 3) + hh) * Nn + n) * Dd + d;
                int a1 = a0 + 8 * Dd;
                *(u32*)(gKh + a0) = packhf(v00, v01);
                *(u32*)(gKh + a1) = packhf(v10, v11);
            } else if (out_mode == 2) {
                // V: fp16 single, transposed [b,h,d,n]
                int base = ((b_ << 3) + hh) * Dd;
                int i00 = (base + d) * Nn + n;
                int i01 = (base + d + 1) * Nn + n;
                gVth[i00]     = __float2half(v00);
                gVth[i01]     = __float2half(v01);
                gVth[i00 + 8] = __float2half(v10);
                gVth[i01 + 8] = __float2half(v11);
            } else {
                *(float2*)(outext + row * Ee + col) = make_float2(v00, v01);
                *(float2*)(outext + (row + 8) * Ee + col) = make_float2(v10, v11);
            }
        }
    }
}

// ---------------------------------------------------------------------------
// HMMA flash attention: fp16 2-term. Q split (hi+lo), K/V single fp16.
// R7 pipeline structure (2-stage cp.async, two syncs per block, x2 B-ldsm).
// ---------------------------------------------------------------------------
#define FTS 72
#define FQ_H 0
#define FQ_L (128 * FTS)
#define FSTG0 (2 * 128 * FTS)
#define FSTG_SZ (2 * 64 * FTS)       // K + V single per stage
#define FV_OFF (64 * FTS)
#define FLASH_SMEM ((FSTG0 + 2 * FSTG_SZ) * 2)   // 73728 bytes

__global__ __launch_bounds__(256, 2) void flash_mma() {
    extern __shared__ unsigned short fsm[];
    unsigned sbase = smem_u32(fsm);

    int rb = blockIdx.x, h = blockIdx.y, b = blockIdx.z;
    int tid = threadIdx.x, wid = tid >> 5, lane = tid & 31;
    int gid = lane >> 2, tig = lane & 3;
    int bh = b * Hh + h;

    const __half* Qhg = gQh + (bh * Nn + rb * 128) * Dd;
    const __half* Qlg = gQl + (bh * Nn + rb * 128) * Dd;
    const __half* Khg = gKh + bh * Nn * Dd;
    const __half* Vhg = gVth + bh * Dd * Nn;
    const unsigned char* codeg = g_code + (b * Nn + rb * 128) * Nn;

    int rA = lane & 15, kA = (lane >> 4) * 8;
    int rB = lane & 7,  kB = ((lane >> 3) & 1) * 8;

    auto load_kv = [&](int kb, int s) {
        unsigned stg = (unsigned)(FSTG0 + s * FSTG_SZ);
        #pragma unroll
        for (int l = 0; l < 2; l++) {
            int idx = tid + l * 256;
            int row = idx >> 3, c8 = (idx & 7) * 8;
            unsigned so = (row * FTS + c8) * 2;
            cpasync16(sbase + stg * 2 + so, Khg + (kb * 64 + row) * Dd + c8);
            cpasync16(sbase + (stg + FV_OFF) * 2 + so, Vhg + row * Nn + kb * 64 + c8);
        }
        cpcommit();
    };

    // Q tiles + stage 0
    #pragma unroll
    for (int l = 0; l < 4; l++) {
        int idx = tid + l * 256;
        int row = idx >> 3, c8 = (idx & 7) * 8;
        cpasync16(sbase + (FQ_H + row * FTS + c8) * 2, Qhg + row * Dd + c8);
        cpasync16(sbase + (FQ_L + row * FTS + c8) * 2, Qlg + row * Dd + c8);
    }
    load_kv(0, 0);

    unsigned qh_base = sbase + ((FQ_H + (wid * 16 + rA) * FTS + kA) * 2);
    unsigned ql_base = sbase + ((FQ_L + (wid * 16 + rA) * FTS + kA) * 2);

    float co[8][4];
    #pragma unroll
    for (int dt = 0; dt < 8; dt++)
        #pragma unroll
        for (int q = 0; q < 4; q++) co[dt][q] = 0.0f;
    float m0r = -1e30f, m1r = -1e30f, l0r = 0.0f, l1r = 0.0f;

    int crow0 = wid * 16 + gid;
    const unsigned char* cp0 = codeg + crow0 * Nn + tig * 2;
    const unsigned char* cp1 = codeg + (crow0 + 8) * Nn + tig * 2;

    for (int kb = 0; kb < 16; kb++) {
        int buf = kb & 1;
        __syncthreads();
        if (kb < 15) load_kv(kb + 1, buf ^ 1);
        if (kb < 15) cpwait<1>(); else cpwait<0>();
        __syncthreads();

        unsigned short cw0[8], cw1[8];
        #pragma unroll
        for (int nt = 0; nt < 8; nt++) {
            cw0[nt] = *(const unsigned short*)(cp0 + kb * 64 + nt * 8);
            cw1[nt] = *(const unsigned short*)(cp1 + kb * 64 + nt * 8);
        }

        unsigned stg = (unsigned)(FSTG0 + buf * FSTG_SZ);
        unsigned kh_b = sbase + stg * 2;
        unsigned vh_b = sbase + (stg + FV_OFF) * 2;

        // ---- S = Q.K^T (2 MMAs: Qh·K + Ql·K) ----
        float sc[8][4];
        #pragma unroll
        for (int nt = 0; nt < 8; nt++)
            #pragma unroll
            for (int q = 0; q < 4; q++) sc[nt][q] = 0.0f;

        #pragma unroll
        for (int ks = 0; ks < 4; ks++) {
            u32 ah[4], al[4];
            ldsm_x4(ah, qh_base + ks * 32);
            ldsm_x4(al, ql_base + ks * 32);
            #pragma unroll
            for (int nt = 0; nt < 8; nt++) {
                unsigned kaddr = kh_b + ((nt * 8 + rB) * FTS + ks * 16 + kB) * 2;
                u32 bh2[2];
                ldsm_x2(bh2, kaddr);
                mma16816h(sc[nt], ah, bh2);
                mma16816h(sc[nt], al, bh2);
            }
        }

        // ---- mask + scale ----
        #pragma unroll
        for (int nt = 0; nt < 8; nt++) {
            sc[nt][0] = ((unsigned)h >= (cw0[nt] & 255u)) ? sc[nt][0] * 0.125f : NEGV;
            sc[nt][1] = ((unsigned)h >= (cw0[nt] >> 8))   ? sc[nt][1] * 0.125f : NEGV;
            sc[nt][2] = ((unsigned)h >= (cw1[nt] & 255u)) ? sc[nt][2] * 0.125f : NEGV;
            sc[nt][3] = ((unsigned)h >= (cw1[nt] >> 8))   ? sc[nt][3] * 0.125f : NEGV;
        }

        // ---- online softmax ----
        float rm0 = -1e30f, rm1 = -1e30f;
        #pragma unroll
        for (int nt = 0; nt < 8; nt++) {
            rm0 = fmaxf(rm0, fmaxf(sc[nt][0], sc[nt][1]));
            rm1 = fmaxf(rm1, fmaxf(sc[nt][2], sc[nt][3]));
        }
        rm0 = fmaxf(rm0, __shfl_xor_sync(0xffffffffu, rm0, 1));
        rm0 = fmaxf(rm0, __shfl_xor_sync(0xffffffffu, rm0, 2));
        rm1 = fmaxf(rm1, __shfl_xor_sync(0xffffffffu, rm1, 1));
        rm1 = fmaxf(rm1, __shfl_xor_sync(0xffffffffu, rm1, 2));
        float mn0 = fmaxf(m0r, rm0), mn1 = fmaxf(m1r, rm1);
        float corr0 = __expf(m0r - mn0), corr1 = __expf(m1r - mn1);
        m0r = mn0; m1r = mn1;

        float ps0 = 0.0f, ps1 = 0.0f;
        #pragma unroll
        for (int nt = 0; nt < 8; nt++) {
            sc[nt][0] = __expf(sc[nt][0] - mn0);
            sc[nt][1] = __expf(sc[nt][1] - mn0);
            sc[nt][2] = __expf(sc[nt][2] - mn1);
            sc[nt][3] = __expf(sc[nt][3] - mn1);
            ps0 += sc[nt][0] + sc[nt][1];
            ps1 += sc[nt][2] + sc[nt][3];
        }
        ps0 += __shfl_xor_sync(0xffffffffu, ps0, 1);
        ps0 += __shfl_xor_sync(0xffffffffu, ps0, 2);
        ps1 += __shfl_xor_sync(0xffffffffu, ps1, 1);
        ps1 += __shfl_xor_sync(0xffffffffu, ps1, 2);
        l0r = l0r * corr0 + ps0;
        l1r = l1r * corr1 + ps1;

        #pragma unroll
        for (int dt = 0; dt < 8; dt++) {
            co[dt][0] *= corr0; co[dt][1] *= corr0;
            co[dt][2] *= corr1; co[dt][3] *= corr1;
        }

        // ---- O += P.V (P split fp16 in registers; V single) ----
        #pragma unroll
        for (int kc = 0; kc < 4; kc++) {
            u32 pah[4], pal[4];
            pah[0] = packhf(sc[2*kc][0],   sc[2*kc][1]);
            pah[1] = packhf(sc[2*kc][2],   sc[2*kc][3]);
            pah[2] = packhf(sc[2*kc+1][0], sc[2*kc+1][1]);
            pah[3] = packhf(sc[2*kc+1][2], sc[2*kc+1][3]);
            float2 f0 = h2ff(pah[0]), f1 = h2ff(pah[1]);
            float2 f2 = h2ff(pah[2]), f3 = h2ff(pah[3]);
            pal[0] = packhf(sc[2*kc][0]   - f0.x, sc[2*kc][1]   - f0.y);
            pal[1] = packhf(sc[2*kc][2]   - f1.x, sc[2*kc][3]   - f1.y);
            pal[2] = packhf(sc[2*kc+1][0] - f2.x, sc[2*kc+1][1] - f2.y);
            pal[3] = packhf(sc[2*kc+1][2] - f3.x, sc[2*kc+1][3] - f3.y);
            #pragma unroll
            for (int dt = 0; dt < 8; dt++) {
                unsigned vaddr = vh_b + ((dt * 8 + rB) * FTS + kc * 16 + kB) * 2;
                u32 vh2[2];
                ldsm_x2(vh2, vaddr);
                mma16816h(co[dt], pah, vh2);
                mma16816h(co[dt], pal, vh2);
            }
        }
    }

    // ---- epilogue: O / l -> gAh/gAl (bf16 split for oproj) ----
    float inv0 = 1.0f / l0r, inv1 = 1.0f / l1r;
    int nrow = rb * 128 + wid * 16 + gid;
    int a0base = ((b << 10) + nrow) * Ee + (h << 6);
    int a1base = a0base + 8 * Ee;
    #pragma unroll
    for (int dt = 0; dt < 8; dt++) {
        int d = dt * 8 + tig * 2;
        float v00 = co[dt][0] * inv0, v01 = co[dt][1] * inv0;
        float v10 = co[dt][2] * inv1, v11 = co[dt][3] * inv1;
        u32 h0 = packbf(v00, v01), h1 = packbf(v10, v11);
        *(u32*)(gAh + a0base + d) = h0;
        *(u32*)(gAh + a1base + d) = h1;
        *(u32*)(gAl + a0base + d) = packbf(v00 - lo_f(h0), v01 - hi_f(h0));
        *(u32*)(gAl + a1base + d) = packbf(v10 - lo_f(h1), v11 - hi_f(h1));
    }
}

// ---------------------------------------------------------------------------
extern "C" void kernel_launch(void* const* d_in, const int* in_sizes, int n_in,
                              void* d_out, int out_size) {
    const float* query = (const float*)d_in[0];
    const float* key   = (const float*)d_in[1];
    const float* value = (const float*)d_in[2];
    const float* dist  = (const float*)d_in[3];
    const int*   mask  = (const int*)d_in[4];
    const float* Wq = (const float*)d_in[5];
    const float* bq = (const float*)d_in[6];
    const float* Wk = (const float*)d_in[7];
    const float* bk = (const float*)d_in[8];
    const float* Wv = (const float*)d_in[9];
    const float* bv = (const float*)d_in[10];
    const float* Wo = (const float*)d_in[11];
    const float* bo = (const float*)d_in[12];
    float* out = (float*)d_out;

    cudaFuncSetAttribute(gemm_mma, cudaFuncAttributeMaxDynamicSharedMemorySize, GEMM_SMEM_BYTES);
    cudaFuncSetAttribute(flash_mma, cudaFuncAttributeMaxDynamicSharedMemorySize, FLASH_SMEM);

    code_kernel<<<(Bb * Nn * Nn) / (4 * 256), 256>>>(dist, mask);

    const int NX4 = (Bb * Nn * Ee) / 4;
    const int NW4 = (Ee * Ee) / 4;
    split_x_kernel<<<dim3(NX4 / 256, 3), 256>>>(query, key, value);
    split_w_kernel<<<dim3(NW4 / 256, 4), 256>>>(Wq, Wk, Wv, Wo);

    gemm_mma<<<dim3((Bb * Nn) / 128, Ee / 128, 3), 256, GEMM_SMEM_BYTES>>>(
        bq, bk, bv, nullptr, 1);

    flash_mma<<<dim3(Nn / 128, Hh, Bb), 256, FLASH_SMEM>>>();

    gemm_mma<<<dim3((Bb * Nn) / 128, Ee / 128, 1), 256, GEMM_SMEM_BYTES>>>(
        bo, nullptr, nullptr, out, 0);
}

// round 10
// speedup vs baseline: 1.8834x; 1.1571x over previous
#include <cuda_runtime.h>
#include <cuda_bf16.h>
#include <cuda_fp16.h>

#define Bb 8
#define Nn 1024
#define Ee 512
#define Hh 8
#define Dd 64
#define NEGV -1000000000.0f

typedef unsigned long long u64;
typedef unsigned int u32;

// ---------------------------------------------------------------------------
// Scratch (device globals; referenced only from device code)
// ---------------------------------------------------------------------------
__device__ unsigned char g_code[Bb*Nn*Nn];

__device__ __half gXh[3][Bb*Nn*Ee];          // inputs split fp16 hi
__device__ __half gXl[3][Bb*Nn*Ee];          // inputs split fp16 lo
__device__ __half gWs[4][Ee*Ee];             // weights single fp16

__device__ __half gQh[Bb*Hh*Nn*Dd];          // Q split fp16 [b,h,n,d]
__device__ __half gQl[Bb*Hh*Nn*Dd];
__device__ __half gKh[Bb*Hh*Nn*Dd];          // K single fp16 [b,h,n,d]
__device__ __half gVth[Bb*Hh*Dd*Nn];         // V single fp16 transposed [b,h,d,n]
__device__ __half gAh[Bb*Nn*Ee];             // attn out split fp16 (for oproj)
__device__ __half gAl[Bb*Nn*Ee];

// ---------------------------------------------------------------------------
// PTX helpers
// ---------------------------------------------------------------------------
__device__ __forceinline__ unsigned smem_u32(const void* p) {
    unsigned a;
    asm("{ .reg .u64 t; cvta.to.shared.u64 t, %1; cvt.u32.u64 %0, t; }"
        : "=r"(a) : "l"(p));
    return a;
}
__device__ __forceinline__ void cpasync16(unsigned dst, const void* src) {
    asm volatile("cp.async.ca.shared.global [%0], [%1], 16;" :: "r"(dst), "l"(src));
}
__device__ __forceinline__ void cpcommit() {
    asm volatile("cp.async.commit_group;" ::: "memory");
}
template<int N> __device__ __forceinline__ void cpwait() {
    asm volatile("cp.async.wait_group %0;" :: "n"(N) : "memory");
}
__device__ __forceinline__ void mma16816h(float* c, const u32* a, const u32* b) {
    asm volatile("mma.sync.aligned.m16n8k16.row.col.f32.f16.f16.f32 "
        "{%0,%1,%2,%3}, {%4,%5,%6,%7}, {%8,%9}, {%0,%1,%2,%3};"
        : "+f"(c[0]), "+f"(c[1]), "+f"(c[2]), "+f"(c[3])
        : "r"(a[0]), "r"(a[1]), "r"(a[2]), "r"(a[3]), "r"(b[0]), "r"(b[1]));
}
__device__ __forceinline__ void ldsm_x4(u32* r, unsigned addr) {
    asm volatile("ldmatrix.sync.aligned.m8n8.x4.shared.b16 {%0,%1,%2,%3}, [%4];"
        : "=r"(r[0]), "=r"(r[1]), "=r"(r[2]), "=r"(r[3]) : "r"(addr));
}
__device__ __forceinline__ void ldsm_x2(u32* r, unsigned addr) {
    asm volatile("ldmatrix.sync.aligned.m8n8.x2.shared.b16 {%0,%1}, [%2];"
        : "=r"(r[0]), "=r"(r[1]) : "r"(addr));
}
__device__ __forceinline__ u32 packhf(float lo, float hi) {
    __half2 t = __floats2half2_rn(lo, hi);
    return *(u32*)&t;
}
__device__ __forceinline__ float2 h2ff(u32 v) {
    __half2 t; *(u32*)&t = v;
    return __half22float2(t);
}

// ---------------------------------------------------------------------------
// Mask precompute
// ---------------------------------------------------------------------------
__device__ __forceinline__ unsigned char code_one(float d, int mk, int i, int j) {
    if (mk == 0) return (unsigned char)255;
    if (i == 0 || j == 0) return (unsigned char)0;
    unsigned char c = 0;
    c += (d >= 0.2f); c += (d >= 0.3f); c += (d >= 0.4f); c += (d >= 0.5f);
    c += (d >= 0.6f); c += (d >= 0.7f); c += (d >= 0.8f); c += (d >= 0.9f);
    return c;
}

__global__ __launch_bounds__(256) void code_kernel(const float* __restrict__ dist,
                                                   const int* __restrict__ mask) {
    int t = blockIdx.x * blockDim.x + threadIdx.x;
    int base = t * 4;
    int rem = base & (Nn*Nn - 1);
    int i = rem >> 10;
    int j0 = rem & (Nn - 1);
    float4 dv = *(const float4*)(dist + base);
    int4  mv = *(const int4*)(mask + base);
    uchar4 o;
    o.x = code_one(dv.x, mv.x, i, j0 + 0);
    o.y = code_one(dv.y, mv.y, i, j0 + 1);
    o.z = code_one(dv.z, mv.z, i, j0 + 2);
    o.w = code_one(dv.w, mv.w, i, j0 + 3);
    *(uchar4*)(g_code + base) = o;
}

// ---------------------------------------------------------------------------
// Splits: X -> fp16 hi/lo; W -> single fp16
// ---------------------------------------------------------------------------
__global__ __launch_bounds__(256) void split_x_kernel(const float* __restrict__ s0,
                                                      const float* __restrict__ s1,
                                                      const float* __restrict__ s2) {
    int which = blockIdx.y;
    const float* src = (which == 0) ? s0 : (which == 1) ? s1 : s2;
    int t = blockIdx.x * blockDim.x + threadIdx.x;
    float4 v = ((const float4*)src)[t];
    u32* h2 = (u32*)gXh[which];
    u32* l2 = (u32*)gXl[which];
    u32 hxy = packhf(v.x, v.y), hzw = packhf(v.z, v.w);
    float2 fxy = h2ff(hxy), fzw = h2ff(hzw);
    h2[2*t+0] = hxy;
    h2[2*t+1] = hzw;
    l2[2*t+0] = packhf(v.x - fxy.x, v.y - fxy.y);
    l2[2*t+1] = packhf(v.z - fzw.x, v.w - fzw.y);
}

__global__ __launch_bounds__(256) void split_w_kernel(const float* __restrict__ s0,
                                                      const float* __restrict__ s1,
                                                      const float* __restrict__ s2,
                                                      const float* __restrict__ s3) {
    int which = blockIdx.y;
    const float* src = (which == 0) ? s0 : (which == 1) ? s1
                      : (which == 2) ? s2 : s3;
    int t = blockIdx.x * blockDim.x + threadIdx.x;
    float4 v = ((const float4*)src)[t];
    u32* h2 = (u32*)gWs[which];
    h2[2*t+0] = packhf(v.x, v.y);
    h2[2*t+1] = packhf(v.z, v.w);
}

// ---------------------------------------------------------------------------
// HMMA fp16 2-term GEMM: out = (Ah+Al)[8192,512] . Ws[512,512]^T + bias
// R7/R9 pipeline structure. smem: 3 tiles per buffer (Ah, Al, W).
// ---------------------------------------------------------------------------
#define TSTRIDE 40
#define TILE_US (128 * TSTRIDE)
#define GEMM_SMEM_BYTES (6 * TILE_US * 2)    // 61440

__global__ __launch_bounds__(256, 2) void gemm_mma(const float* __restrict__ bias0,
                                                   const float* __restrict__ bias1,
                                                   const float* __restrict__ bias2,
                                                   float* __restrict__ outext,
                                                   int fused) {
    extern __shared__ unsigned short gsm[];
    unsigned sbase = smem_u32(gsm);

    int sel = fused ? blockIdx.z : 3;
    const __half* Ahg = (sel < 3) ? gXh[sel] : gAh;
    const __half* Alg = (sel < 3) ? gXl[sel] : gAl;
    const __half* Wsg = gWs[sel];
    const float* bias = (sel == 0 || sel == 3) ? bias0 : (sel == 1) ? bias1 : bias2;
    int out_mode = sel;

    int tid = threadIdx.x;
    int wid = tid >> 5, lane = tid & 31;
    int wr = wid >> 2, wc = wid & 3;
    int gid = lane >> 2, tig = lane & 3;
    int m0 = blockIdx.x * 128, n0 = blockIdx.y * 128;

    int id0 = tid, id1 = 256 + tid;
    int r0 = id0 >> 2, c80 = (id0 & 3) * 8;
    int r1 = id1 >> 2, c81 = (id1 & 3) * 8;

    int rA = lane & 15, kA = (lane >> 4) * 8;
    int rB = lane & 7,  kB = ((lane >> 3) & 1) * 8;

    float c[4][4][4];
    #pragma unroll
    for (int mt = 0; mt < 4; mt++)
        #pragma unroll
        for (int nt = 0; nt < 4; nt++)
            #pragma unroll
            for (int q = 0; q < 4; q++) c[mt][nt][q] = 0.0f;

    auto load_chunk = [&](int kc, int buf) {
        int kb = kc * 32;
        unsigned base = (unsigned)(buf * 3 * TILE_US);
        {
            int a0 = (m0 + r0) * Ee + kb + c80;
            int a1 = (m0 + r1) * Ee + kb + c81;
            cpasync16(sbase + (base + r0 * TSTRIDE + c80) * 2, Ahg + a0);
            cpasync16(sbase + (base + r1 * TSTRIDE + c81) * 2, Ahg + a1);
            cpasync16(sbase + (base + TILE_US + r0 * TSTRIDE + c80) * 2, Alg + a0);
            cpasync16(sbase + (base + TILE_US + r1 * TSTRIDE + c81) * 2, Alg + a1);
        }
        {
            int w0 = (n0 + r0) * Ee + kb + c80;
            int w1 = (n0 + r1) * Ee + kb + c81;
            cpasync16(sbase + (base + 2 * TILE_US + r0 * TSTRIDE + c80) * 2, Wsg + w0);
            cpasync16(sbase + (base + 2 * TILE_US + r1 * TSTRIDE + c81) * 2, Wsg + w1);
        }
        cpcommit();
    };

    load_chunk(0, 0);

    for (int kc = 0; kc < 16; kc++) {
        int buf = kc & 1;
        if (kc < 15) load_chunk(kc + 1, buf ^ 1);
        if (kc < 15) cpwait<1>(); else cpwait<0>();
        __syncthreads();

        unsigned base = (unsigned)(buf * 3 * TILE_US);
        unsigned ah_b = sbase + base * 2;
        unsigned al_b = sbase + (base + TILE_US) * 2;
        unsigned wh_b = sbase + (base + 2 * TILE_US) * 2;

        #pragma unroll
        for (int ks = 0; ks < 2; ks++) {
            int k0 = ks * 16;
            u32 bh[4][2];
            #pragma unroll
            for (int nt = 0; nt < 4; nt++) {
                unsigned boff = ((wc * 32 + nt * 8 + rB) * TSTRIDE + k0 + kB) * 2;
                ldsm_x2(bh[nt], wh_b + boff);
            }
            #pragma unroll
            for (int mt = 0; mt < 4; mt++) {
                unsigned aoff = ((wr * 64 + mt * 16 + rA) * TSTRIDE + k0 + kA) * 2;
                u32 ah[4], al[4];
                ldsm_x4(ah, ah_b + aoff);
                ldsm_x4(al, al_b + aoff);
                #pragma unroll
                for (int nt = 0; nt < 4; nt++) {
                    mma16816h(c[mt][nt], ah, bh[nt]);
                    mma16816h(c[mt][nt], al, bh[nt]);
                }
            }
        }
        __syncthreads();
    }

    // Epilogue
    #pragma unroll
    for (int mt = 0; mt < 4; mt++) {
        #pragma unroll
        for (int nt = 0; nt < 4; nt++) {
            int row = m0 + wr * 64 + mt * 16 + gid;
            int col = n0 + wc * 32 + nt * 8 + tig * 2;
            float b0v = bias[col], b1v = bias[col + 1];
            float v00 = c[mt][nt][0] + b0v, v01 = c[mt][nt][1] + b1v;
            float v10 = c[mt][nt][2] + b0v, v11 = c[mt][nt][3] + b1v;
            int b_ = row >> 10, n = row & (Nn - 1);
            int hh = col >> 6, d = col & 63;
            if (out_mode == 0) {
                // Q: fp16 hi + lo
                int a0 = (((b_ << 3) + hh) * Nn + n) * Dd + d;
                int a1 = a0 + 8 * Dd;
                u32 h0 = packhf(v00, v01), h1 = packhf(v10, v11);
                float2 f0 = h2ff(h0), f1 = h2ff(h1);
                *(u32*)(gQh + a0) = h0;
                *(u32*)(gQh + a1) = h1;
                *(u32*)(gQl + a0) = packhf(v00 - f0.x, v01 - f0.y);
                *(u32*)(gQl + a1) = packhf(v10 - f1.x, v11 - f1.y);
            } else if (out_mode == 1) {
                // K: fp16 single
                int a0 = (((b_ << 3) + hh) * Nn + n) * Dd + d;
                int a1 = a0 + 8 * Dd;
                *(u32*)(gKh + a0) = packhf(v00, v01);
                *(u32*)(gKh + a1) = packhf(v10, v11);
            } else if (out_mode == 2) {
                // V: fp16 single, transposed [b,h,d,n]
                int base = ((b_ << 3) + hh) * Dd;
                int i00 = (base + d) * Nn + n;
                int i01 = (base + d + 1) * Nn + n;
                gVth[i00]     = __float2half(v00);
                gVth[i01]     = __float2half(v01);
                gVth[i00 + 8] = __float2half(v10);
                gVth[i01 + 8] = __float2half(v11);
            } else {
                *(float2*)(outext + row * Ee + col) = make_float2(v00, v01);
                *(float2*)(outext + (row + 8) * Ee + col) = make_float2(v10, v11);
            }
        }
    }
}

// ---------------------------------------------------------------------------
// HMMA flash attention: fp16 2-term (R9 verbatim; epilogue emits fp16 splits)
// ---------------------------------------------------------------------------
#define FTS 72
#define FQ_H 0
#define FQ_L (128 * FTS)
#define FSTG0 (2 * 128 * FTS)
#define FSTG_SZ (2 * 64 * FTS)
#define FV_OFF (64 * FTS)
#define FLASH_SMEM ((FSTG0 + 2 * FSTG_SZ) * 2)

__global__ __launch_bounds__(256, 2) void flash_mma() {
    extern __shared__ unsigned short fsm[];
    unsigned sbase = smem_u32(fsm);

    int rb = blockIdx.x, h = blockIdx.y, b = blockIdx.z;
    int tid = threadIdx.x, wid = tid >> 5, lane = tid & 31;
    int gid = lane >> 2, tig = lane & 3;
    int bh = b * Hh + h;

    const __half* Qhg = gQh + (bh * Nn + rb * 128) * Dd;
    const __half* Qlg = gQl + (bh * Nn + rb * 128) * Dd;
    const __half* Khg = gKh + bh * Nn * Dd;
    const __half* Vhg = gVth + bh * Dd * Nn;
    const unsigned char* codeg = g_code + (b * Nn + rb * 128) * Nn;

    int rA = lane & 15, kA = (lane >> 4) * 8;
    int rB = lane & 7,  kB = ((lane >> 3) & 1) * 8;

    auto load_kv = [&](int kb, int s) {
        unsigned stg = (unsigned)(FSTG0 + s * FSTG_SZ);
        #pragma unroll
        for (int l = 0; l < 2; l++) {
            int idx = tid + l * 256;
            int row = idx >> 3, c8 = (idx & 7) * 8;
            unsigned so = (row * FTS + c8) * 2;
            cpasync16(sbase + stg * 2 + so, Khg + (kb * 64 + row) * Dd + c8);
            cpasync16(sbase + (stg + FV_OFF) * 2 + so, Vhg + row * Nn + kb * 64 + c8);
        }
        cpcommit();
    };

    #pragma unroll
    for (int l = 0; l < 4; l++) {
        int idx = tid + l * 256;
        int row = idx >> 3, c8 = (idx & 7) * 8;
        cpasync16(sbase + (FQ_H + row * FTS + c8) * 2, Qhg + row * Dd + c8);
        cpasync16(sbase + (FQ_L + row * FTS + c8) * 2, Qlg + row * Dd + c8);
    }
    load_kv(0, 0);

    unsigned qh_base = sbase + ((FQ_H + (wid * 16 + rA) * FTS + kA) * 2);
    unsigned ql_base = sbase + ((FQ_L + (wid * 16 + rA) * FTS + kA) * 2);

    float co[8][4];
    #pragma unroll
    for (int dt = 0; dt < 8; dt++)
        #pragma unroll
        for (int q = 0; q < 4; q++) co[dt][q] = 0.0f;
    float m0r = -1e30f, m1r = -1e30f, l0r = 0.0f, l1r = 0.0f;

    int crow0 = wid * 16 + gid;
    const unsigned char* cp0 = codeg + crow0 * Nn + tig * 2;
    const unsigned char* cp1 = codeg + (crow0 + 8) * Nn + tig * 2;

    for (int kb = 0; kb < 16; kb++) {
        int buf = kb & 1;
        __syncthreads();
        if (kb < 15) load_kv(kb + 1, buf ^ 1);
        if (kb < 15) cpwait<1>(); else cpwait<0>();
        __syncthreads();

        unsigned short cw0[8], cw1[8];
        #pragma unroll
        for (int nt = 0; nt < 8; nt++) {
            cw0[nt] = *(const unsigned short*)(cp0 + kb * 64 + nt * 8);
            cw1[nt] = *(const unsigned short*)(cp1 + kb * 64 + nt * 8);
        }

        unsigned stg = (unsigned)(FSTG0 + buf * FSTG_SZ);
        unsigned kh_b = sbase + stg * 2;
        unsigned vh_b = sbase + (stg + FV_OFF) * 2;

        float sc[8][4];
        #pragma unroll
        for (int nt = 0; nt < 8; nt++)
            #pragma unroll
            for (int q = 0; q < 4; q++) sc[nt][q] = 0.0f;

        #pragma unroll
        for (int ks = 0; ks < 4; ks++) {
            u32 ah[4], al[4];
            ldsm_x4(ah, qh_base + ks * 32);
            ldsm_x4(al, ql_base + ks * 32);
            #pragma unroll
            for (int nt = 0; nt < 8; nt++) {
                unsigned kaddr = kh_b + ((nt * 8 + rB) * FTS + ks * 16 + kB) * 2;
                u32 bh2[2];
                ldsm_x2(bh2, kaddr);
                mma16816h(sc[nt], ah, bh2);
                mma16816h(sc[nt], al, bh2);
            }
        }

        #pragma unroll
        for (int nt = 0; nt < 8; nt++) {
            sc[nt][0] = ((unsigned)h >= (cw0[nt] & 255u)) ? sc[nt][0] * 0.125f : NEGV;
            sc[nt][1] = ((unsigned)h >= (cw0[nt] >> 8))   ? sc[nt][1] * 0.125f : NEGV;
            sc[nt][2] = ((unsigned)h >= (cw1[nt] & 255u)) ? sc[nt][2] * 0.125f : NEGV;
            sc[nt][3] = ((unsigned)h >= (cw1[nt] >> 8))   ? sc[nt][3] * 0.125f : NEGV;
        }

        float rm0 = -1e30f, rm1 = -1e30f;
        #pragma unroll
        for (int nt = 0; nt < 8; nt++) {
            rm0 = fmaxf(rm0, fmaxf(sc[nt][0], sc[nt][1]));
            rm1 = fmaxf(rm1, fmaxf(sc[nt][2], sc[nt][3]));
        }
        rm0 = fmaxf(rm0, __shfl_xor_sync(0xffffffffu, rm0, 1));
        rm0 = fmaxf(rm0, __shfl_xor_sync(0xffffffffu, rm0, 2));
        rm1 = fmaxf(rm1, __shfl_xor_sync(0xffffffffu, rm1, 1));
        rm1 = fmaxf(rm1, __shfl_xor_sync(0xffffffffu, rm1, 2));
        float mn0 = fmaxf(m0r, rm0), mn1 = fmaxf(m1r, rm1);
        float corr0 = __expf(m0r - mn0), corr1 = __expf(m1r - mn1);
        m0r = mn0; m1r = mn1;

        float ps0 = 0.0f, ps1 = 0.0f;
        #pragma unroll
        for (int nt = 0; nt < 8; nt++) {
            sc[nt][0] = __expf(sc[nt][0] - mn0);
            sc[nt][1] = __expf(sc[nt][1] - mn0);
            sc[nt][2] = __expf(sc[nt][2] - mn1);
            sc[nt][3] = __expf(sc[nt][3] - mn1);
            ps0 += sc[nt][0] + sc[nt][1];
            ps1 += sc[nt][2] + sc[nt][3];
        }
        ps0 += __shfl_xor_sync(0xffffffffu, ps0, 1);
        ps0 += __shfl_xor_sync(0xffffffffu, ps0, 2);
        ps1 += __shfl_xor_sync(0xffffffffu, ps1, 1);
        ps1 += __shfl_xor_sync(0xffffffffu, ps1, 2);
        l0r = l0r * corr0 + ps0;
        l1r = l1r * corr1 + ps1;

        #pragma unroll
        for (int dt = 0; dt < 8; dt++) {
            co[dt][0] *= corr0; co[dt][1] *= corr0;
            co[dt][2] *= corr1; co[dt][3] *= corr1;
        }

        #pragma unroll
        for (int kc = 0; kc < 4; kc++) {
            u32 pah[4], pal[4];
            pah[0] = packhf(sc[2*kc][0],   sc[2*kc][1]);
            pah[1] = packhf(sc[2*kc][2],   sc[2*kc][3]);
            pah[2] = packhf(sc[2*kc+1][0], sc[2*kc+1][1]);
            pah[3] = packhf(sc[2*kc+1][2], sc[2*kc+1][3]);
            float2 f0 = h2ff(pah[0]), f1 = h2ff(pah[1]);
            float2 f2 = h2ff(pah[2]), f3 = h2ff(pah[3]);
            pal[0] = packhf(sc[2*kc][0]   - f0.x, sc[2*kc][1]   - f0.y);
            pal[1] = packhf(sc[2*kc][2]   - f1.x, sc[2*kc][3]   - f1.y);
            pal[2] = packhf(sc[2*kc+1][0] - f2.x, sc[2*kc+1][1] - f2.y);
            pal[3] = packhf(sc[2*kc+1][2] - f3.x, sc[2*kc+1][3] - f3.y);
            #pragma unroll
            for (int dt = 0; dt < 8; dt++) {
                unsigned vaddr = vh_b + ((dt * 8 + rB) * FTS + kc * 16 + kB) * 2;
                u32 vh2[2];
                ldsm_x2(vh2, vaddr);
                mma16816h(co[dt], pah, vh2);
                mma16816h(co[dt], pal, vh2);
            }
        }
    }

    // ---- epilogue: O / l -> gAh/gAl (fp16 split for 2-term oproj) ----
    float inv0 = 1.0f / l0r, inv1 = 1.0f / l1r;
    int nrow = rb * 128 + wid * 16 + gid;
    int a0base = ((b << 10) + nrow) * Ee + (h << 6);
    int a1base = a0base + 8 * Ee;
    #pragma unroll
    for (int dt = 0; dt < 8; dt++) {
        int d = dt * 8 + tig * 2;
        float v00 = co[dt][0] * inv0, v01 = co[dt][1] * inv0;
        float v10 = co[dt][2] * inv1, v11 = co[dt][3] * inv1;
        u32 h0 = packhf(v00, v01), h1 = packhf(v10, v11);
        float2 f0 = h2ff(h0), f1 = h2ff(h1);
        *(u32*)(gAh + a0base + d) = h0;
        *(u32*)(gAh + a1base + d) = h1;
        *(u32*)(gAl + a0base + d) = packhf(v00 - f0.x, v01 - f0.y);
        *(u32*)(gAl + a1base + d) = packhf(v10 - f1.x, v11 - f1.y);
    }
}

// ---------------------------------------------------------------------------
extern "C" void kernel_launch(void* const* d_in, const int* in_sizes, int n_in,
                              void* d_out, int out_size) {
    const float* query = (const float*)d_in[0];
    const float* key   = (const float*)d_in[1];
    const float* value = (const float*)d_in[2];
    const float* dist  = (const float*)d_in[3];
    const int*   mask  = (const int*)d_in[4];
    const float* Wq = (const float*)d_in[5];
    const float* bq = (const float*)d_in[6];
    const float* Wk = (const float*)d_in[7];
    const float* bk = (const float*)d_in[8];
    const float* Wv = (const float*)d_in[9];
    const float* bv = (const float*)d_in[10];
    const float* Wo = (const float*)d_in[11];
    const float* bo = (const float*)d_in[12];
    float* out = (float*)d_out;

    cudaFuncSetAttribute(gemm_mma, cudaFuncAttributeMaxDynamicSharedMemorySize, GEMM_SMEM_BYTES);
    cudaFuncSetAttribute(flash_mma, cudaFuncAttributeMaxDynamicSharedMemorySize, FLASH_SMEM);

    code_kernel<<<(Bb * Nn * Nn) / (4 * 256), 256>>>(dist, mask);

    const int NX4 = (Bb * Nn * Ee) / 4;
    const int NW4 = (Ee * Ee) / 4;
    split_x_kernel<<<dim3(NX4 / 256, 3), 256>>>(query, key, value);
    split_w_kernel<<<dim3(NW4 / 256, 4), 256>>>(Wq, Wk, Wv, Wo);

    gemm_mma<<<dim3((Bb * Nn) / 128, Ee / 128, 3), 256, GEMM_SMEM_BYTES>>>(
        bq, bk, bv, nullptr, 1);

    flash_mma<<<dim3(Nn / 128, Hh, Bb), 256, FLASH_SMEM>>>();

    gemm_mma<<<dim3((Bb * Nn) / 128, Ee / 128, 1), 256, GEMM_SMEM_BYTES>>>(
        bo, nullptr, nullptr, out, 0);
}

// round 11
// speedup vs baseline: 1.9880x; 1.0555x over previous
#include <cuda_runtime.h>
#include <cuda_bf16.h>
#include <cuda_fp16.h>

#define Bb 8
#define Nn 1024
#define Ee 512
#define Hh 8
#define Dd 64
#define NEGV -1000000000.0f

typedef unsigned long long u64;
typedef unsigned int u32;

// ---------------------------------------------------------------------------
// Scratch (device globals; referenced only from device code)
// ---------------------------------------------------------------------------
__device__ unsigned char g_code[Bb*Nn*Nn];

__device__ __half gXh[3][Bb*Nn*Ee];          // inputs split fp16 hi
__device__ __half gXl[3][Bb*Nn*Ee];          // inputs split fp16 lo
__device__ __half gWs[4][Ee*Ee];             // weights single fp16

__device__ __half gQh[Bb*Hh*Nn*Dd];          // Q split fp16 [b,h,n,d]
__device__ __half gQl[Bb*Hh*Nn*Dd];
__device__ __half gKh[Bb*Hh*Nn*Dd];          // K single fp16 [b,h,n,d]
__device__ __half gVth[Bb*Hh*Dd*Nn];         // V single fp16 transposed [b,h,d,n]
__device__ __half gAh[Bb*Nn*Ee];             // attn out split fp16 (for oproj)
__device__ __half gAl[Bb*Nn*Ee];

// ---------------------------------------------------------------------------
// PTX helpers
// ---------------------------------------------------------------------------
__device__ __forceinline__ unsigned smem_u32(const void* p) {
    unsigned a;
    asm("{ .reg .u64 t; cvta.to.shared.u64 t, %1; cvt.u32.u64 %0, t; }"
        : "=r"(a) : "l"(p));
    return a;
}
__device__ __forceinline__ void cpasync16(unsigned dst, const void* src) {
    asm volatile("cp.async.ca.shared.global [%0], [%1], 16;" :: "r"(dst), "l"(src));
}
__device__ __forceinline__ void cpcommit() {
    asm volatile("cp.async.commit_group;" ::: "memory");
}
template<int N> __device__ __forceinline__ void cpwait() {
    asm volatile("cp.async.wait_group %0;" :: "n"(N) : "memory");
}
__device__ __forceinline__ void mma16816h(float* c, const u32* a, const u32* b) {
    asm volatile("mma.sync.aligned.m16n8k16.row.col.f32.f16.f16.f32 "
        "{%0,%1,%2,%3}, {%4,%5,%6,%7}, {%8,%9}, {%0,%1,%2,%3};"
        : "+f"(c[0]), "+f"(c[1]), "+f"(c[2]), "+f"(c[3])
        : "r"(a[0]), "r"(a[1]), "r"(a[2]), "r"(a[3]), "r"(b[0]), "r"(b[1]));
}
__device__ __forceinline__ void ldsm_x4(u32* r, unsigned addr) {
    asm volatile("ldmatrix.sync.aligned.m8n8.x4.shared.b16 {%0,%1,%2,%3}, [%4];"
        : "=r"(r[0]), "=r"(r[1]), "=r"(r[2]), "=r"(r[3]) : "r"(addr));
}
__device__ __forceinline__ void ldsm_x2(u32* r, unsigned addr) {
    asm volatile("ldmatrix.sync.aligned.m8n8.x2.shared.b16 {%0,%1}, [%2];"
        : "=r"(r[0]), "=r"(r[1]) : "r"(addr));
}
__device__ __forceinline__ u32 packhf(float lo, float hi) {
    __half2 t = __floats2half2_rn(lo, hi);
    return *(u32*)&t;
}
__device__ __forceinline__ float2 h2ff(u32 v) {
    __half2 t; *(u32*)&t = v;
    return __half22float2(t);
}

// ---------------------------------------------------------------------------
// Mask precompute (8 elements/thread for MLP)
// ---------------------------------------------------------------------------
__device__ __forceinline__ unsigned char code_one(float d, int mk, int i, int j) {
    if (mk == 0) return (unsigned char)255;
    if (i == 0 || j == 0) return (unsigned char)0;
    unsigned char c = 0;
    c += (d >= 0.2f); c += (d >= 0.3f); c += (d >= 0.4f); c += (d >= 0.5f);
    c += (d >= 0.6f); c += (d >= 0.7f); c += (d >= 0.8f); c += (d >= 0.9f);
    return c;
}

__global__ __launch_bounds__(256) void code_kernel(const float* __restrict__ dist,
                                                   const int* __restrict__ mask) {
    int t = blockIdx.x * blockDim.x + threadIdx.x;
    int base = t * 8;                 // row length 1024 divisible by 8: no row cross
    int rem = base & (Nn*Nn - 1);
    int i = rem >> 10;
    int j0 = rem & (Nn - 1);
    float4 dv0 = *(const float4*)(dist + base);
    float4 dv1 = *(const float4*)(dist + base + 4);
    int4  mv0 = *(const int4*)(mask + base);
    int4  mv1 = *(const int4*)(mask + base + 4);
    uchar4 o0, o1;
    o0.x = code_one(dv0.x, mv0.x, i, j0 + 0);
    o0.y = code_one(dv0.y, mv0.y, i, j0 + 1);
    o0.z = code_one(dv0.z, mv0.z, i, j0 + 2);
    o0.w = code_one(dv0.w, mv0.w, i, j0 + 3);
    o1.x = code_one(dv1.x, mv1.x, i, j0 + 4);
    o1.y = code_one(dv1.y, mv1.y, i, j0 + 5);
    o1.z = code_one(dv1.z, mv1.z, i, j0 + 6);
    o1.w = code_one(dv1.w, mv1.w, i, j0 + 7);
    uint2 pack;
    pack.x = *(u32*)&o0;
    pack.y = *(u32*)&o1;
    *(uint2*)(g_code + base) = pack;
}

// ---------------------------------------------------------------------------
// Splits: X -> fp16 hi/lo; W -> single fp16 (2 x float4 per thread)
// ---------------------------------------------------------------------------
__global__ __launch_bounds__(256) void split_x_kernel(const float* __restrict__ s0,
                                                      const float* __restrict__ s1,
                                                      const float* __restrict__ s2) {
    int which = blockIdx.y;
    const float* src = (which == 0) ? s0 : (which == 1) ? s1 : s2;
    int t0 = (blockIdx.x * blockDim.x + threadIdx.x) * 2;
    u32* h2 = (u32*)gXh[which];
    u32* l2 = (u32*)gXl[which];
    float4 va = ((const float4*)src)[t0];
    float4 vb = ((const float4*)src)[t0 + 1];
    #pragma unroll
    for (int s = 0; s < 2; s++) {
        float4 v = s ? vb : va;
        int t = t0 + s;
        u32 hxy = packhf(v.x, v.y), hzw = packhf(v.z, v.w);
        float2 fxy = h2ff(hxy), fzw = h2ff(hzw);
        h2[2*t+0] = hxy;
        h2[2*t+1] = hzw;
        l2[2*t+0] = packhf(v.x - fxy.x, v.y - fxy.y);
        l2[2*t+1] = packhf(v.z - fzw.x, v.w - fzw.y);
    }
}

__global__ __launch_bounds__(256) void split_w_kernel(const float* __restrict__ s0,
                                                      const float* __restrict__ s1,
                                                      const float* __restrict__ s2,
                                                      const float* __restrict__ s3) {
    int which = blockIdx.y;
    const float* src = (which == 0) ? s0 : (which == 1) ? s1
                      : (which == 2) ? s2 : s3;
    int t0 = (blockIdx.x * blockDim.x + threadIdx.x) * 2;
    u32* h2 = (u32*)gWs[which];
    float4 va = ((const float4*)src)[t0];
    float4 vb = ((const float4*)src)[t0 + 1];
    h2[2*t0+0] = packhf(va.x, va.y);
    h2[2*t0+1] = packhf(va.z, va.w);
    h2[2*t0+2] = packhf(vb.x, vb.y);
    h2[2*t0+3] = packhf(vb.z, vb.w);
}

// ---------------------------------------------------------------------------
// HMMA fp16 2-term GEMM (R10 verbatim)
// ---------------------------------------------------------------------------
#define TSTRIDE 40
#define TILE_US (128 * TSTRIDE)
#define GEMM_SMEM_BYTES (6 * TILE_US * 2)

__global__ __launch_bounds__(256, 2) void gemm_mma(const float* __restrict__ bias0,
                                                   const float* __restrict__ bias1,
                                                   const float* __restrict__ bias2,
                                                   float* __restrict__ outext,
                                                   int fused) {
    extern __shared__ unsigned short gsm[];
    unsigned sbase = smem_u32(gsm);

    int sel = fused ? blockIdx.z : 3;
    const __half* Ahg = (sel < 3) ? gXh[sel] : gAh;
    const __half* Alg = (sel < 3) ? gXl[sel] : gAl;
    const __half* Wsg = gWs[sel];
    const float* bias = (sel == 0 || sel == 3) ? bias0 : (sel == 1) ? bias1 : bias2;
    int out_mode = sel;

    int tid = threadIdx.x;
    int wid = tid >> 5, lane = tid & 31;
    int wr = wid >> 2, wc = wid & 3;
    int gid = lane >> 2, tig = lane & 3;
    int m0 = blockIdx.x * 128, n0 = blockIdx.y * 128;

    int id0 = tid, id1 = 256 + tid;
    int r0 = id0 >> 2, c80 = (id0 & 3) * 8;
    int r1 = id1 >> 2, c81 = (id1 & 3) * 8;

    int rA = lane & 15, kA = (lane >> 4) * 8;
    int rB = lane & 7,  kB = ((lane >> 3) & 1) * 8;

    float c[4][4][4];
    #pragma unroll
    for (int mt = 0; mt < 4; mt++)
        #pragma unroll
        for (int nt = 0; nt < 4; nt++)
            #pragma unroll
            for (int q = 0; q < 4; q++) c[mt][nt][q] = 0.0f;

    auto load_chunk = [&](int kc, int buf) {
        int kb = kc * 32;
        unsigned base = (unsigned)(buf * 3 * TILE_US);
        {
            int a0 = (m0 + r0) * Ee + kb + c80;
            int a1 = (m0 + r1) * Ee + kb + c81;
            cpasync16(sbase + (base + r0 * TSTRIDE + c80) * 2, Ahg + a0);
            cpasync16(sbase + (base + r1 * TSTRIDE + c81) * 2, Ahg + a1);
            cpasync16(sbase + (base + TILE_US + r0 * TSTRIDE + c80) * 2, Alg + a0);
            cpasync16(sbase + (base + TILE_US + r1 * TSTRIDE + c81) * 2, Alg + a1);
        }
        {
            int w0 = (n0 + r0) * Ee + kb + c80;
            int w1 = (n0 + r1) * Ee + kb + c81;
            cpasync16(sbase + (base + 2 * TILE_US + r0 * TSTRIDE + c80) * 2, Wsg + w0);
            cpasync16(sbase + (base + 2 * TILE_US + r1 * TSTRIDE + c81) * 2, Wsg + w1);
        }
        cpcommit();
    };

    load_chunk(0, 0);

    for (int kc = 0; kc < 16; kc++) {
        int buf = kc & 1;
        if (kc < 15) load_chunk(kc + 1, buf ^ 1);
        if (kc < 15) cpwait<1>(); else cpwait<0>();
        __syncthreads();

        unsigned base = (unsigned)(buf * 3 * TILE_US);
        unsigned ah_b = sbase + base * 2;
        unsigned al_b = sbase + (base + TILE_US) * 2;
        unsigned wh_b = sbase + (base + 2 * TILE_US) * 2;

        #pragma unroll
        for (int ks = 0; ks < 2; ks++) {
            int k0 = ks * 16;
            u32 bh[4][2];
            #pragma unroll
            for (int nt = 0; nt < 4; nt++) {
                unsigned boff = ((wc * 32 + nt * 8 + rB) * TSTRIDE + k0 + kB) * 2;
                ldsm_x2(bh[nt], wh_b + boff);
            }
            #pragma unroll
            for (int mt = 0; mt < 4; mt++) {
                unsigned aoff = ((wr * 64 + mt * 16 + rA) * TSTRIDE + k0 + kA) * 2;
                u32 ah[4], al[4];
                ldsm_x4(ah, ah_b + aoff);
                ldsm_x4(al, al_b + aoff);
                #pragma unroll
                for (int nt = 0; nt < 4; nt++) {
                    mma16816h(c[mt][nt], ah, bh[nt]);
                    mma16816h(c[mt][nt], al, bh[nt]);
                }
            }
        }
        __syncthreads();
    }

    // Epilogue
    #pragma unroll
    for (int mt = 0; mt < 4; mt++) {
        #pragma unroll
        for (int nt = 0; nt < 4; nt++) {
            int row = m0 + wr * 64 + mt * 16 + gid;
            int col = n0 + wc * 32 + nt * 8 + tig * 2;
            float b0v = bias[col], b1v = bias[col + 1];
            float v00 = c[mt][nt][0] + b0v, v01 = c[mt][nt][1] + b1v;
            float v10 = c[mt][nt][2] + b0v, v11 = c[mt][nt][3] + b1v;
            int b_ = row >> 10, n = row & (Nn - 1);
            int hh = col >> 6, d = col & 63;
            if (out_mode == 0) {
                int a0 = (((b_ << 3) + hh) * Nn + n) * Dd + d;
                int a1 = a0 + 8 * Dd;
                u32 h0 = packhf(v00, v01), h1 = packhf(v10, v11);
                float2 f0 = h2ff(h0), f1 = h2ff(h1);
                *(u32*)(gQh + a0) = h0;
                *(u32*)(gQh + a1) = h1;
                *(u32*)(gQl + a0) = packhf(v00 - f0.x, v01 - f0.y);
                *(u32*)(gQl + a1) = packhf(v10 - f1.x, v11 - f1.y);
            } else if (out_mode == 1) {
                int a0 = (((b_ << 3) + hh) * Nn + n) * Dd + d;
                int a1 = a0 + 8 * Dd;
                *(u32*)(gKh + a0) = packhf(v00, v01);
                *(u32*)(gKh + a1) = packhf(v10, v11);
            } else if (out_mode == 2) {
                int base = ((b_ << 3) + hh) * Dd;
                int i00 = (base + d) * Nn + n;
                int i01 = (base + d + 1) * Nn + n;
                gVth[i00]     = __float2half(v00);
                gVth[i01]     = __float2half(v01);
                gVth[i00 + 8] = __float2half(v10);
                gVth[i01 + 8] = __float2half(v11);
            } else {
                *(float2*)(outext + row * Ee + col) = make_float2(v00, v01);
                *(float2*)(outext + (row + 8) * Ee + col) = make_float2(v10, v11);
            }
        }
    }
}

// ---------------------------------------------------------------------------
// HMMA flash attention: QK 2-term, PV 1-term (P single fp16)
// ---------------------------------------------------------------------------
#define FTS 72
#define FQ_H 0
#define FQ_L (128 * FTS)
#define FSTG0 (2 * 128 * FTS)
#define FSTG_SZ (2 * 64 * FTS)
#define FV_OFF (64 * FTS)
#define FLASH_SMEM ((FSTG0 + 2 * FSTG_SZ) * 2)

__global__ __launch_bounds__(256, 2) void flash_mma() {
    extern __shared__ unsigned short fsm[];
    unsigned sbase = smem_u32(fsm);

    int rb = blockIdx.x, h = blockIdx.y, b = blockIdx.z;
    int tid = threadIdx.x, wid = tid >> 5, lane = tid & 31;
    int gid = lane >> 2, tig = lane & 3;
    int bh = b * Hh + h;

    const __half* Qhg = gQh + (bh * Nn + rb * 128) * Dd;
    const __half* Qlg = gQl + (bh * Nn + rb * 128) * Dd;
    const __half* Khg = gKh + bh * Nn * Dd;
    const __half* Vhg = gVth + bh * Dd * Nn;
    const unsigned char* codeg = g_code + (b * Nn + rb * 128) * Nn;

    int rA = lane & 15, kA = (lane >> 4) * 8;
    int rB = lane & 7,  kB = ((lane >> 3) & 1) * 8;

    auto load_kv = [&](int kb, int s) {
        unsigned stg = (unsigned)(FSTG0 + s * FSTG_SZ);
        #pragma unroll
        for (int l = 0; l < 2; l++) {
            int idx = tid + l * 256;
            int row = idx >> 3, c8 = (idx & 7) * 8;
            unsigned so = (row * FTS + c8) * 2;
            cpasync16(sbase + stg * 2 + so, Khg + (kb * 64 + row) * Dd + c8);
            cpasync16(sbase + (stg + FV_OFF) * 2 + so, Vhg + row * Nn + kb * 64 + c8);
        }
        cpcommit();
    };

    #pragma unroll
    for (int l = 0; l < 4; l++) {
        int idx = tid + l * 256;
        int row = idx >> 3, c8 = (idx & 7) * 8;
        cpasync16(sbase + (FQ_H + row * FTS + c8) * 2, Qhg + row * Dd + c8);
        cpasync16(sbase + (FQ_L + row * FTS + c8) * 2, Qlg + row * Dd + c8);
    }
    load_kv(0, 0);

    unsigned qh_base = sbase + ((FQ_H + (wid * 16 + rA) * FTS + kA) * 2);
    unsigned ql_base = sbase + ((FQ_L + (wid * 16 + rA) * FTS + kA) * 2);

    float co[8][4];
    #pragma unroll
    for (int dt = 0; dt < 8; dt++)
        #pragma unroll
        for (int q = 0; q < 4; q++) co[dt][q] = 0.0f;
    float m0r = -1e30f, m1r = -1e30f, l0r = 0.0f, l1r = 0.0f;

    int crow0 = wid * 16 + gid;
    const unsigned char* cp0 = codeg + crow0 * Nn + tig * 2;
    const unsigned char* cp1 = codeg + (crow0 + 8) * Nn + tig * 2;

    for (int kb = 0; kb < 16; kb++) {
        int buf = kb & 1;
        __syncthreads();
        if (kb < 15) load_kv(kb + 1, buf ^ 1);
        if (kb < 15) cpwait<1>(); else cpwait<0>();
        __syncthreads();

        unsigned short cw0[8], cw1[8];
        #pragma unroll
        for (int nt = 0; nt < 8; nt++) {
            cw0[nt] = *(const unsigned short*)(cp0 + kb * 64 + nt * 8);
            cw1[nt] = *(const unsigned short*)(cp1 + kb * 64 + nt * 8);
        }

        unsigned stg = (unsigned)(FSTG0 + buf * FSTG_SZ);
        unsigned kh_b = sbase + stg * 2;
        unsigned vh_b = sbase + (stg + FV_OFF) * 2;

        // ---- S = Q.K^T (QK 2-term) ----
        float sc[8][4];
        #pragma unroll
        for (int nt = 0; nt < 8; nt++)
            #pragma unroll
            for (int q = 0; q < 4; q++) sc[nt][q] = 0.0f;

        #pragma unroll
        for (int ks = 0; ks < 4; ks++) {
            u32 ah[4], al[4];
            ldsm_x4(ah, qh_base + ks * 32);
            ldsm_x4(al, ql_base + ks * 32);
            #pragma unroll
            for (int nt = 0; nt < 8; nt++) {
                unsigned kaddr = kh_b + ((nt * 8 + rB) * FTS + ks * 16 + kB) * 2;
                u32 bh2[2];
                ldsm_x2(bh2, kaddr);
                mma16816h(sc[nt], ah, bh2);
                mma16816h(sc[nt], al, bh2);
            }
        }

        // ---- mask + scale ----
        #pragma unroll
        for (int nt = 0; nt < 8; nt++) {
            sc[nt][0] = ((unsigned)h >= (cw0[nt] & 255u)) ? sc[nt][0] * 0.125f : NEGV;
            sc[nt][1] = ((unsigned)h >= (cw0[nt] >> 8))   ? sc[nt][1] * 0.125f : NEGV;
            sc[nt][2] = ((unsigned)h >= (cw1[nt] & 255u)) ? sc[nt][2] * 0.125f : NEGV;
            sc[nt][3] = ((unsigned)h >= (cw1[nt] >> 8))   ? sc[nt][3] * 0.125f : NEGV;
        }

        // ---- online softmax ----
        float rm0 = -1e30f, rm1 = -1e30f;
        #pragma unroll
        for (int nt = 0; nt < 8; nt++) {
            rm0 = fmaxf(rm0, fmaxf(sc[nt][0], sc[nt][1]));
            rm1 = fmaxf(rm1, fmaxf(sc[nt][2], sc[nt][3]));
        }
        rm0 = fmaxf(rm0, __shfl_xor_sync(0xffffffffu, rm0, 1));
        rm0 = fmaxf(rm0, __shfl_xor_sync(0xffffffffu, rm0, 2));
        rm1 = fmaxf(rm1, __shfl_xor_sync(0xffffffffu, rm1, 1));
        rm1 = fmaxf(rm1, __shfl_xor_sync(0xffffffffu, rm1, 2));
        float mn0 = fmaxf(m0r, rm0), mn1 = fmaxf(m1r, rm1);
        float corr0 = __expf(m0r - mn0), corr1 = __expf(m1r - mn1);
        m0r = mn0; m1r = mn1;

        float ps0 = 0.0f, ps1 = 0.0f;
        #pragma unroll
        for (int nt = 0; nt < 8; nt++) {
            sc[nt][0] = __expf(sc[nt][0] - mn0);
            sc[nt][1] = __expf(sc[nt][1] - mn0);
            sc[nt][2] = __expf(sc[nt][2] - mn1);
            sc[nt][3] = __expf(sc[nt][3] - mn1);
            ps0 += sc[nt][0] + sc[nt][1];
            ps1 += sc[nt][2] + sc[nt][3];
        }
        ps0 += __shfl_xor_sync(0xffffffffu, ps0, 1);
        ps0 += __shfl_xor_sync(0xffffffffu, ps0, 2);
        ps1 += __shfl_xor_sync(0xffffffffu, ps1, 1);
        ps1 += __shfl_xor_sync(0xffffffffu, ps1, 2);
        l0r = l0r * corr0 + ps0;
        l1r = l1r * corr1 + ps1;

        #pragma unroll
        for (int dt = 0; dt < 8; dt++) {
            co[dt][0] *= corr0; co[dt][1] *= corr0;
            co[dt][2] *= corr1; co[dt][3] *= corr1;
        }

        // ---- O += P.V (P single fp16; 1 MMA per tile) ----
        #pragma unroll
        for (int kc = 0; kc < 4; kc++) {
            u32 pah[4];
            pah[0] = packhf(sc[2*kc][0],   sc[2*kc][1]);
            pah[1] = packhf(sc[2*kc][2],   sc[2*kc][3]);
            pah[2] = packhf(sc[2*kc+1][0], sc[2*kc+1][1]);
            pah[3] = packhf(sc[2*kc+1][2], sc[2*kc+1][3]);
            #pragma unroll
            for (int dt = 0; dt < 8; dt++) {
                unsigned vaddr = vh_b + ((dt * 8 + rB) * FTS + kc * 16 + kB) * 2;
                u32 vh2[2];
                ldsm_x2(vh2, vaddr);
                mma16816h(co[dt], pah, vh2);
            }
        }
    }

    // ---- epilogue: O / l -> gAh/gAl (fp16 split for 2-term oproj) ----
    float inv0 = 1.0f / l0r, inv1 = 1.0f / l1r;
    int nrow = rb * 128 + wid * 16 + gid;
    int a0base = ((b << 10) + nrow) * Ee + (h << 6);
    int a1base = a0base + 8 * Ee;
    #pragma unroll
    for (int dt = 0; dt < 8; dt++) {
        int d = dt * 8 + tig * 2;
        float v00 = co[dt][0] * inv0, v01 = co[dt][1] * inv0;
        float v10 = co[dt][2] * inv1, v11 = co[dt][3] * inv1;
        u32 h0 = packhf(v00, v01), h1 = packhf(v10, v11);
        float2 f0 = h2ff(h0), f1 = h2ff(h1);
        *(u32*)(gAh + a0base + d) = h0;
        *(u32*)(gAh + a1base + d) = h1;
        *(u32*)(gAl + a0base + d) = packhf(v00 - f0.x, v01 - f0.y);
        *(u32*)(gAl + a1base + d) = packhf(v10 - f1.x, v11 - f1.y);
    }
}

// ---------------------------------------------------------------------------
extern "C" void kernel_launch(void* const* d_in, const int* in_sizes, int n_in,
                              void* d_out, int out_size) {
    const float* query = (const float*)d_in[0];
    const float* key   = (const float*)d_in[1];
    const float* value = (const float*)d_in[2];
    const float* dist  = (const float*)d_in[3];
    const int*   mask  = (const int*)d_in[4];
    const float* Wq = (const float*)d_in[5];
    const float* bq = (const float*)d_in[6];
    const float* Wk = (const float*)d_in[7];
    const float* bk = (const float*)d_in[8];
    const float* Wv = (const float*)d_in[9];
    const float* bv = (const float*)d_in[10];
    const float* Wo = (const float*)d_in[11];
    const float* bo = (const float*)d_in[12];
    float* out = (float*)d_out;

    cudaFuncSetAttribute(gemm_mma, cudaFuncAttributeMaxDynamicSharedMemorySize, GEMM_SMEM_BYTES);
    cudaFuncSetAttribute(flash_mma, cudaFuncAttributeMaxDynamicSharedMemorySize, FLASH_SMEM);

    // 1) mask code precompute (8 elems/thread)
    code_kernel<<<(Bb * Nn * Nn) / (8 * 256), 256>>>(dist, mask);

    // 2) splits (2 float4/thread)
    const int NX8 = (Bb * Nn * Ee) / 8;
    const int NW8 = (Ee * Ee) / 8;
    split_x_kernel<<<dim3(NX8 / 256, 3), 256>>>(query, key, value);
    split_w_kernel<<<dim3(NW8 / 256, 4), 256>>>(Wq, Wk, Wv, Wo);

    // 3) fused Q/K/V projections
    gemm_mma<<<dim3((Bb * Nn) / 128, Ee / 128, 3), 256, GEMM_SMEM_BYTES>>>(
        bq, bk, bv, nullptr, 1);

    // 4) flash attention
    flash_mma<<<dim3(Nn / 128, Hh, Bb), 256, FLASH_SMEM>>>();

    // 5) output projection
    gemm_mma<<<dim3((Bb * Nn) / 128, Ee / 128, 1), 256, GEMM_SMEM_BYTES>>>(
        bo, nullptr, nullptr, out, 0);
}

// round 12
// speedup vs baseline: 2.0595x; 1.0360x over previous
#include <cuda_runtime.h>
#include <cuda_bf16.h>
#include <cuda_fp16.h>

#define Bb 8
#define Nn 1024
#define Ee 512
#define Hh 8
#define Dd 64
#define NEGV -1000000000.0f

typedef unsigned long long u64;
typedef unsigned int u32;

// ---------------------------------------------------------------------------
// Scratch (device globals; referenced only from device code)
// ---------------------------------------------------------------------------
__device__ unsigned char g_code[Bb*Nn*Nn];

__device__ __half gXh[3][Bb*Nn*Ee];          // inputs split fp16 hi
__device__ __half gXl[3][Bb*Nn*Ee];          // inputs split fp16 lo
__device__ __half gWs[4][Ee*Ee];             // weights single fp16

__device__ __half gQh[Bb*Hh*Nn*Dd];          // Q single fp16 [b,h,n,d]
__device__ __half gKh[Bb*Hh*Nn*Dd];          // K single fp16 [b,h,n,d]
__device__ __half gVth[Bb*Hh*Dd*Nn];         // V single fp16 transposed [b,h,d,n]
__device__ __half gAh[Bb*Nn*Ee];             // attn out split fp16 (for oproj)
__device__ __half gAl[Bb*Nn*Ee];

// ---------------------------------------------------------------------------
// PTX helpers
// ---------------------------------------------------------------------------
__device__ __forceinline__ unsigned smem_u32(const void* p) {
    unsigned a;
    asm("{ .reg .u64 t; cvta.to.shared.u64 t, %1; cvt.u32.u64 %0, t; }"
        : "=r"(a) : "l"(p));
    return a;
}
__device__ __forceinline__ void cpasync16(unsigned dst, const void* src) {
    asm volatile("cp.async.ca.shared.global [%0], [%1], 16;" :: "r"(dst), "l"(src));
}
__device__ __forceinline__ void cpcommit() {
    asm volatile("cp.async.commit_group;" ::: "memory");
}
template<int N> __device__ __forceinline__ void cpwait() {
    asm volatile("cp.async.wait_group %0;" :: "n"(N) : "memory");
}
__device__ __forceinline__ void mma16816h(float* c, const u32* a, const u32* b) {
    asm volatile("mma.sync.aligned.m16n8k16.row.col.f32.f16.f16.f32 "
        "{%0,%1,%2,%3}, {%4,%5,%6,%7}, {%8,%9}, {%0,%1,%2,%3};"
        : "+f"(c[0]), "+f"(c[1]), "+f"(c[2]), "+f"(c[3])
        : "r"(a[0]), "r"(a[1]), "r"(a[2]), "r"(a[3]), "r"(b[0]), "r"(b[1]));
}
__device__ __forceinline__ void ldsm_x4(u32* r, unsigned addr) {
    asm volatile("ldmatrix.sync.aligned.m8n8.x4.shared.b16 {%0,%1,%2,%3}, [%4];"
        : "=r"(r[0]), "=r"(r[1]), "=r"(r[2]), "=r"(r[3]) : "r"(addr));
}
__device__ __forceinline__ void ldsm_x2(u32* r, unsigned addr) {
    asm volatile("ldmatrix.sync.aligned.m8n8.x2.shared.b16 {%0,%1}, [%2];"
        : "=r"(r[0]), "=r"(r[1]) : "r"(addr));
}
__device__ __forceinline__ u32 packhf(float lo, float hi) {
    __half2 t = __floats2half2_rn(lo, hi);
    return *(u32*)&t;
}
__device__ __forceinline__ float2 h2ff(u32 v) {
    __half2 t; *(u32*)&t = v;
    return __half22float2(t);
}

// ---------------------------------------------------------------------------
// Mask precompute (8 elements/thread for MLP)
// ---------------------------------------------------------------------------
__device__ __forceinline__ unsigned char code_one(float d, int mk, int i, int j) {
    if (mk == 0) return (unsigned char)255;
    if (i == 0 || j == 0) return (unsigned char)0;
    unsigned char c = 0;
    c += (d >= 0.2f); c += (d >= 0.3f); c += (d >= 0.4f); c += (d >= 0.5f);
    c += (d >= 0.6f); c += (d >= 0.7f); c += (d >= 0.8f); c += (d >= 0.9f);
    return c;
}

__global__ __launch_bounds__(256) void code_kernel(const float* __restrict__ dist,
                                                   const int* __restrict__ mask) {
    int t = blockIdx.x * blockDim.x + threadIdx.x;
    int base = t * 8;
    int rem = base & (Nn*Nn - 1);
    int i = rem >> 10;
    int j0 = rem & (Nn - 1);
    float4 dv0 = *(const float4*)(dist + base);
    float4 dv1 = *(const float4*)(dist + base + 4);
    int4  mv0 = *(const int4*)(mask + base);
    int4  mv1 = *(const int4*)(mask + base + 4);
    uchar4 o0, o1;
    o0.x = code_one(dv0.x, mv0.x, i, j0 + 0);
    o0.y = code_one(dv0.y, mv0.y, i, j0 + 1);
    o0.z = code_one(dv0.z, mv0.z, i, j0 + 2);
    o0.w = code_one(dv0.w, mv0.w, i, j0 + 3);
    o1.x = code_one(dv1.x, mv1.x, i, j0 + 4);
    o1.y = code_one(dv1.y, mv1.y, i, j0 + 5);
    o1.z = code_one(dv1.z, mv1.z, i, j0 + 6);
    o1.w = code_one(dv1.w, mv1.w, i, j0 + 7);
    uint2 pack;
    pack.x = *(u32*)&o0;
    pack.y = *(u32*)&o1;
    *(uint2*)(g_code + base) = pack;
}

// ---------------------------------------------------------------------------
// Splits: X -> fp16 hi/lo; W -> single fp16 (2 x float4 per thread)
// ---------------------------------------------------------------------------
__global__ __launch_bounds__(256) void split_x_kernel(const float* __restrict__ s0,
                                                      const float* __restrict__ s1,
                                                      const float* __restrict__ s2) {
    int which = blockIdx.y;
    const float* src = (which == 0) ? s0 : (which == 1) ? s1 : s2;
    int t0 = (blockIdx.x * blockDim.x + threadIdx.x) * 2;
    u32* h2 = (u32*)gXh[which];
    u32* l2 = (u32*)gXl[which];
    float4 va = ((const float4*)src)[t0];
    float4 vb = ((const float4*)src)[t0 + 1];
    #pragma unroll
    for (int s = 0; s < 2; s++) {
        float4 v = s ? vb : va;
        int t = t0 + s;
        u32 hxy = packhf(v.x, v.y), hzw = packhf(v.z, v.w);
        float2 fxy = h2ff(hxy), fzw = h2ff(hzw);
        h2[2*t+0] = hxy;
        h2[2*t+1] = hzw;
        l2[2*t+0] = packhf(v.x - fxy.x, v.y - fxy.y);
        l2[2*t+1] = packhf(v.z - fzw.x, v.w - fzw.y);
    }
}

__global__ __launch_bounds__(256) void split_w_kernel(const float* __restrict__ s0,
                                                      const float* __restrict__ s1,
                                                      const float* __restrict__ s2,
                                                      const float* __restrict__ s3) {
    int which = blockIdx.y;
    const float* src = (which == 0) ? s0 : (which == 1) ? s1
                      : (which == 2) ? s2 : s3;
    int t0 = (blockIdx.x * blockDim.x + threadIdx.x) * 2;
    u32* h2 = (u32*)gWs[which];
    float4 va = ((const float4*)src)[t0];
    float4 vb = ((const float4*)src)[t0 + 1];
    h2[2*t0+0] = packhf(va.x, va.y);
    h2[2*t0+1] = packhf(va.z, va.w);
    h2[2*t0+2] = packhf(vb.x, vb.y);
    h2[2*t0+3] = packhf(vb.z, vb.w);
}

// ---------------------------------------------------------------------------
// HMMA fp16 2-term GEMM (R10/R11 verbatim; Q epilogue now single fp16)
// ---------------------------------------------------------------------------
#define TSTRIDE 40
#define TILE_US (128 * TSTRIDE)
#define GEMM_SMEM_BYTES (6 * TILE_US * 2)

__global__ __launch_bounds__(256, 2) void gemm_mma(const float* __restrict__ bias0,
                                                   const float* __restrict__ bias1,
                                                   const float* __restrict__ bias2,
                                                   float* __restrict__ outext,
                                                   int fused) {
    extern __shared__ unsigned short gsm[];
    unsigned sbase = smem_u32(gsm);

    int sel = fused ? blockIdx.z : 3;
    const __half* Ahg = (sel < 3) ? gXh[sel] : gAh;
    const __half* Alg = (sel < 3) ? gXl[sel] : gAl;
    const __half* Wsg = gWs[sel];
    const float* bias = (sel == 0 || sel == 3) ? bias0 : (sel == 1) ? bias1 : bias2;
    int out_mode = sel;

    int tid = threadIdx.x;
    int wid = tid >> 5, lane = tid & 31;
    int wr = wid >> 2, wc = wid & 3;
    int gid = lane >> 2, tig = lane & 3;
    int m0 = blockIdx.x * 128, n0 = blockIdx.y * 128;

    int id0 = tid, id1 = 256 + tid;
    int r0 = id0 >> 2, c80 = (id0 & 3) * 8;
    int r1 = id1 >> 2, c81 = (id1 & 3) * 8;

    int rA = lane & 15, kA = (lane >> 4) * 8;
    int rB = lane & 7,  kB = ((lane >> 3) & 1) * 8;

    float c[4][4][4];
    #pragma unroll
    for (int mt = 0; mt < 4; mt++)
        #pragma unroll
        for (int nt = 0; nt < 4; nt++)
            #pragma unroll
            for (int q = 0; q < 4; q++) c[mt][nt][q] = 0.0f;

    auto load_chunk = [&](int kc, int buf) {
        int kb = kc * 32;
        unsigned base = (unsigned)(buf * 3 * TILE_US);
        {
            int a0 = (m0 + r0) * Ee + kb + c80;
            int a1 = (m0 + r1) * Ee + kb + c81;
            cpasync16(sbase + (base + r0 * TSTRIDE + c80) * 2, Ahg + a0);
            cpasync16(sbase + (base + r1 * TSTRIDE + c81) * 2, Ahg + a1);
            cpasync16(sbase + (base + TILE_US + r0 * TSTRIDE + c80) * 2, Alg + a0);
            cpasync16(sbase + (base + TILE_US + r1 * TSTRIDE + c81) * 2, Alg + a1);
        }
        {
            int w0 = (n0 + r0) * Ee + kb + c80;
            int w1 = (n0 + r1) * Ee + kb + c81;
            cpasync16(sbase + (base + 2 * TILE_US + r0 * TSTRIDE + c80) * 2, Wsg + w0);
            cpasync16(sbase + (base + 2 * TILE_US + r1 * TSTRIDE + c81) * 2, Wsg + w1);
        }
        cpcommit();
    };

    load_chunk(0, 0);

    for (int kc = 0; kc < 16; kc++) {
        int buf = kc & 1;
        if (kc < 15) load_chunk(kc + 1, buf ^ 1);
        if (kc < 15) cpwait<1>(); else cpwait<0>();
        __syncthreads();

        unsigned base = (unsigned)(buf * 3 * TILE_US);
        unsigned ah_b = sbase + base * 2;
        unsigned al_b = sbase + (base + TILE_US) * 2;
        unsigned wh_b = sbase + (base + 2 * TILE_US) * 2;

        #pragma unroll
        for (int ks = 0; ks < 2; ks++) {
            int k0 = ks * 16;
            u32 bh[4][2];
            #pragma unroll
            for (int nt = 0; nt < 4; nt++) {
                unsigned boff = ((wc * 32 + nt * 8 + rB) * TSTRIDE + k0 + kB) * 2;
                ldsm_x2(bh[nt], wh_b + boff);
            }
            #pragma unroll
            for (int mt = 0; mt < 4; mt++) {
                unsigned aoff = ((wr * 64 + mt * 16 + rA) * TSTRIDE + k0 + kA) * 2;
                u32 ah[4], al[4];
                ldsm_x4(ah, ah_b + aoff);
                ldsm_x4(al, al_b + aoff);
                #pragma unroll
                for (int nt = 0; nt < 4; nt++) {
                    mma16816h(c[mt][nt], ah, bh[nt]);
                    mma16816h(c[mt][nt], al, bh[nt]);
                }
            }
        }
        __syncthreads();
    }

    // Epilogue
    #pragma unroll
    for (int mt = 0; mt < 4; mt++) {
        #pragma unroll
        for (int nt = 0; nt < 4; nt++) {
            int row = m0 + wr * 64 + mt * 16 + gid;
            int col = n0 + wc * 32 + nt * 8 + tig * 2;
            float b0v = bias[col], b1v = bias[col + 1];
            float v00 = c[mt][nt][0] + b0v, v01 = c[mt][nt][1] + b1v;
            float v10 = c[mt][nt][2] + b0v, v11 = c[mt][nt][3] + b1v;
            int b_ = row >> 10, n = row & (Nn - 1);
            int hh = col >> 6, d = col & 63;
            if (out_mode <= 1) {
                // Q and K: single fp16 [b,h,n,d]
                __half* Hp = (out_mode == 0) ? gQh : gKh;
                int a0 = (((b_ << 3) + hh) * Nn + n) * Dd + d;
                int a1 = a0 + 8 * Dd;
                *(u32*)(Hp + a0) = packhf(v00, v01);
                *(u32*)(Hp + a1) = packhf(v10, v11);
            } else if (out_mode == 2) {
                // V: single fp16, transposed [b,h,d,n]
                int base = ((b_ << 3) + hh) * Dd;
                int i00 = (base + d) * Nn + n;
                int i01 = (base + d + 1) * Nn + n;
                gVth[i00]     = __float2half(v00);
                gVth[i01]     = __float2half(v01);
                gVth[i00 + 8] = __float2half(v10);
                gVth[i01 + 8] = __float2half(v11);
            } else {
                *(float2*)(outext + row * Ee + col) = make_float2(v00, v01);
                *(float2*)(outext + (row + 8) * Ee + col) = make_float2(v10, v11);
            }
        }
    }
}

// ---------------------------------------------------------------------------
// HMMA flash attention: QK 1-term (Q,K single fp16), PV 1-term
// ---------------------------------------------------------------------------
#define FTS 72
#define FQ_H 0
#define FSTG0 (128 * FTS)
#define FSTG_SZ (2 * 64 * FTS)
#define FV_OFF (64 * FTS)
#define FLASH_SMEM ((FSTG0 + 2 * FSTG_SZ) * 2)   // 55296 bytes

__global__ __launch_bounds__(256, 2) void flash_mma() {
    extern __shared__ unsigned short fsm[];
    unsigned sbase = smem_u32(fsm);

    int rb = blockIdx.x, h = blockIdx.y, b = blockIdx.z;
    int tid = threadIdx.x, wid = tid >> 5, lane = tid & 31;
    int gid = lane >> 2, tig = lane & 3;
    int bh = b * Hh + h;

    const __half* Qhg = gQh + (bh * Nn + rb * 128) * Dd;
    const __half* Khg = gKh + bh * Nn * Dd;
    const __half* Vhg = gVth + bh * Dd * Nn;
    const unsigned char* codeg = g_code + (b * Nn + rb * 128) * Nn;

    int rA = lane & 15, kA = (lane >> 4) * 8;
    int rB = lane & 7,  kB = ((lane >> 3) & 1) * 8;

    auto load_kv = [&](int kb, int s) {
        unsigned stg = (unsigned)(FSTG0 + s * FSTG_SZ);
        #pragma unroll
        for (int l = 0; l < 2; l++) {
            int idx = tid + l * 256;
            int row = idx >> 3, c8 = (idx & 7) * 8;
            unsigned so = (row * FTS + c8) * 2;
            cpasync16(sbase + stg * 2 + so, Khg + (kb * 64 + row) * Dd + c8);
            cpasync16(sbase + (stg + FV_OFF) * 2 + so, Vhg + row * Nn + kb * 64 + c8);
        }
        cpcommit();
    };

    // Q tile (single) + stage 0
    #pragma unroll
    for (int l = 0; l < 4; l++) {
        int idx = tid + l * 256;
        int row = idx >> 3, c8 = (idx & 7) * 8;
        cpasync16(sbase + (FQ_H + row * FTS + c8) * 2, Qhg + row * Dd + c8);
    }
    load_kv(0, 0);

    unsigned qh_base = sbase + ((FQ_H + (wid * 16 + rA) * FTS + kA) * 2);

    float co[8][4];
    #pragma unroll
    for (int dt = 0; dt < 8; dt++)
        #pragma unroll
        for (int q = 0; q < 4; q++) co[dt][q] = 0.0f;
    float m0r = -1e30f, m1r = -1e30f, l0r = 0.0f, l1r = 0.0f;

    int crow0 = wid * 16 + gid;
    const unsigned char* cp0 = codeg + crow0 * Nn + tig * 2;
    const unsigned char* cp1 = codeg + (crow0 + 8) * Nn + tig * 2;

    for (int kb = 0; kb < 16; kb++) {
        int buf = kb & 1;
        __syncthreads();
        if (kb < 15) load_kv(kb + 1, buf ^ 1);
        if (kb < 15) cpwait<1>(); else cpwait<0>();
        __syncthreads();

        unsigned short cw0[8], cw1[8];
        #pragma unroll
        for (int nt = 0; nt < 8; nt++) {
            cw0[nt] = *(const unsigned short*)(cp0 + kb * 64 + nt * 8);
            cw1[nt] = *(const unsigned short*)(cp1 + kb * 64 + nt * 8);
        }

        unsigned stg = (unsigned)(FSTG0 + buf * FSTG_SZ);
        unsigned kh_b = sbase + stg * 2;
        unsigned vh_b = sbase + (stg + FV_OFF) * 2;

        // ---- S = Q.K^T (1 MMA per tile) ----
        float sc[8][4];
        #pragma unroll
        for (int nt = 0; nt < 8; nt++)
            #pragma unroll
            for (int q = 0; q < 4; q++) sc[nt][q] = 0.0f;

        #pragma unroll
        for (int ks = 0; ks < 4; ks++) {
            u32 ah[4];
            ldsm_x4(ah, qh_base + ks * 32);
            #pragma unroll
            for (int nt = 0; nt < 8; nt++) {
                unsigned kaddr = kh_b + ((nt * 8 + rB) * FTS + ks * 16 + kB) * 2;
                u32 bh2[2];
                ldsm_x2(bh2, kaddr);
                mma16816h(sc[nt], ah, bh2);
            }
        }

        // ---- mask + scale ----
        #pragma unroll
        for (int nt = 0; nt < 8; nt++) {
            sc[nt][0] = ((unsigned)h >= (cw0[nt] & 255u)) ? sc[nt][0] * 0.125f : NEGV;
            sc[nt][1] = ((unsigned)h >= (cw0[nt] >> 8))   ? sc[nt][1] * 0.125f : NEGV;
            sc[nt][2] = ((unsigned)h >= (cw1[nt] & 255u)) ? sc[nt][2] * 0.125f : NEGV;
            sc[nt][3] = ((unsigned)h >= (cw1[nt] >> 8))   ? sc[nt][3] * 0.125f : NEGV;
        }

        // ---- online softmax ----
        float rm0 = -1e30f, rm1 = -1e30f;
        #pragma unroll
        for (int nt = 0; nt < 8; nt++) {
            rm0 = fmaxf(rm0, fmaxf(sc[nt][0], sc[nt][1]));
            rm1 = fmaxf(rm1, fmaxf(sc[nt][2], sc[nt][3]));
        }
        rm0 = fmaxf(rm0, __shfl_xor_sync(0xffffffffu, rm0, 1));
        rm0 = fmaxf(rm0, __shfl_xor_sync(0xffffffffu, rm0, 2));
        rm1 = fmaxf(rm1, __shfl_xor_sync(0xffffffffu, rm1, 1));
        rm1 = fmaxf(rm1, __shfl_xor_sync(0xffffffffu, rm1, 2));
        float mn0 = fmaxf(m0r, rm0), mn1 = fmaxf(m1r, rm1);
        float corr0 = __expf(m0r - mn0), corr1 = __expf(m1r - mn1);
        m0r = mn0; m1r = mn1;

        float ps0 = 0.0f, ps1 = 0.0f;
        #pragma unroll
        for (int nt = 0; nt < 8; nt++) {
            sc[nt][0] = __expf(sc[nt][0] - mn0);
            sc[nt][1] = __expf(sc[nt][1] - mn0);
            sc[nt][2] = __expf(sc[nt][2] - mn1);
            sc[nt][3] = __expf(sc[nt][3] - mn1);
            ps0 += sc[nt][0] + sc[nt][1];
            ps1 += sc[nt][2] + sc[nt][3];
        }
        ps0 += __shfl_xor_sync(0xffffffffu, ps0, 1);
        ps0 += __shfl_xor_sync(0xffffffffu, ps0, 2);
        ps1 += __shfl_xor_sync(0xffffffffu, ps1, 1);
        ps1 += __shfl_xor_sync(0xffffffffu, ps1, 2);
        l0r = l0r * corr0 + ps0;
        l1r = l1r * corr1 + ps1;

        #pragma unroll
        for (int dt = 0; dt < 8; dt++) {
            co[dt][0] *= corr0; co[dt][1] *= corr0;
            co[dt][2] *= corr1; co[dt][3] *= corr1;
        }

        // ---- O += P.V (P single fp16; 1 MMA per tile) ----
        #pragma unroll
        for (int kc = 0; kc < 4; kc++) {
            u32 pah[4];
            pah[0] = packhf(sc[2*kc][0],   sc[2*kc][1]);
            pah[1] = packhf(sc[2*kc][2],   sc[2*kc][3]);
            pah[2] = packhf(sc[2*kc+1][0], sc[2*kc+1][1]);
            pah[3] = packhf(sc[2*kc+1][2], sc[2*kc+1][3]);
            #pragma unroll
            for (int dt = 0; dt < 8; dt++) {
                unsigned vaddr = vh_b + ((dt * 8 + rB) * FTS + kc * 16 + kB) * 2;
                u32 vh2[2];
                ldsm_x2(vh2, vaddr);
                mma16816h(co[dt], pah, vh2);
            }
        }
    }

    // ---- epilogue: O / l -> gAh/gAl (fp16 split for 2-term oproj) ----
    float inv0 = 1.0f / l0r, inv1 = 1.0f / l1r;
    int nrow = rb * 128 + wid * 16 + gid;
    int a0base = ((b << 10) + nrow) * Ee + (h << 6);
    int a1base = a0base + 8 * Ee;
    #pragma unroll
    for (int dt = 0; dt < 8; dt++) {
        int d = dt * 8 + tig * 2;
        float v00 = co[dt][0] * inv0, v01 = co[dt][1] * inv0;
        float v10 = co[dt][2] * inv1, v11 = co[dt][3] * inv1;
        u32 h0 = packhf(v00, v01), h1 = packhf(v10, v11);
        float2 f0 = h2ff(h0), f1 = h2ff(h1);
        *(u32*)(gAh + a0base + d) = h0;
        *(u32*)(gAh + a1base + d) = h1;
        *(u32*)(gAl + a0base + d) = packhf(v00 - f0.x, v01 - f0.y);
        *(u32*)(gAl + a1base + d) = packhf(v10 - f1.x, v11 - f1.y);
    }
}

// ---------------------------------------------------------------------------
extern "C" void kernel_launch(void* const* d_in, const int* in_sizes, int n_in,
                              void* d_out, int out_size) {
    const float* query = (const float*)d_in[0];
    const float* key   = (const float*)d_in[1];
    const float* value = (const float*)d_in[2];
    const float* dist  = (const float*)d_in[3];
    const int*   mask  = (const int*)d_in[4];
    const float* Wq = (const float*)d_in[5];
    const float* bq = (const float*)d_in[6];
    const float* Wk = (const float*)d_in[7];
    const float* bk = (const float*)d_in[8];
    const float* Wv = (const float*)d_in[9];
    const float* bv = (const float*)d_in[10];
    const float* Wo = (const float*)d_in[11];
    const float* bo = (const float*)d_in[12];
    float* out = (float*)d_out;

    cudaFuncSetAttribute(gemm_mma, cudaFuncAttributeMaxDynamicSharedMemorySize, GEMM_SMEM_BYTES);
    cudaFuncSetAttribute(flash_mma, cudaFuncAttributeMaxDynamicSharedMemorySize, FLASH_SMEM);

    // 1) mask code precompute
    code_kernel<<<(Bb * Nn * Nn) / (8 * 256), 256>>>(dist, mask);

    // 2) splits
    const int NX8 = (Bb * Nn * Ee) / 8;
    const int NW8 = (Ee * Ee) / 8;
    split_x_kernel<<<dim3(NX8 / 256, 3), 256>>>(query, key, value);
    split_w_kernel<<<dim3(NW8 / 256, 4), 256>>>(Wq, Wk, Wv, Wo);

    // 3) fused Q/K/V projections
    gemm_mma<<<dim3((Bb * Nn) / 128, Ee / 128, 3), 256, GEMM_SMEM_BYTES>>>(
        bq, bk, bv, nullptr, 1);

    // 4) flash attention
    flash_mma<<<dim3(Nn / 128, Hh, Bb), 256, FLASH_SMEM>>>();

    // 5) output projection
    gemm_mma<<<dim3((Bb * Nn) / 128, Ee / 128, 1), 256, GEMM_SMEM_BYTES>>>(
        bo, nullptr, nullptr, out, 0);
}

// round 13
// speedup vs baseline: 2.3175x; 1.1252x over previous
#include <cuda_runtime.h>
#include <cuda_bf16.h>
#include <cuda_fp16.h>

#define Bb 8
#define Nn 1024
#define Ee 512
#define Hh 8
#define Dd 64
#define NEGV -1000000000.0f

typedef unsigned long long u64;
typedef unsigned int u32;

// ---------------------------------------------------------------------------
// Scratch (device globals; referenced only from device code)
// ---------------------------------------------------------------------------
__device__ unsigned char g_code[Bb*Nn*Nn];

__device__ __half gXs[3][Bb*Nn*Ee];          // inputs single fp16
__device__ __half gWs[4][Ee*Ee];             // weights single fp16

__device__ __half gQh[Bb*Hh*Nn*Dd];          // Q single fp16 [b,h,n,d]
__device__ __half gKh[Bb*Hh*Nn*Dd];          // K single fp16 [b,h,n,d]
__device__ __half gVth[Bb*Hh*Dd*Nn];         // V single fp16 transposed [b,h,d,n]
__device__ __half gAh[Bb*Nn*Ee];             // attn out split fp16 (for 2-term oproj)
__device__ __half gAl[Bb*Nn*Ee];

// ---------------------------------------------------------------------------
// PTX helpers
// ---------------------------------------------------------------------------
__device__ __forceinline__ unsigned smem_u32(const void* p) {
    unsigned a;
    asm("{ .reg .u64 t; cvta.to.shared.u64 t, %1; cvt.u32.u64 %0, t; }"
        : "=r"(a) : "l"(p));
    return a;
}
__device__ __forceinline__ void cpasync16(unsigned dst, const void* src) {
    asm volatile("cp.async.ca.shared.global [%0], [%1], 16;" :: "r"(dst), "l"(src));
}
__device__ __forceinline__ void cpcommit() {
    asm volatile("cp.async.commit_group;" ::: "memory");
}
template<int N> __device__ __forceinline__ void cpwait() {
    asm volatile("cp.async.wait_group %0;" :: "n"(N) : "memory");
}
__device__ __forceinline__ void mma16816h(float* c, const u32* a, const u32* b) {
    asm volatile("mma.sync.aligned.m16n8k16.row.col.f32.f16.f16.f32 "
        "{%0,%1,%2,%3}, {%4,%5,%6,%7}, {%8,%9}, {%0,%1,%2,%3};"
        : "+f"(c[0]), "+f"(c[1]), "+f"(c[2]), "+f"(c[3])
        : "r"(a[0]), "r"(a[1]), "r"(a[2]), "r"(a[3]), "r"(b[0]), "r"(b[1]));
}
__device__ __forceinline__ void ldsm_x4(u32* r, unsigned addr) {
    asm volatile("ldmatrix.sync.aligned.m8n8.x4.shared.b16 {%0,%1,%2,%3}, [%4];"
        : "=r"(r[0]), "=r"(r[1]), "=r"(r[2]), "=r"(r[3]) : "r"(addr));
}
__device__ __forceinline__ void ldsm_x2(u32* r, unsigned addr) {
    asm volatile("ldmatrix.sync.aligned.m8n8.x2.shared.b16 {%0,%1}, [%2];"
        : "=r"(r[0]), "=r"(r[1]) : "r"(addr));
}
__device__ __forceinline__ u32 packhf(float lo, float hi) {
    __half2 t = __floats2half2_rn(lo, hi);
    return *(u32*)&t;
}
__device__ __forceinline__ float2 h2ff(u32 v) {
    __half2 t; *(u32*)&t = v;
    return __half22float2(t);
}

// ---------------------------------------------------------------------------
// Mask precompute (8 elements/thread)
// ---------------------------------------------------------------------------
__device__ __forceinline__ unsigned char code_one(float d, int mk, int i, int j) {
    if (mk == 0) return (unsigned char)255;
    if (i == 0 || j == 0) return (unsigned char)0;
    unsigned char c = 0;
    c += (d >= 0.2f); c += (d >= 0.3f); c += (d >= 0.4f); c += (d >= 0.5f);
    c += (d >= 0.6f); c += (d >= 0.7f); c += (d >= 0.8f); c += (d >= 0.9f);
    return c;
}

__global__ __launch_bounds__(256) void code_kernel(const float* __restrict__ dist,
                                                   const int* __restrict__ mask) {
    int t = blockIdx.x * blockDim.x + threadIdx.x;
    int base = t * 8;
    int rem = base & (Nn*Nn - 1);
    int i = rem >> 10;
    int j0 = rem & (Nn - 1);
    float4 dv0 = *(const float4*)(dist + base);
    float4 dv1 = *(const float4*)(dist + base + 4);
    int4  mv0 = *(const int4*)(mask + base);
    int4  mv1 = *(const int4*)(mask + base + 4);
    uchar4 o0, o1;
    o0.x = code_one(dv0.x, mv0.x, i, j0 + 0);
    o0.y = code_one(dv0.y, mv0.y, i, j0 + 1);
    o0.z = code_one(dv0.z, mv0.z, i, j0 + 2);
    o0.w = code_one(dv0.w, mv0.w, i, j0 + 3);
    o1.x = code_one(dv1.x, mv1.x, i, j0 + 4);
    o1.y = code_one(dv1.y, mv1.y, i, j0 + 5);
    o1.z = code_one(dv1.z, mv1.z, i, j0 + 6);
    o1.w = code_one(dv1.w, mv1.w, i, j0 + 7);
    uint2 pack;
    pack.x = *(u32*)&o0;
    pack.y = *(u32*)&o1;
    *(uint2*)(g_code + base) = pack;
}

// ---------------------------------------------------------------------------
// Splits: X -> single fp16; W -> single fp16 (2 x float4 per thread)
// ---------------------------------------------------------------------------
__global__ __launch_bounds__(256) void split_x_kernel(const float* __restrict__ s0,
                                                      const float* __restrict__ s1,
                                                      const float* __restrict__ s2) {
    int which = blockIdx.y;
    const float* src = (which == 0) ? s0 : (which == 1) ? s1 : s2;
    int t0 = (blockIdx.x * blockDim.x + threadIdx.x) * 2;
    u32* h2 = (u32*)gXs[which];
    float4 va = ((const float4*)src)[t0];
    float4 vb = ((const float4*)src)[t0 + 1];
    h2[2*t0+0] = packhf(va.x, va.y);
    h2[2*t0+1] = packhf(va.z, va.w);
    h2[2*t0+2] = packhf(vb.x, vb.y);
    h2[2*t0+3] = packhf(vb.z, vb.w);
}

__global__ __launch_bounds__(256) void split_w_kernel(const float* __restrict__ s0,
                                                      const float* __restrict__ s1,
                                                      const float* __restrict__ s2,
                                                      const float* __restrict__ s3) {
    int which = blockIdx.y;
    const float* src = (which == 0) ? s0 : (which == 1) ? s1
                      : (which == 2) ? s2 : s3;
    int t0 = (blockIdx.x * blockDim.x + threadIdx.x) * 2;
    u32* h2 = (u32*)gWs[which];
    float4 va = ((const float4*)src)[t0];
    float4 vb = ((const float4*)src)[t0 + 1];
    h2[2*t0+0] = packhf(va.x, va.y);
    h2[2*t0+1] = packhf(va.z, va.w);
    h2[2*t0+2] = packhf(vb.x, vb.y);
    h2[2*t0+3] = packhf(vb.z, vb.w);
}

#define TSTRIDE 40
#define TILE_US (128 * TSTRIDE)

// ---------------------------------------------------------------------------
// gemm_1t: 1-term fp16 GEMM for QKV projections (A single, W single)
// blockIdx.z = 0/1/2 -> Q/K/V. Epilogues: Q,K [b,h,n,d] single; V transposed.
// ---------------------------------------------------------------------------
#define G1_SMEM_BYTES (4 * TILE_US * 2)      // 40960

__global__ __launch_bounds__(256, 2) void gemm_1t(const float* __restrict__ bias0,
                                                  const float* __restrict__ bias1,
                                                  const float* __restrict__ bias2) {
    extern __shared__ unsigned short gsm[];
    unsigned sbase = smem_u32(gsm);

    int sel = blockIdx.z;
    const __half* Ahg = gXs[sel];
    const __half* Wsg = gWs[sel];
    const float* bias = (sel == 0) ? bias0 : (sel == 1) ? bias1 : bias2;

    int tid = threadIdx.x;
    int wid = tid >> 5, lane = tid & 31;
    int wr = wid >> 2, wc = wid & 3;
    int gid = lane >> 2, tig = lane & 3;
    int m0 = blockIdx.x * 128, n0 = blockIdx.y * 128;

    int id0 = tid, id1 = 256 + tid;
    int r0 = id0 >> 2, c80 = (id0 & 3) * 8;
    int r1 = id1 >> 2, c81 = (id1 & 3) * 8;

    int rA = lane & 15, kA = (lane >> 4) * 8;
    int rB = lane & 7,  kB = ((lane >> 3) & 1) * 8;

    float c[4][4][4];
    #pragma unroll
    for (int mt = 0; mt < 4; mt++)
        #pragma unroll
        for (int nt = 0; nt < 4; nt++)
            #pragma unroll
            for (int q = 0; q < 4; q++) c[mt][nt][q] = 0.0f;

    auto load_chunk = [&](int kc, int buf) {
        int kb = kc * 32;
        unsigned base = (unsigned)(buf * 2 * TILE_US);
        int a0 = (m0 + r0) * Ee + kb + c80;
        int a1 = (m0 + r1) * Ee + kb + c81;
        cpasync16(sbase + (base + r0 * TSTRIDE + c80) * 2, Ahg + a0);
        cpasync16(sbase + (base + r1 * TSTRIDE + c81) * 2, Ahg + a1);
        int w0 = (n0 + r0) * Ee + kb + c80;
        int w1 = (n0 + r1) * Ee + kb + c81;
        cpasync16(sbase + (base + TILE_US + r0 * TSTRIDE + c80) * 2, Wsg + w0);
        cpasync16(sbase + (base + TILE_US + r1 * TSTRIDE + c81) * 2, Wsg + w1);
        cpcommit();
    };

    load_chunk(0, 0);

    for (int kc = 0; kc < 16; kc++) {
        int buf = kc & 1;
        if (kc < 15) load_chunk(kc + 1, buf ^ 1);
        if (kc < 15) cpwait<1>(); else cpwait<0>();
        __syncthreads();

        unsigned base = (unsigned)(buf * 2 * TILE_US);
        unsigned ah_b = sbase + base * 2;
        unsigned wh_b = sbase + (base + TILE_US) * 2;

        #pragma unroll
        for (int ks = 0; ks < 2; ks++) {
            int k0 = ks * 16;
            u32 bh[4][2];
            #pragma unroll
            for (int nt = 0; nt < 4; nt++) {
                unsigned boff = ((wc * 32 + nt * 8 + rB) * TSTRIDE + k0 + kB) * 2;
                ldsm_x2(bh[nt], wh_b + boff);
            }
            #pragma unroll
            for (int mt = 0; mt < 4; mt++) {
                unsigned aoff = ((wr * 64 + mt * 16 + rA) * TSTRIDE + k0 + kA) * 2;
                u32 ah[4];
                ldsm_x4(ah, ah_b + aoff);
                #pragma unroll
                for (int nt = 0; nt < 4; nt++)
                    mma16816h(c[mt][nt], ah, bh[nt]);
            }
        }
        __syncthreads();
    }

    // Epilogue
    #pragma unroll
    for (int mt = 0; mt < 4; mt++) {
        #pragma unroll
        for (int nt = 0; nt < 4; nt++) {
            int row = m0 + wr * 64 + mt * 16 + gid;
            int col = n0 + wc * 32 + nt * 8 + tig * 2;
            float b0v = bias[col], b1v = bias[col + 1];
            float v00 = c[mt][nt][0] + b0v, v01 = c[mt][nt][1] + b1v;
            float v10 = c[mt][nt][2] + b0v, v11 = c[mt][nt][3] + b1v;
            int b_ = row >> 10, n = row & (Nn - 1);
            int hh = col >> 6, d = col & 63;
            if (sel <= 1) {
                __half* Hp = (sel == 0) ? gQh : gKh;
                int a0 = (((b_ << 3) + hh) * Nn + n) * Dd + d;
                int a1 = a0 + 8 * Dd;
                *(u32*)(Hp + a0) = packhf(v00, v01);
                *(u32*)(Hp + a1) = packhf(v10, v11);
            } else {
                int base = ((b_ << 3) + hh) * Dd;
                int i00 = (base + d) * Nn + n;
                int i01 = (base + d + 1) * Nn + n;
                gVth[i00]     = __float2half(v00);
                gVth[i01]     = __float2half(v01);
                gVth[i00 + 8] = __float2half(v10);
                gVth[i01 + 8] = __float2half(v11);
            }
        }
    }
}

// ---------------------------------------------------------------------------
// gemm_mma: 2-term fp16 GEMM, oproj only (A = gAh+gAl, W = Wo, fp32 flat out)
// ---------------------------------------------------------------------------
#define GEMM_SMEM_BYTES (6 * TILE_US * 2)

__global__ __launch_bounds__(256, 2) void gemm_mma(const float* __restrict__ bias,
                                                   float* __restrict__ outext) {
    extern __shared__ unsigned short gsm[];
    unsigned sbase = smem_u32(gsm);

    const __half* Ahg = gAh;
    const __half* Alg = gAl;
    const __half* Wsg = gWs[3];

    int tid = threadIdx.x;
    int wid = tid >> 5, lane = tid & 31;
    int wr = wid >> 2, wc = wid & 3;
    int gid = lane >> 2, tig = lane & 3;
    int m0 = blockIdx.x * 128, n0 = blockIdx.y * 128;

    int id0 = tid, id1 = 256 + tid;
    int r0 = id0 >> 2, c80 = (id0 & 3) * 8;
    int r1 = id1 >> 2, c81 = (id1 & 3) * 8;

    int rA = lane & 15, kA = (lane >> 4) * 8;
    int rB = lane & 7,  kB = ((lane >> 3) & 1) * 8;

    float c[4][4][4];
    #pragma unroll
    for (int mt = 0; mt < 4; mt++)
        #pragma unroll
        for (int nt = 0; nt < 4; nt++)
            #pragma unroll
            for (int q = 0; q < 4; q++) c[mt][nt][q] = 0.0f;

    auto load_chunk = [&](int kc, int buf) {
        int kb = kc * 32;
        unsigned base = (unsigned)(buf * 3 * TILE_US);
        {
            int a0 = (m0 + r0) * Ee + kb + c80;
            int a1 = (m0 + r1) * Ee + kb + c81;
            cpasync16(sbase + (base + r0 * TSTRIDE + c80) * 2, Ahg + a0);
            cpasync16(sbase + (base + r1 * TSTRIDE + c81) * 2, Ahg + a1);
            cpasync16(sbase + (base + TILE_US + r0 * TSTRIDE + c80) * 2, Alg + a0);
            cpasync16(sbase + (base + TILE_US + r1 * TSTRIDE + c81) * 2, Alg + a1);
        }
        {
            int w0 = (n0 + r0) * Ee + kb + c80;
            int w1 = (n0 + r1) * Ee + kb + c81;
            cpasync16(sbase + (base + 2 * TILE_US + r0 * TSTRIDE + c80) * 2, Wsg + w0);
            cpasync16(sbase + (base + 2 * TILE_US + r1 * TSTRIDE + c81) * 2, Wsg + w1);
        }
        cpcommit();
    };

    load_chunk(0, 0);

    for (int kc = 0; kc < 16; kc++) {
        int buf = kc & 1;
        if (kc < 15) load_chunk(kc + 1, buf ^ 1);
        if (kc < 15) cpwait<1>(); else cpwait<0>();
        __syncthreads();

        unsigned base = (unsigned)(buf * 3 * TILE_US);
        unsigned ah_b = sbase + base * 2;
        unsigned al_b = sbase + (base + TILE_US) * 2;
        unsigned wh_b = sbase + (base + 2 * TILE_US) * 2;

        #pragma unroll
        for (int ks = 0; ks < 2; ks++) {
            int k0 = ks * 16;
            u32 bh[4][2];
            #pragma unroll
            for (int nt = 0; nt < 4; nt++) {
                unsigned boff = ((wc * 32 + nt * 8 + rB) * TSTRIDE + k0 + kB) * 2;
                ldsm_x2(bh[nt], wh_b + boff);
            }
            #pragma unroll
            for (int mt = 0; mt < 4; mt++) {
                unsigned aoff = ((wr * 64 + mt * 16 + rA) * TSTRIDE + k0 + kA) * 2;
                u32 ah[4], al[4];
                ldsm_x4(ah, ah_b + aoff);
                ldsm_x4(al, al_b + aoff);
                #pragma unroll
                for (int nt = 0; nt < 4; nt++) {
                    mma16816h(c[mt][nt], ah, bh[nt]);
                    mma16816h(c[mt][nt], al, bh[nt]);
                }
            }
        }
        __syncthreads();
    }

    #pragma unroll
    for (int mt = 0; mt < 4; mt++) {
        #pragma unroll
        for (int nt = 0; nt < 4; nt++) {
            int row = m0 + wr * 64 + mt * 16 + gid;
            int col = n0 + wc * 32 + nt * 8 + tig * 2;
            float b0v = bias[col], b1v = bias[col + 1];
            *(float2*)(outext + row * Ee + col) =
                make_float2(c[mt][nt][0] + b0v, c[mt][nt][1] + b1v);
            *(float2*)(outext + (row + 8) * Ee + col) =
                make_float2(c[mt][nt][2] + b0v, c[mt][nt][3] + b1v);
        }
    }
}

// ---------------------------------------------------------------------------
// HMMA flash attention: QK 1-term, PV 1-term (R12 verbatim)
// ---------------------------------------------------------------------------
#define FTS 72
#define FQ_H 0
#define FSTG0 (128 * FTS)
#define FSTG_SZ (2 * 64 * FTS)
#define FV_OFF (64 * FTS)
#define FLASH_SMEM ((FSTG0 + 2 * FSTG_SZ) * 2)

__global__ __launch_bounds__(256, 2) void flash_mma() {
    extern __shared__ unsigned short fsm[];
    unsigned sbase = smem_u32(fsm);

    int rb = blockIdx.x, h = blockIdx.y, b = blockIdx.z;
    int tid = threadIdx.x, wid = tid >> 5, lane = tid & 31;
    int gid = lane >> 2, tig = lane & 3;
    int bh = b * Hh + h;

    const __half* Qhg = gQh + (bh * Nn + rb * 128) * Dd;
    const __half* Khg = gKh + bh * Nn * Dd;
    const __half* Vhg = gVth + bh * Dd * Nn;
    const unsigned char* codeg = g_code + (b * Nn + rb * 128) * Nn;

    int rA = lane & 15, kA = (lane >> 4) * 8;
    int rB = lane & 7,  kB = ((lane >> 3) & 1) * 8;

    auto load_kv = [&](int kb, int s) {
        unsigned stg = (unsigned)(FSTG0 + s * FSTG_SZ);
        #pragma unroll
        for (int l = 0; l < 2; l++) {
            int idx = tid + l * 256;
            int row = idx >> 3, c8 = (idx & 7) * 8;
            unsigned so = (row * FTS + c8) * 2;
            cpasync16(sbase + stg * 2 + so, Khg + (kb * 64 + row) * Dd + c8);
            cpasync16(sbase + (stg + FV_OFF) * 2 + so, Vhg + row * Nn + kb * 64 + c8);
        }
        cpcommit();
    };

    #pragma unroll
    for (int l = 0; l < 4; l++) {
        int idx = tid + l * 256;
        int row = idx >> 3, c8 = (idx & 7) * 8;
        cpasync16(sbase + (FQ_H + row * FTS + c8) * 2, Qhg + row * Dd + c8);
    }
    load_kv(0, 0);

    unsigned qh_base = sbase + ((FQ_H + (wid * 16 + rA) * FTS + kA) * 2);

    float co[8][4];
    #pragma unroll
    for (int dt = 0; dt < 8; dt++)
        #pragma unroll
        for (int q = 0; q < 4; q++) co[dt][q] = 0.0f;
    float m0r = -1e30f, m1r = -1e30f, l0r = 0.0f, l1r = 0.0f;

    int crow0 = wid * 16 + gid;
    const unsigned char* cp0 = codeg + crow0 * Nn + tig * 2;
    const unsigned char* cp1 = codeg + (crow0 + 8) * Nn + tig * 2;

    for (int kb = 0; kb < 16; kb++) {
        int buf = kb & 1;
        __syncthreads();
        if (kb < 15) load_kv(kb + 1, buf ^ 1);
        if (kb < 15) cpwait<1>(); else cpwait<0>();
        __syncthreads();

        unsigned short cw0[8], cw1[8];
        #pragma unroll
        for (int nt = 0; nt < 8; nt++) {
            cw0[nt] = *(const unsigned short*)(cp0 + kb * 64 + nt * 8);
            cw1[nt] = *(const unsigned short*)(cp1 + kb * 64 + nt * 8);
        }

        unsigned stg = (unsigned)(FSTG0 + buf * FSTG_SZ);
        unsigned kh_b = sbase + stg * 2;
        unsigned vh_b = sbase + (stg + FV_OFF) * 2;

        float sc[8][4];
        #pragma unroll
        for (int nt = 0; nt < 8; nt++)
            #pragma unroll
            for (int q = 0; q < 4; q++) sc[nt][q] = 0.0f;

        #pragma unroll
        for (int ks = 0; ks < 4; ks++) {
            u32 ah[4];
            ldsm_x4(ah, qh_base + ks * 32);
            #pragma unroll
            for (int nt = 0; nt < 8; nt++) {
                unsigned kaddr = kh_b + ((nt * 8 + rB) * FTS + ks * 16 + kB) * 2;
                u32 bh2[2];
                ldsm_x2(bh2, kaddr);
                mma16816h(sc[nt], ah, bh2);
            }
        }

        #pragma unroll
        for (int nt = 0; nt < 8; nt++) {
            sc[nt][0] = ((unsigned)h >= (cw0[nt] & 255u)) ? sc[nt][0] * 0.125f : NEGV;
            sc[nt][1] = ((unsigned)h >= (cw0[nt] >> 8))   ? sc[nt][1] * 0.125f : NEGV;
            sc[nt][2] = ((unsigned)h >= (cw1[nt] & 255u)) ? sc[nt][2] * 0.125f : NEGV;
            sc[nt][3] = ((unsigned)h >= (cw1[nt] >> 8))   ? sc[nt][3] * 0.125f : NEGV;
        }

        float rm0 = -1e30f, rm1 = -1e30f;
        #pragma unroll
        for (int nt = 0; nt < 8; nt++) {
            rm0 = fmaxf(rm0, fmaxf(sc[nt][0], sc[nt][1]));
            rm1 = fmaxf(rm1, fmaxf(sc[nt][2], sc[nt][3]));
        }
        rm0 = fmaxf(rm0, __shfl_xor_sync(0xffffffffu, rm0, 1));
        rm0 = fmaxf(rm0, __shfl_xor_sync(0xffffffffu, rm0, 2));
        rm1 = fmaxf(rm1, __shfl_xor_sync(0xffffffffu, rm1, 1));
        rm1 = fmaxf(rm1, __shfl_xor_sync(0xffffffffu, rm1, 2));
        float mn0 = fmaxf(m0r, rm0), mn1 = fmaxf(m1r, rm1);
        float corr0 = __expf(m0r - mn0), corr1 = __expf(m1r - mn1);
        m0r = mn0; m1r = mn1;

        float ps0 = 0.0f, ps1 = 0.0f;
        #pragma unroll
        for (int nt = 0; nt < 8; nt++) {
            sc[nt][0] = __expf(sc[nt][0] - mn0);
            sc[nt][1] = __expf(sc[nt][1] - mn0);
            sc[nt][2] = __expf(sc[nt][2] - mn1);
            sc[nt][3] = __expf(sc[nt][3] - mn1);
            ps0 += sc[nt][0] + sc[nt][1];
            ps1 += sc[nt][2] + sc[nt][3];
        }
        ps0 += __shfl_xor_sync(0xffffffffu, ps0, 1);
        ps0 += __shfl_xor_sync(0xffffffffu, ps0, 2);
        ps1 += __shfl_xor_sync(0xffffffffu, ps1, 1);
        ps1 += __shfl_xor_sync(0xffffffffu, ps1, 2);
        l0r = l0r * corr0 + ps0;
        l1r = l1r * corr1 + ps1;

        #pragma unroll
        for (int dt = 0; dt < 8; dt++) {
            co[dt][0] *= corr0; co[dt][1] *= corr0;
            co[dt][2] *= corr1; co[dt][3] *= corr1;
        }

        #pragma unroll
        for (int kc = 0; kc < 4; kc++) {
            u32 pah[4];
            pah[0] = packhf(sc[2*kc][0],   sc[2*kc][1]);
            pah[1] = packhf(sc[2*kc][2],   sc[2*kc][3]);
            pah[2] = packhf(sc[2*kc+1][0], sc[2*kc+1][1]);
            pah[3] = packhf(sc[2*kc+1][2], sc[2*kc+1][3]);
            #pragma unroll
            for (int dt = 0; dt < 8; dt++) {
                unsigned vaddr = vh_b + ((dt * 8 + rB) * FTS + kc * 16 + kB) * 2;
                u32 vh2[2];
                ldsm_x2(vh2, vaddr);
                mma16816h(co[dt], pah, vh2);
            }
        }
    }

    float inv0 = 1.0f / l0r, inv1 = 1.0f / l1r;
    int nrow = rb * 128 + wid * 16 + gid;
    int a0base = ((b << 10) + nrow) * Ee + (h << 6);
    int a1base = a0base + 8 * Ee;
    #pragma unroll
    for (int dt = 0; dt < 8; dt++) {
        int d = dt * 8 + tig * 2;
        float v00 = co[dt][0] * inv0, v01 = co[dt][1] * inv0;
        float v10 = co[dt][2] * inv1, v11 = co[dt][3] * inv1;
        u32 h0 = packhf(v00, v01), h1 = packhf(v10, v11);
        float2 f0 = h2ff(h0), f1 = h2ff(h1);
        *(u32*)(gAh + a0base + d) = h0;
        *(u32*)(gAh + a1base + d) = h1;
        *(u32*)(gAl + a0base + d) = packhf(v00 - f0.x, v01 - f0.y);
        *(u32*)(gAl + a1base + d) = packhf(v10 - f1.x, v11 - f1.y);
    }
}

// ---------------------------------------------------------------------------
extern "C" void kernel_launch(void* const* d_in, const int* in_sizes, int n_in,
                              void* d_out, int out_size) {
    const float* query = (const float*)d_in[0];
    const float* key   = (const float*)d_in[1];
    const float* value = (const float*)d_in[2];
    const float* dist  = (const float*)d_in[3];
    const int*   mask  = (const int*)d_in[4];
    const float* Wq = (const float*)d_in[5];
    const float* bq = (const float*)d_in[6];
    const float* Wk = (const float*)d_in[7];
    const float* bk = (const float*)d_in[8];
    const float* Wv = (const float*)d_in[9];
    const float* bv = (const float*)d_in[10];
    const float* Wo = (const float*)d_in[11];
    const float* bo = (const float*)d_in[12];
    float* out = (float*)d_out;

    cudaFuncSetAttribute(gemm_1t, cudaFuncAttributeMaxDynamicSharedMemorySize, G1_SMEM_BYTES);
    cudaFuncSetAttribute(gemm_mma, cudaFuncAttributeMaxDynamicSharedMemorySize, GEMM_SMEM_BYTES);
    cudaFuncSetAttribute(flash_mma, cudaFuncAttributeMaxDynamicSharedMemorySize, FLASH_SMEM);

    // 1) mask code precompute
    code_kernel<<<(Bb * Nn * Nn) / (8 * 256), 256>>>(dist, mask);

    // 2) conversions
    const int NX8 = (Bb * Nn * Ee) / 8;
    const int NW8 = (Ee * Ee) / 8;
    split_x_kernel<<<dim3(NX8 / 256, 3), 256>>>(query, key, value);
    split_w_kernel<<<dim3(NW8 / 256, 4), 256>>>(Wq, Wk, Wv, Wo);

    // 3) fused Q/K/V projections (1-term)
    gemm_1t<<<dim3((Bb * Nn) / 128, Ee / 128, 3), 256, G1_SMEM_BYTES>>>(bq, bk, bv);

    // 4) flash attention
    flash_mma<<<dim3(Nn / 128, Hh, Bb), 256, FLASH_SMEM>>>();

    // 5) output projection (2-term)
    gemm_mma<<<dim3((Bb * Nn) / 128, Ee / 128), 256, GEMM_SMEM_BYTES>>>(bo, out);
}

// round 14
// speedup vs baseline: 2.4831x; 1.0715x over previous
#include <cuda_runtime.h>
#include <cuda_bf16.h>
#include <cuda_fp16.h>

#define Bb 8
#define Nn 1024
#define Ee 512
#define Hh 8
#define Dd 64
#define NEGV -1000000000.0f
#define SCL2 0.1803368801111204f   // 0.125 * log2(e)

typedef unsigned long long u64;
typedef unsigned int u32;

// ---------------------------------------------------------------------------
// Scratch (device globals; referenced only from device code)
// ---------------------------------------------------------------------------
__device__ unsigned char g_code[Bb*Nn*Nn];

__device__ __half gXs[3][Bb*Nn*Ee];          // inputs single fp16
__device__ __half gWs[4][Ee*Ee];             // weights single fp16

__device__ __half gQh[Bb*Hh*Nn*Dd];          // Q single fp16 [b,h,n,d]
__device__ __half gKh[Bb*Hh*Nn*Dd];          // K single fp16 [b,h,n,d]
__device__ __half gVth[Bb*Hh*Dd*Nn];         // V single fp16 transposed [b,h,d,n]
__device__ __half gAh[Bb*Nn*Ee];             // attn out split fp16 (2-term oproj)
__device__ __half gAl[Bb*Nn*Ee];

// ---------------------------------------------------------------------------
// PTX helpers
// ---------------------------------------------------------------------------
__device__ __forceinline__ unsigned smem_u32(const void* p) {
    unsigned a;
    asm("{ .reg .u64 t; cvta.to.shared.u64 t, %1; cvt.u32.u64 %0, t; }"
        : "=r"(a) : "l"(p));
    return a;
}
__device__ __forceinline__ void cpasync16(unsigned dst, const void* src) {
    asm volatile("cp.async.ca.shared.global [%0], [%1], 16;" :: "r"(dst), "l"(src));
}
__device__ __forceinline__ void cpcommit() {
    asm volatile("cp.async.commit_group;" ::: "memory");
}
template<int N> __device__ __forceinline__ void cpwait() {
    asm volatile("cp.async.wait_group %0;" :: "n"(N) : "memory");
}
__device__ __forceinline__ void mma16816h(float* c, const u32* a, const u32* b) {
    asm volatile("mma.sync.aligned.m16n8k16.row.col.f32.f16.f16.f32 "
        "{%0,%1,%2,%3}, {%4,%5,%6,%7}, {%8,%9}, {%0,%1,%2,%3};"
        : "+f"(c[0]), "+f"(c[1]), "+f"(c[2]), "+f"(c[3])
        : "r"(a[0]), "r"(a[1]), "r"(a[2]), "r"(a[3]), "r"(b[0]), "r"(b[1]));
}
__device__ __forceinline__ void ldsm_x4(u32* r, unsigned addr) {
    asm volatile("ldmatrix.sync.aligned.m8n8.x4.shared.b16 {%0,%1,%2,%3}, [%4];"
        : "=r"(r[0]), "=r"(r[1]), "=r"(r[2]), "=r"(r[3]) : "r"(addr));
}
__device__ __forceinline__ void ldsm_x2(u32* r, unsigned addr) {
    asm volatile("ldmatrix.sync.aligned.m8n8.x2.shared.b16 {%0,%1}, [%2];"
        : "=r"(r[0]), "=r"(r[1]) : "r"(addr));
}
__device__ __forceinline__ float ex2(float x) {
    float y; asm("ex2.approx.f32 %0, %1;" : "=f"(y) : "f"(x)); return y;
}
__device__ __forceinline__ u32 packhf(float lo, float hi) {
    __half2 t = __floats2half2_rn(lo, hi);
    return *(u32*)&t;
}
__device__ __forceinline__ float2 h2ff(u32 v) {
    __half2 t; *(u32*)&t = v;
    return __half22float2(t);
}

// ---------------------------------------------------------------------------
// Mask precompute (8 elements/thread)
// ---------------------------------------------------------------------------
__device__ __forceinline__ unsigned char code_one(float d, int mk, int i, int j) {
    if (mk == 0) return (unsigned char)255;
    if (i == 0 || j == 0) return (unsigned char)0;
    unsigned char c = 0;
    c += (d >= 0.2f); c += (d >= 0.3f); c += (d >= 0.4f); c += (d >= 0.5f);
    c += (d >= 0.6f); c += (d >= 0.7f); c += (d >= 0.8f); c += (d >= 0.9f);
    return c;
}

__global__ __launch_bounds__(256) void code_kernel(const float* __restrict__ dist,
                                                   const int* __restrict__ mask) {
    int t = blockIdx.x * blockDim.x + threadIdx.x;
    int base = t * 8;
    int rem = base & (Nn*Nn - 1);
    int i = rem >> 10;
    int j0 = rem & (Nn - 1);
    float4 dv0 = *(const float4*)(dist + base);
    float4 dv1 = *(const float4*)(dist + base + 4);
    int4  mv0 = *(const int4*)(mask + base);
    int4  mv1 = *(const int4*)(mask + base + 4);
    uchar4 o0, o1;
    o0.x = code_one(dv0.x, mv0.x, i, j0 + 0);
    o0.y = code_one(dv0.y, mv0.y, i, j0 + 1);
    o0.z = code_one(dv0.z, mv0.z, i, j0 + 2);
    o0.w = code_one(dv0.w, mv0.w, i, j0 + 3);
    o1.x = code_one(dv1.x, mv1.x, i, j0 + 4);
    o1.y = code_one(dv1.y, mv1.y, i, j0 + 5);
    o1.z = code_one(dv1.z, mv1.z, i, j0 + 6);
    o1.w = code_one(dv1.w, mv1.w, i, j0 + 7);
    uint2 pack;
    pack.x = *(u32*)&o0;
    pack.y = *(u32*)&o1;
    *(uint2*)(g_code + base) = pack;
}

// ---------------------------------------------------------------------------
// Conversions: X, W -> single fp16 (2 x float4 per thread)
// ---------------------------------------------------------------------------
__global__ __launch_bounds__(256) void split_x_kernel(const float* __restrict__ s0,
                                                      const float* __restrict__ s1,
                                                      const float* __restrict__ s2) {
    int which = blockIdx.y;
    const float* src = (which == 0) ? s0 : (which == 1) ? s1 : s2;
    int t0 = (blockIdx.x * blockDim.x + threadIdx.x) * 2;
    u32* h2 = (u32*)gXs[which];
    float4 va = ((const float4*)src)[t0];
    float4 vb = ((const float4*)src)[t0 + 1];
    h2[2*t0+0] = packhf(va.x, va.y);
    h2[2*t0+1] = packhf(va.z, va.w);
    h2[2*t0+2] = packhf(vb.x, vb.y);
    h2[2*t0+3] = packhf(vb.z, vb.w);
}

__global__ __launch_bounds__(256) void split_w_kernel(const float* __restrict__ s0,
                                                      const float* __restrict__ s1,
                                                      const float* __restrict__ s2,
                                                      const float* __restrict__ s3) {
    int which = blockIdx.y;
    const float* src = (which == 0) ? s0 : (which == 1) ? s1
                      : (which == 2) ? s2 : s3;
    int t0 = (blockIdx.x * blockDim.x + threadIdx.x) * 2;
    u32* h2 = (u32*)gWs[which];
    float4 va = ((const float4*)src)[t0];
    float4 vb = ((const float4*)src)[t0 + 1];
    h2[2*t0+0] = packhf(va.x, va.y);
    h2[2*t0+1] = packhf(va.z, va.w);
    h2[2*t0+2] = packhf(vb.x, vb.y);
    h2[2*t0+3] = packhf(vb.z, vb.w);
}

// K-chunk 64: rows are 64 halves + 8 pad = 72 (144B stride -> conflict-free)
#define TSTRIDE 72
#define TILE_US (128 * TSTRIDE)     // 9216 ushorts = 18432 B per tile

// ---------------------------------------------------------------------------
// gemm_1t: 1-term fp16 GEMM for QKV projections, K-chunk 64 (8 chunks)
// ---------------------------------------------------------------------------
#define G1_SMEM_BYTES (4 * TILE_US * 2)      // 73728

__global__ __launch_bounds__(256, 2) void gemm_1t(const float* __restrict__ bias0,
                                                  const float* __restrict__ bias1,
                                                  const float* __restrict__ bias2) {
    extern __shared__ unsigned short gsm[];
    unsigned sbase = smem_u32(gsm);

    int sel = blockIdx.z;
    const __half* Ahg = gXs[sel];
    const __half* Wsg = gWs[sel];
    const float* bias = (sel == 0) ? bias0 : (sel == 1) ? bias1 : bias2;

    int tid = threadIdx.x;
    int wid = tid >> 5, lane = tid & 31;
    int wr = wid >> 2, wc = wid & 3;
    int gid = lane >> 2, tig = lane & 3;
    int m0 = blockIdx.x * 128, n0 = blockIdx.y * 128;

    int rA = lane & 15, kA = (lane >> 4) * 8;
    int rB = lane & 7,  kB = ((lane >> 3) & 1) * 8;

    float c[4][4][4];
    #pragma unroll
    for (int mt = 0; mt < 4; mt++)
        #pragma unroll
        for (int nt = 0; nt < 4; nt++)
            #pragma unroll
            for (int q = 0; q < 4; q++) c[mt][nt][q] = 0.0f;

    auto load_chunk = [&](int kc, int buf) {
        int kb = kc * 64;
        unsigned base = (unsigned)(buf * 2 * TILE_US);
        #pragma unroll
        for (int l = 0; l < 4; l++) {
            int idx = tid + l * 256;
            int row = idx >> 3, c8 = (idx & 7) * 8;
            unsigned so = (row * TSTRIDE + c8) * 2;
            cpasync16(sbase + base * 2 + so, Ahg + (m0 + row) * Ee + kb + c8);
            cpasync16(sbase + (base + TILE_US) * 2 + so, Wsg + (n0 + row) * Ee + kb + c8);
        }
        cpcommit();
    };

    load_chunk(0, 0);

    for (int kc = 0; kc < 8; kc++) {
        int buf = kc & 1;
        if (kc < 7) load_chunk(kc + 1, buf ^ 1);
        if (kc < 7) cpwait<1>(); else cpwait<0>();
        __syncthreads();

        unsigned base = (unsigned)(buf * 2 * TILE_US);
        unsigned ah_b = sbase + base * 2;
        unsigned wh_b = sbase + (base + TILE_US) * 2;

        #pragma unroll
        for (int ks = 0; ks < 4; ks++) {
            int k0 = ks * 16;
            u32 bh[4][2];
            #pragma unroll
            for (int nt = 0; nt < 4; nt++) {
                unsigned boff = ((wc * 32 + nt * 8 + rB) * TSTRIDE + k0 + kB) * 2;
                ldsm_x2(bh[nt], wh_b + boff);
            }
            #pragma unroll
            for (int mt = 0; mt < 4; mt++) {
                unsigned aoff = ((wr * 64 + mt * 16 + rA) * TSTRIDE + k0 + kA) * 2;
                u32 ah[4];
                ldsm_x4(ah, ah_b + aoff);
                #pragma unroll
                for (int nt = 0; nt < 4; nt++)
                    mma16816h(c[mt][nt], ah, bh[nt]);
            }
        }
        __syncthreads();
    }

    // Epilogue
    #pragma unroll
    for (int mt = 0; mt < 4; mt++) {
        #pragma unroll
        for (int nt = 0; nt < 4; nt++) {
            int row = m0 + wr * 64 + mt * 16 + gid;
            int col = n0 + wc * 32 + nt * 8 + tig * 2;
            float b0v = bias[col], b1v = bias[col + 1];
            float v00 = c[mt][nt][0] + b0v, v01 = c[mt][nt][1] + b1v;
            float v10 = c[mt][nt][2] + b0v, v11 = c[mt][nt][3] + b1v;
            int b_ = row >> 10, n = row & (Nn - 1);
            int hh = col >> 6, d = col & 63;
            if (sel <= 1) {
                __half* Hp = (sel == 0) ? gQh : gKh;
                int a0 = (((b_ << 3) + hh) * Nn + n) * Dd + d;
                int a1 = a0 + 8 * Dd;
                *(u32*)(Hp + a0) = packhf(v00, v01);
                *(u32*)(Hp + a1) = packhf(v10, v11);
            } else {
                int base = ((b_ << 3) + hh) * Dd;
                int i00 = (base + d) * Nn + n;
                int i01 = (base + d + 1) * Nn + n;
                gVth[i00]     = __float2half(v00);
                gVth[i01]     = __float2half(v01);
                gVth[i00 + 8] = __float2half(v10);
                gVth[i01 + 8] = __float2half(v11);
            }
        }
    }
}

// ---------------------------------------------------------------------------
// gemm_mma: 2-term fp16 GEMM, oproj only, K-chunk 64 (8 chunks)
// ---------------------------------------------------------------------------
#define GEMM_SMEM_BYTES (6 * TILE_US * 2)    // 110592

__global__ __launch_bounds__(256, 2) void gemm_mma(const float* __restrict__ bias,
                                                   float* __restrict__ outext) {
    extern __shared__ unsigned short gsm[];
    unsigned sbase = smem_u32(gsm);

    const __half* Ahg = gAh;
    const __half* Alg = gAl;
    const __half* Wsg = gWs[3];

    int tid = threadIdx.x;
    int wid = tid >> 5, lane = tid & 31;
    int wr = wid >> 2, wc = wid & 3;
    int gid = lane >> 2, tig = lane & 3;
    int m0 = blockIdx.x * 128, n0 = blockIdx.y * 128;

    int rA = lane & 15, kA = (lane >> 4) * 8;
    int rB = lane & 7,  kB = ((lane >> 3) & 1) * 8;

    float c[4][4][4];
    #pragma unroll
    for (int mt = 0; mt < 4; mt++)
        #pragma unroll
        for (int nt = 0; nt < 4; nt++)
            #pragma unroll
            for (int q = 0; q < 4; q++) c[mt][nt][q] = 0.0f;

    auto load_chunk = [&](int kc, int buf) {
        int kb = kc * 64;
        unsigned base = (unsigned)(buf * 3 * TILE_US);
        #pragma unroll
        for (int l = 0; l < 4; l++) {
            int idx = tid + l * 256;
            int row = idx >> 3, c8 = (idx & 7) * 8;
            unsigned so = (row * TSTRIDE + c8) * 2;
            int aoff = (m0 + row) * Ee + kb + c8;
            cpasync16(sbase + base * 2 + so, Ahg + aoff);
            cpasync16(sbase + (base + TILE_US) * 2 + so, Alg + aoff);
            cpasync16(sbase + (base + 2 * TILE_US) * 2 + so, Wsg + (n0 + row) * Ee + kb + c8);
        }
        cpcommit();
    };

    load_chunk(0, 0);

    for (int kc = 0; kc < 8; kc++) {
        int buf = kc & 1;
        if (kc < 7) load_chunk(kc + 1, buf ^ 1);
        if (kc < 7) cpwait<1>(); else cpwait<0>();
        __syncthreads();

        unsigned base = (unsigned)(buf * 3 * TILE_US);
        unsigned ah_b = sbase + base * 2;
        unsigned al_b = sbase + (base + TILE_US) * 2;
        unsigned wh_b = sbase + (base + 2 * TILE_US) * 2;

        #pragma unroll
        for (int ks = 0; ks < 4; ks++) {
            int k0 = ks * 16;
            u32 bh[4][2];
            #pragma unroll
            for (int nt = 0; nt < 4; nt++) {
                unsigned boff = ((wc * 32 + nt * 8 + rB) * TSTRIDE + k0 + kB) * 2;
                ldsm_x2(bh[nt], wh_b + boff);
            }
            #pragma unroll
            for (int mt = 0; mt < 4; mt++) {
                unsigned aoff = ((wr * 64 + mt * 16 + rA) * TSTRIDE + k0 + kA) * 2;
                u32 ah[4], al[4];
                ldsm_x4(ah, ah_b + aoff);
                ldsm_x4(al, al_b + aoff);
                #pragma unroll
                for (int nt = 0; nt < 4; nt++) {
                    mma16816h(c[mt][nt], ah, bh[nt]);
                    mma16816h(c[mt][nt], al, bh[nt]);
                }
            }
        }
        __syncthreads();
    }

    #pragma unroll
    for (int mt = 0; mt < 4; mt++) {
        #pragma unroll
        for (int nt = 0; nt < 4; nt++) {
            int row = m0 + wr * 64 + mt * 16 + gid;
            int col = n0 + wc * 32 + nt * 8 + tig * 2;
            float b0v = bias[col], b1v = bias[col + 1];
            *(float2*)(outext + row * Ee + col) =
                make_float2(c[mt][nt][0] + b0v, c[mt][nt][1] + b1v);
            *(float2*)(outext + (row + 8) * Ee + col) =
                make_float2(c[mt][nt][2] + b0v, c[mt][nt][3] + b1v);
        }
    }
}

// ---------------------------------------------------------------------------
// HMMA flash attention: QK 1-term, PV 1-term.
// 3-stage K/V pipeline, ONE __syncthreads per iteration, base-2 softmax.
// ---------------------------------------------------------------------------
#define FTS 72
#define FQ_H 0
#define FSTG0 (128 * FTS)
#define FSTG_SZ (2 * 64 * FTS)
#define FV_OFF (64 * FTS)
#define FLASH_SMEM ((FSTG0 + 3 * FSTG_SZ) * 2)   // 73728 bytes

__global__ __launch_bounds__(256, 2) void flash_mma() {
    extern __shared__ unsigned short fsm[];
    unsigned sbase = smem_u32(fsm);

    int rb = blockIdx.x, h = blockIdx.y, b = blockIdx.z;
    int tid = threadIdx.x, wid = tid >> 5, lane = tid & 31;
    int gid = lane >> 2, tig = lane & 3;
    int bh = b * Hh + h;

    const __half* Qhg = gQh + (bh * Nn + rb * 128) * Dd;
    const __half* Khg = gKh + bh * Nn * Dd;
    const __half* Vhg = gVth + bh * Dd * Nn;
    const unsigned char* codeg = g_code + (b * Nn + rb * 128) * Nn;

    int rA = lane & 15, kA = (lane >> 4) * 8;
    int rB = lane & 7,  kB = ((lane >> 3) & 1) * 8;

    auto load_kv = [&](int kb, int s) {
        unsigned stg = (unsigned)(FSTG0 + s * FSTG_SZ);
        #pragma unroll
        for (int l = 0; l < 2; l++) {
            int idx = tid + l * 256;
            int row = idx >> 3, c8 = (idx & 7) * 8;
            unsigned so = (row * FTS + c8) * 2;
            cpasync16(sbase + stg * 2 + so, Khg + (kb * 64 + row) * Dd + c8);
            cpasync16(sbase + (stg + FV_OFF) * 2 + so, Vhg + row * Nn + kb * 64 + c8);
        }
        cpcommit();
    };

    // Prologue: Q + stage0 (group 0), stage1 (group 1)
    #pragma unroll
    for (int l = 0; l < 4; l++) {
        int idx = tid + l * 256;
        int row = idx >> 3, c8 = (idx & 7) * 8;
        cpasync16(sbase + (FQ_H + row * FTS + c8) * 2, Qhg + row * Dd + c8);
    }
    load_kv(0, 0);
    load_kv(1, 1);

    unsigned qh_base = sbase + ((FQ_H + (wid * 16 + rA) * FTS + kA) * 2);

    float co[8][4];
    #pragma unroll
    for (int dt = 0; dt < 8; dt++)
        #pragma unroll
        for (int q = 0; q < 4; q++) co[dt][q] = 0.0f;
    float m0r = -1e30f, m1r = -1e30f, l0r = 0.0f, l1r = 0.0f;

    int crow0 = wid * 16 + gid;
    const unsigned char* cp0 = codeg + crow0 * Nn + tig * 2;
    const unsigned char* cp1 = codeg + (crow0 + 8) * Nn + tig * 2;

    for (int kb = 0; kb < 16; kb++) {
        // wait for this iteration's group (pending: kb, kb+1)
        if (kb < 15) cpwait<1>(); else cpwait<0>();
        __syncthreads();                          // single barrier per iteration
        if (kb < 14) load_kv(kb + 2, (kb + 2) % 3);  // overwrites stage read in kb-1

        unsigned short cw0[8], cw1[8];
        #pragma unroll
        for (int nt = 0; nt < 8; nt++) {
            cw0[nt] = *(const unsigned short*)(cp0 + kb * 64 + nt * 8);
            cw1[nt] = *(const unsigned short*)(cp1 + kb * 64 + nt * 8);
        }

        unsigned stg = (unsigned)(FSTG0 + (kb % 3) * FSTG_SZ);
        unsigned kh_b = sbase + stg * 2;
        unsigned vh_b = sbase + (stg + FV_OFF) * 2;

        // ---- S = Q.K^T ----
        float sc[8][4];
        #pragma unroll
        for (int nt = 0; nt < 8; nt++)
            #pragma unroll
            for (int q = 0; q < 4; q++) sc[nt][q] = 0.0f;

        #pragma unroll
        for (int ks = 0; ks < 4; ks++) {
            u32 ah[4];
            ldsm_x4(ah, qh_base + ks * 32);
            #pragma unroll
            for (int nt = 0; nt < 8; nt++) {
                unsigned kaddr = kh_b + ((nt * 8 + rB) * FTS + ks * 16 + kB) * 2;
                u32 bh2[2];
                ldsm_x2(bh2, kaddr);
                mma16816h(sc[nt], ah, bh2);
            }
        }

        // ---- mask + scale (log2 domain) ----
        #pragma unroll
        for (int nt = 0; nt < 8; nt++) {
            sc[nt][0] = ((unsigned)h >= (cw0[nt] & 255u)) ? sc[nt][0] * SCL2 : NEGV;
            sc[nt][1] = ((unsigned)h >= (cw0[nt] >> 8))   ? sc[nt][1] * SCL2 : NEGV;
            sc[nt][2] = ((unsigned)h >= (cw1[nt] & 255u)) ? sc[nt][2] * SCL2 : NEGV;
            sc[nt][3] = ((unsigned)h >= (cw1[nt] >> 8))   ? sc[nt][3] * SCL2 : NEGV;
        }

        // ---- online softmax (base 2) ----
        float rm0 = -1e30f, rm1 = -1e30f;
        #pragma unroll
        for (int nt = 0; nt < 8; nt++) {
            rm0 = fmaxf(rm0, fmaxf(sc[nt][0], sc[nt][1]));
            rm1 = fmaxf(rm1, fmaxf(sc[nt][2], sc[nt][3]));
        }
        rm0 = fmaxf(rm0, __shfl_xor_sync(0xffffffffu, rm0, 1));
        rm0 = fmaxf(rm0, __shfl_xor_sync(0xffffffffu, rm0, 2));
        rm1 = fmaxf(rm1, __shfl_xor_sync(0xffffffffu, rm1, 1));
        rm1 = fmaxf(rm1, __shfl_xor_sync(0xffffffffu, rm1, 2));
        float mn0 = fmaxf(m0r, rm0), mn1 = fmaxf(m1r, rm1);
        float corr0 = ex2(m0r - mn0), corr1 = ex2(m1r - mn1);
        m0r = mn0; m1r = mn1;

        float ps0 = 0.0f, ps1 = 0.0f;
        #pragma unroll
        for (int nt = 0; nt < 8; nt++) {
            sc[nt][0] = ex2(sc[nt][0] - mn0);
            sc[nt][1] = ex2(sc[nt][1] - mn0);
            sc[nt][2] = ex2(sc[nt][2] - mn1);
            sc[nt][3] = ex2(sc[nt][3] - mn1);
            ps0 += sc[nt][0] + sc[nt][1];
            ps1 += sc[nt][2] + sc[nt][3];
        }
        ps0 += __shfl_xor_sync(0xffffffffu, ps0, 1);
        ps0 += __shfl_xor_sync(0xffffffffu, ps0, 2);
        ps1 += __shfl_xor_sync(0xffffffffu, ps1, 1);
        ps1 += __shfl_xor_sync(0xffffffffu, ps1, 2);
        l0r = l0r * corr0 + ps0;
        l1r = l1r * corr1 + ps1;

        #pragma unroll
        for (int dt = 0; dt < 8; dt++) {
            co[dt][0] *= corr0; co[dt][1] *= corr0;
            co[dt][2] *= corr1; co[dt][3] *= corr1;
        }

        // ---- O += P.V ----
        #pragma unroll
        for (int kc = 0; kc < 4; kc++) {
            u32 pah[4];
            pah[0] = packhf(sc[2*kc][0],   sc[2*kc][1]);
            pah[1] = packhf(sc[2*kc][2],   sc[2*kc][3]);
            pah[2] = packhf(sc[2*kc+1][0], sc[2*kc+1][1]);
            pah[3] = packhf(sc[2*kc+1][2], sc[2*kc+1][3]);
            #pragma unroll
            for (int dt = 0; dt < 8; dt++) {
                unsigned vaddr = vh_b + ((dt * 8 + rB) * FTS + kc * 16 + kB) * 2;
                u32 vh2[2];
                ldsm_x2(vh2, vaddr);
                mma16816h(co[dt], pah, vh2);
            }
        }
    }

    // ---- epilogue ----
    float inv0 = 1.0f / l0r, inv1 = 1.0f / l1r;
    int nrow = rb * 128 + wid * 16 + gid;
    int a0base = ((b << 10) + nrow) * Ee + (h << 6);
    int a1base = a0base + 8 * Ee;
    #pragma unroll
    for (int dt = 0; dt < 8; dt++) {
        int d = dt * 8 + tig * 2;
        float v00 = co[dt][0] * inv0, v01 = co[dt][1] * inv0;
        float v10 = co[dt][2] * inv1, v11 = co[dt][3] * inv1;
        u32 h0 = packhf(v00, v01), h1 = packhf(v10, v11);
        float2 f0 = h2ff(h0), f1 = h2ff(h1);
        *(u32*)(gAh + a0base + d) = h0;
        *(u32*)(gAh + a1base + d) = h1;
        *(u32*)(gAl + a0base + d) = packhf(v00 - f0.x, v01 - f0.y);
        *(u32*)(gAl + a1base + d) = packhf(v10 - f1.x, v11 - f1.y);
    }
}

// ---------------------------------------------------------------------------
extern "C" void kernel_launch(void* const* d_in, const int* in_sizes, int n_in,
                              void* d_out, int out_size) {
    const float* query = (const float*)d_in[0];
    const float* key   = (const float*)d_in[1];
    const float* value = (const float*)d_in[2];
    const float* dist  = (const float*)d_in[3];
    const int*   mask  = (const int*)d_in[4];
    const float* Wq = (const float*)d_in[5];
    const float* bq = (const float*)d_in[6];
    const float* Wk = (const float*)d_in[7];
    const float* bk = (const float*)d_in[8];
    const float* Wv = (const float*)d_in[9];
    const float* bv = (const float*)d_in[10];
    const float* Wo = (const float*)d_in[11];
    const float* bo = (const float*)d_in[12];
    float* out = (float*)d_out;

    cudaFuncSetAttribute(gemm_1t, cudaFuncAttributeMaxDynamicSharedMemorySize, G1_SMEM_BYTES);
    cudaFuncSetAttribute(gemm_mma, cudaFuncAttributeMaxDynamicSharedMemorySize, GEMM_SMEM_BYTES);
    cudaFuncSetAttribute(flash_mma, cudaFuncAttributeMaxDynamicSharedMemorySize, FLASH_SMEM);

    // 1) mask code precompute
    code_kernel<<<(Bb * Nn * Nn) / (8 * 256), 256>>>(dist, mask);

    // 2) conversions
    const int NX8 = (Bb * Nn * Ee) / 8;
    const int NW8 = (Ee * Ee) / 8;
    split_x_kernel<<<dim3(NX8 / 256, 3), 256>>>(query, key, value);
    split_w_kernel<<<dim3(NW8 / 256, 4), 256>>>(Wq, Wk, Wv, Wo);

    // 3) fused Q/K/V projections (1-term, chunk-64)
    gemm_1t<<<dim3((Bb * Nn) / 128, Ee / 128, 3), 256, G1_SMEM_BYTES>>>(bq, bk, bv);

    // 4) flash attention (3-stage, single-sync)
    flash_mma<<<dim3(Nn / 128, Hh, Bb), 256, FLASH_SMEM>>>();

    // 5) output projection (2-term, chunk-64)
    gemm_mma<<<dim3((Bb * Nn) / 128, Ee / 128), 256, GEMM_SMEM_BYTES>>>(bo, out);
}

// round 15
// speedup vs baseline: 2.7673x; 1.1145x over previous
#include <cuda_runtime.h>
#include <cuda_bf16.h>
#include <cuda_fp16.h>

#define Bb 8
#define Nn 1024
#define Ee 512
#define Hh 8
#define Dd 64
#define NEGV -1000000000.0f
#define SCL2 0.1803368801111204f   // 0.125 * log2(e)

typedef unsigned long long u64;
typedef unsigned int u32;

// ---------------------------------------------------------------------------
// Scratch (device globals; referenced only from device code)
// ---------------------------------------------------------------------------
__device__ unsigned char g_code[Bb*Nn*Nn];

__device__ __half gXs[3][Bb*Nn*Ee];          // inputs single fp16
__device__ __half gWs[4][Ee*Ee];             // weights single fp16

__device__ __half gQh[Bb*Hh*Nn*Dd];          // Q single fp16 [b,h,n,d]
__device__ __half gKh[Bb*Hh*Nn*Dd];          // K single fp16 [b,h,n,d]
__device__ __half gVth[Bb*Hh*Dd*Nn];         // V single fp16 transposed [b,h,d,n]
__device__ __half gAh[Bb*Nn*Ee];             // attn out single fp16 (1-term oproj)

// ---------------------------------------------------------------------------
// PTX helpers
// ---------------------------------------------------------------------------
__device__ __forceinline__ unsigned smem_u32(const void* p) {
    unsigned a;
    asm("{ .reg .u64 t; cvta.to.shared.u64 t, %1; cvt.u32.u64 %0, t; }"
        : "=r"(a) : "l"(p));
    return a;
}
__device__ __forceinline__ void cpasync16(unsigned dst, const void* src) {
    asm volatile("cp.async.ca.shared.global [%0], [%1], 16;" :: "r"(dst), "l"(src));
}
__device__ __forceinline__ void cpcommit() {
    asm volatile("cp.async.commit_group;" ::: "memory");
}
template<int N> __device__ __forceinline__ void cpwait() {
    asm volatile("cp.async.wait_group %0;" :: "n"(N) : "memory");
}
__device__ __forceinline__ void mma16816h(float* c, const u32* a, const u32* b) {
    asm volatile("mma.sync.aligned.m16n8k16.row.col.f32.f16.f16.f32 "
        "{%0,%1,%2,%3}, {%4,%5,%6,%7}, {%8,%9}, {%0,%1,%2,%3};"
        : "+f"(c[0]), "+f"(c[1]), "+f"(c[2]), "+f"(c[3])
        : "r"(a[0]), "r"(a[1]), "r"(a[2]), "r"(a[3]), "r"(b[0]), "r"(b[1]));
}
__device__ __forceinline__ void ldsm_x4(u32* r, unsigned addr) {
    asm volatile("ldmatrix.sync.aligned.m8n8.x4.shared.b16 {%0,%1,%2,%3}, [%4];"
        : "=r"(r[0]), "=r"(r[1]), "=r"(r[2]), "=r"(r[3]) : "r"(addr));
}
__device__ __forceinline__ void ldsm_x2(u32* r, unsigned addr) {
    asm volatile("ldmatrix.sync.aligned.m8n8.x2.shared.b16 {%0,%1}, [%2];"
        : "=r"(r[0]), "=r"(r[1]) : "r"(addr));
}
__device__ __forceinline__ float ex2(float x) {
    float y; asm("ex2.approx.f32 %0, %1;" : "=f"(y) : "f"(x)); return y;
}
__device__ __forceinline__ u32 packhf(float lo, float hi) {
    __half2 t = __floats2half2_rn(lo, hi);
    return *(u32*)&t;
}
__device__ __forceinline__ float2 h2ff(u32 v) {
    __half2 t; *(u32*)&t = v;
    return __half22float2(t);
}

// ---------------------------------------------------------------------------
// Fused prologue: code (blocks [0,4096)), X->fp16 ([4096,10240)),
// W->fp16 ([10240,10752))
// ---------------------------------------------------------------------------
__device__ __forceinline__ unsigned char code_one(float d, int mk, int i, int j) {
    if (mk == 0) return (unsigned char)255;
    if (i == 0 || j == 0) return (unsigned char)0;
    unsigned char c = 0;
    c += (d >= 0.2f); c += (d >= 0.3f); c += (d >= 0.4f); c += (d >= 0.5f);
    c += (d >= 0.6f); c += (d >= 0.7f); c += (d >= 0.8f); c += (d >= 0.9f);
    return c;
}

#define PREP_CODE_BLOCKS 4096
#define PREP_X_BLOCKS 2048
#define PREP_W_BLOCKS 128
#define PREP_TOTAL (PREP_CODE_BLOCKS + 3 * PREP_X_BLOCKS + 4 * PREP_W_BLOCKS)

__global__ __launch_bounds__(256) void prep_kernel(
    const float* __restrict__ dist, const int* __restrict__ mask,
    const float* __restrict__ xq, const float* __restrict__ xk,
    const float* __restrict__ xv,
    const float* __restrict__ w0, const float* __restrict__ w1,
    const float* __restrict__ w2, const float* __restrict__ w3)
{
    int bx = blockIdx.x;
    int tid = threadIdx.x;
    if (bx < PREP_CODE_BLOCKS) {
        int t = bx * 256 + tid;
        int base = t * 8;
        int rem = base & (Nn*Nn - 1);
        int i = rem >> 10;
        int j0 = rem & (Nn - 1);
        float4 dv0 = *(const float4*)(dist + base);
        float4 dv1 = *(const float4*)(dist + base + 4);
        int4  mv0 = *(const int4*)(mask + base);
        int4  mv1 = *(const int4*)(mask + base + 4);
        uchar4 o0, o1;
        o0.x = code_one(dv0.x, mv0.x, i, j0 + 0);
        o0.y = code_one(dv0.y, mv0.y, i, j0 + 1);
        o0.z = code_one(dv0.z, mv0.z, i, j0 + 2);
        o0.w = code_one(dv0.w, mv0.w, i, j0 + 3);
        o1.x = code_one(dv1.x, mv1.x, i, j0 + 4);
        o1.y = code_one(dv1.y, mv1.y, i, j0 + 5);
        o1.z = code_one(dv1.z, mv1.z, i, j0 + 6);
        o1.w = code_one(dv1.w, mv1.w, i, j0 + 7);
        uint2 pack;
        pack.x = *(u32*)&o0;
        pack.y = *(u32*)&o1;
        *(uint2*)(g_code + base) = pack;
    } else if (bx < PREP_CODE_BLOCKS + 3 * PREP_X_BLOCKS) {
        int lb = bx - PREP_CODE_BLOCKS;
        int which = lb / PREP_X_BLOCKS;
        int xb = lb - which * PREP_X_BLOCKS;
        const float* src = (which == 0) ? xq : (which == 1) ? xk : xv;
        int t0 = (xb * 256 + tid) * 2;
        u32* h2 = (u32*)gXs[which];
        float4 va = ((const float4*)src)[t0];
        float4 vb = ((const float4*)src)[t0 + 1];
        h2[2*t0+0] = packhf(va.x, va.y);
        h2[2*t0+1] = packhf(va.z, va.w);
        h2[2*t0+2] = packhf(vb.x, vb.y);
        h2[2*t0+3] = packhf(vb.z, vb.w);
    } else {
        int lb = bx - PREP_CODE_BLOCKS - 3 * PREP_X_BLOCKS;
        int which = lb / PREP_W_BLOCKS;
        int wb = lb - which * PREP_W_BLOCKS;
        const float* src = (which == 0) ? w0 : (which == 1) ? w1
                          : (which == 2) ? w2 : w3;
        int t0 = (wb * 256 + tid) * 2;
        u32* h2 = (u32*)gWs[which];
        float4 va = ((const float4*)src)[t0];
        float4 vb = ((const float4*)src)[t0 + 1];
        h2[2*t0+0] = packhf(va.x, va.y);
        h2[2*t0+1] = packhf(va.z, va.w);
        h2[2*t0+2] = packhf(vb.x, vb.y);
        h2[2*t0+3] = packhf(vb.z, vb.w);
    }
}

// K-chunk 64: rows are 64 halves + 8 pad = 72 (144B stride -> conflict-free)
#define TSTRIDE 72
#define TILE_US (128 * TSTRIDE)

// ---------------------------------------------------------------------------
// gemm_1t: 1-term fp16 GEMM. mode=0 (fused): blockIdx.z=0/1/2 -> Q/K/V proj.
// mode=1: oproj (A=gAh, W=gWs[3], fp32 flat out).
// ---------------------------------------------------------------------------
#define G1_SMEM_BYTES (4 * TILE_US * 2)      // 73728

__global__ __launch_bounds__(256, 2) void gemm_1t(const float* __restrict__ bias0,
                                                  const float* __restrict__ bias1,
                                                  const float* __restrict__ bias2,
                                                  float* __restrict__ outext,
                                                  int mode) {
    extern __shared__ unsigned short gsm[];
    unsigned sbase = smem_u32(gsm);

    int sel = mode ? 3 : blockIdx.z;
    const __half* Ahg = (sel < 3) ? gXs[sel] : gAh;
    const __half* Wsg = gWs[sel];
    const float* bias = (sel == 0 || sel == 3) ? bias0 : (sel == 1) ? bias1 : bias2;

    int tid = threadIdx.x;
    int wid = tid >> 5, lane = tid & 31;
    int wr = wid >> 2, wc = wid & 3;
    int gid = lane >> 2, tig = lane & 3;
    int m0 = blockIdx.x * 128, n0 = blockIdx.y * 128;

    int rA = lane & 15, kA = (lane >> 4) * 8;
    int rB = lane & 7,  kB = ((lane >> 3) & 1) * 8;

    float c[4][4][4];
    #pragma unroll
    for (int mt = 0; mt < 4; mt++)
        #pragma unroll
        for (int nt = 0; nt < 4; nt++)
            #pragma unroll
            for (int q = 0; q < 4; q++) c[mt][nt][q] = 0.0f;

    auto load_chunk = [&](int kc, int buf) {
        int kb = kc * 64;
        unsigned base = (unsigned)(buf * 2 * TILE_US);
        #pragma unroll
        for (int l = 0; l < 4; l++) {
            int idx = tid + l * 256;
            int row = idx >> 3, c8 = (idx & 7) * 8;
            unsigned so = (row * TSTRIDE + c8) * 2;
            cpasync16(sbase + base * 2 + so, Ahg + (m0 + row) * Ee + kb + c8);
            cpasync16(sbase + (base + TILE_US) * 2 + so, Wsg + (n0 + row) * Ee + kb + c8);
        }
        cpcommit();
    };

    load_chunk(0, 0);

    for (int kc = 0; kc < 8; kc++) {
        int buf = kc & 1;
        if (kc < 7) load_chunk(kc + 1, buf ^ 1);
        if (kc < 7) cpwait<1>(); else cpwait<0>();
        __syncthreads();

        unsigned base = (unsigned)(buf * 2 * TILE_US);
        unsigned ah_b = sbase + base * 2;
        unsigned wh_b = sbase + (base + TILE_US) * 2;

        #pragma unroll
        for (int ks = 0; ks < 4; ks++) {
            int k0 = ks * 16;
            u32 bh[4][2];
            #pragma unroll
            for (int nt = 0; nt < 4; nt++) {
                unsigned boff = ((wc * 32 + nt * 8 + rB) * TSTRIDE + k0 + kB) * 2;
                ldsm_x2(bh[nt], wh_b + boff);
            }
            #pragma unroll
            for (int mt = 0; mt < 4; mt++) {
                unsigned aoff = ((wr * 64 + mt * 16 + rA) * TSTRIDE + k0 + kA) * 2;
                u32 ah[4];
                ldsm_x4(ah, ah_b + aoff);
                #pragma unroll
                for (int nt = 0; nt < 4; nt++)
                    mma16816h(c[mt][nt], ah, bh[nt]);
            }
        }
        __syncthreads();
    }

    // Epilogue
    #pragma unroll
    for (int mt = 0; mt < 4; mt++) {
        #pragma unroll
        for (int nt = 0; nt < 4; nt++) {
            int row = m0 + wr * 64 + mt * 16 + gid;
            int col = n0 + wc * 32 + nt * 8 + tig * 2;
            float b0v = bias[col], b1v = bias[col + 1];
            float v00 = c[mt][nt][0] + b0v, v01 = c[mt][nt][1] + b1v;
            float v10 = c[mt][nt][2] + b0v, v11 = c[mt][nt][3] + b1v;
            int b_ = row >> 10, n = row & (Nn - 1);
            int hh = col >> 6, d = col & 63;
            if (sel <= 1) {
                __half* Hp = (sel == 0) ? gQh : gKh;
                int a0 = (((b_ << 3) + hh) * Nn + n) * Dd + d;
                int a1 = a0 + 8 * Dd;
                *(u32*)(Hp + a0) = packhf(v00, v01);
                *(u32*)(Hp + a1) = packhf(v10, v11);
            } else if (sel == 2) {
                int base = ((b_ << 3) + hh) * Dd;
                int i00 = (base + d) * Nn + n;
                int i01 = (base + d + 1) * Nn + n;
                gVth[i00]     = __float2half(v00);
                gVth[i01]     = __float2half(v01);
                gVth[i00 + 8] = __float2half(v10);
                gVth[i01 + 8] = __float2half(v11);
            } else {
                *(float2*)(outext + row * Ee + col) = make_float2(v00, v01);
                *(float2*)(outext + (row + 8) * Ee + col) = make_float2(v10, v11);
            }
        }
    }
}

// ---------------------------------------------------------------------------
// HMMA flash attention: QK 1-term, PV 1-term.
// 3-stage K/V pipeline, ONE __syncthreads per iteration, base-2 softmax.
// (R14 verbatim except epilogue writes single-fp16 gAh.)
// ---------------------------------------------------------------------------
#define FTS 72
#define FQ_H 0
#define FSTG0 (128 * FTS)
#define FSTG_SZ (2 * 64 * FTS)
#define FV_OFF (64 * FTS)
#define FLASH_SMEM ((FSTG0 + 3 * FSTG_SZ) * 2)   // 73728 bytes

__global__ __launch_bounds__(256, 2) void flash_mma() {
    extern __shared__ unsigned short fsm[];
    unsigned sbase = smem_u32(fsm);

    int rb = blockIdx.x, h = blockIdx.y, b = blockIdx.z;
    int tid = threadIdx.x, wid = tid >> 5, lane = tid & 31;
    int gid = lane >> 2, tig = lane & 3;
    int bh = b * Hh + h;

    const __half* Qhg = gQh + (bh * Nn + rb * 128) * Dd;
    const __half* Khg = gKh + bh * Nn * Dd;
    const __half* Vhg = gVth + bh * Dd * Nn;
    const unsigned char* codeg = g_code + (b * Nn + rb * 128) * Nn;

    int rA = lane & 15, kA = (lane >> 4) * 8;
    int rB = lane & 7,  kB = ((lane >> 3) & 1) * 8;

    auto load_kv = [&](int kb, int s) {
        unsigned stg = (unsigned)(FSTG0 + s * FSTG_SZ);
        #pragma unroll
        for (int l = 0; l < 2; l++) {
            int idx = tid + l * 256;
            int row = idx >> 3, c8 = (idx & 7) * 8;
            unsigned so = (row * FTS + c8) * 2;
            cpasync16(sbase + stg * 2 + so, Khg + (kb * 64 + row) * Dd + c8);
            cpasync16(sbase + (stg + FV_OFF) * 2 + so, Vhg + row * Nn + kb * 64 + c8);
        }
        cpcommit();
    };

    // Prologue: Q + stage0 (group 0), stage1 (group 1)
    #pragma unroll
    for (int l = 0; l < 4; l++) {
        int idx = tid + l * 256;
        int row = idx >> 3, c8 = (idx & 7) * 8;
        cpasync16(sbase + (FQ_H + row * FTS + c8) * 2, Qhg + row * Dd + c8);
    }
    load_kv(0, 0);
    load_kv(1, 1);

    unsigned qh_base = sbase + ((FQ_H + (wid * 16 + rA) * FTS + kA) * 2);

    float co[8][4];
    #pragma unroll
    for (int dt = 0; dt < 8; dt++)
        #pragma unroll
        for (int q = 0; q < 4; q++) co[dt][q] = 0.0f;
    float m0r = -1e30f, m1r = -1e30f, l0r = 0.0f, l1r = 0.0f;

    int crow0 = wid * 16 + gid;
    const unsigned char* cp0 = codeg + crow0 * Nn + tig * 2;
    const unsigned char* cp1 = codeg + (crow0 + 8) * Nn + tig * 2;

    for (int kb = 0; kb < 16; kb++) {
        if (kb < 15) cpwait<1>(); else cpwait<0>();
        __syncthreads();
        if (kb < 14) load_kv(kb + 2, (kb + 2) % 3);

        unsigned short cw0[8], cw1[8];
        #pragma unroll
        for (int nt = 0; nt < 8; nt++) {
            cw0[nt] = *(const unsigned short*)(cp0 + kb * 64 + nt * 8);
            cw1[nt] = *(const unsigned short*)(cp1 + kb * 64 + nt * 8);
        }

        unsigned stg = (unsigned)(FSTG0 + (kb % 3) * FSTG_SZ);
        unsigned kh_b = sbase + stg * 2;
        unsigned vh_b = sbase + (stg + FV_OFF) * 2;

        // ---- S = Q.K^T ----
        float sc[8][4];
        #pragma unroll
        for (int nt = 0; nt < 8; nt++)
            #pragma unroll
            for (int q = 0; q < 4; q++) sc[nt][q] = 0.0f;

        #pragma unroll
        for (int ks = 0; ks < 4; ks++) {
            u32 ah[4];
            ldsm_x4(ah, qh_base + ks * 32);
            #pragma unroll
            for (int nt = 0; nt < 8; nt++) {
                unsigned kaddr = kh_b + ((nt * 8 + rB) * FTS + ks * 16 + kB) * 2;
                u32 bh2[2];
                ldsm_x2(bh2, kaddr);
                mma16816h(sc[nt], ah, bh2);
            }
        }

        // ---- mask + scale (log2 domain) ----
        #pragma unroll
        for (int nt = 0; nt < 8; nt++) {
            sc[nt][0] = ((unsigned)h >= (cw0[nt] & 255u)) ? sc[nt][0] * SCL2 : NEGV;
            sc[nt][1] = ((unsigned)h >= (cw0[nt] >> 8))   ? sc[nt][1] * SCL2 : NEGV;
            sc[nt][2] = ((unsigned)h >= (cw1[nt] & 255u)) ? sc[nt][2] * SCL2 : NEGV;
            sc[nt][3] = ((unsigned)h >= (cw1[nt] >> 8))   ? sc[nt][3] * SCL2 : NEGV;
        }

        // ---- online softmax (base 2) ----
        float rm0 = -1e30f, rm1 = -1e30f;
        #pragma unroll
        for (int nt = 0; nt < 8; nt++) {
            rm0 = fmaxf(rm0, fmaxf(sc[nt][0], sc[nt][1]));
            rm1 = fmaxf(rm1, fmaxf(sc[nt][2], sc[nt][3]));
        }
        rm0 = fmaxf(rm0, __shfl_xor_sync(0xffffffffu, rm0, 1));
        rm0 = fmaxf(rm0, __shfl_xor_sync(0xffffffffu, rm0, 2));
        rm1 = fmaxf(rm1, __shfl_xor_sync(0xffffffffu, rm1, 1));
        rm1 = fmaxf(rm1, __shfl_xor_sync(0xffffffffu, rm1, 2));
        float mn0 = fmaxf(m0r, rm0), mn1 = fmaxf(m1r, rm1);
        float corr0 = ex2(m0r - mn0), corr1 = ex2(m1r - mn1);
        m0r = mn0; m1r = mn1;

        float ps0 = 0.0f, ps1 = 0.0f;
        #pragma unroll
        for (int nt = 0; nt < 8; nt++) {
            sc[nt][0] = ex2(sc[nt][0] - mn0);
            sc[nt][1] = ex2(sc[nt][1] - mn0);
            sc[nt][2] = ex2(sc[nt][2] - mn1);
            sc[nt][3] = ex2(sc[nt][3] - mn1);
            ps0 += sc[nt][0] + sc[nt][1];
            ps1 += sc[nt][2] + sc[nt][3];
        }
        ps0 += __shfl_xor_sync(0xffffffffu, ps0, 1);
        ps0 += __shfl_xor_sync(0xffffffffu, ps0, 2);
        ps1 += __shfl_xor_sync(0xffffffffu, ps1, 1);
        ps1 += __shfl_xor_sync(0xffffffffu, ps1, 2);
        l0r = l0r * corr0 + ps0;
        l1r = l1r * corr1 + ps1;

        #pragma unroll
        for (int dt = 0; dt < 8; dt++) {
            co[dt][0] *= corr0; co[dt][1] *= corr0;
            co[dt][2] *= corr1; co[dt][3] *= corr1;
        }

        // ---- O += P.V ----
        #pragma unroll
        for (int kc = 0; kc < 4; kc++) {
            u32 pah[4];
            pah[0] = packhf(sc[2*kc][0],   sc[2*kc][1]);
            pah[1] = packhf(sc[2*kc][2],   sc[2*kc][3]);
            pah[2] = packhf(sc[2*kc+1][0], sc[2*kc+1][1]);
            pah[3] = packhf(sc[2*kc+1][2], sc[2*kc+1][3]);
            #pragma unroll
            for (int dt = 0; dt < 8; dt++) {
                unsigned vaddr = vh_b + ((dt * 8 + rB) * FTS + kc * 16 + kB) * 2;
                u32 vh2[2];
                ldsm_x2(vh2, vaddr);
                mma16816h(co[dt], pah, vh2);
            }
        }
    }

    // ---- epilogue: O / l -> gAh single fp16 ----
    float inv0 = 1.0f / l0r, inv1 = 1.0f / l1r;
    int nrow = rb * 128 + wid * 16 + gid;
    int a0base = ((b << 10) + nrow) * Ee + (h << 6);
    int a1base = a0base + 8 * Ee;
    #pragma unroll
    for (int dt = 0; dt < 8; dt++) {
        int d = dt * 8 + tig * 2;
        *(u32*)(gAh + a0base + d) = packhf(co[dt][0] * inv0, co[dt][1] * inv0);
        *(u32*)(gAh + a1base + d) = packhf(co[dt][2] * inv1, co[dt][3] * inv1);
    }
}

// ---------------------------------------------------------------------------
extern "C" void kernel_launch(void* const* d_in, const int* in_sizes, int n_in,
                              void* d_out, int out_size) {
    const float* query = (const float*)d_in[0];
    const float* key   = (const float*)d_in[1];
    const float* value = (const float*)d_in[2];
    const float* dist  = (const float*)d_in[3];
    const int*   mask  = (const int*)d_in[4];
    const float* Wq = (const float*)d_in[5];
    const float* bq = (const float*)d_in[6];
    const float* Wk = (const float*)d_in[7];
    const float* bk = (const float*)d_in[8];
    const float* Wv = (const float*)d_in[9];
    const float* bv = (const float*)d_in[10];
    const float* Wo = (const float*)d_in[11];
    const float* bo = (const float*)d_in[12];
    float* out = (float*)d_out;

    cudaFuncSetAttribute(gemm_1t, cudaFuncAttributeMaxDynamicSharedMemorySize, G1_SMEM_BYTES);
    cudaFuncSetAttribute(flash_mma, cudaFuncAttributeMaxDynamicSharedMemorySize, FLASH_SMEM);

    // 1) fused prologue: mask codes + fp16 conversions
    prep_kernel<<<PREP_TOTAL, 256>>>(dist, mask, query, key, value, Wq, Wk, Wv, Wo);

    // 2) fused Q/K/V projections (1-term, chunk-64)
    gemm_1t<<<dim3((Bb * Nn) / 128, Ee / 128, 3), 256, G1_SMEM_BYTES>>>(
        bq, bk, bv, nullptr, 0);

    // 3) flash attention (3-stage, single-sync)
    flash_mma<<<dim3(Nn / 128, Hh, Bb), 256, FLASH_SMEM>>>();

    // 4) output projection (1-term, chunk-64)
    gemm_1t<<<dim3((Bb * Nn) / 128, Ee / 128, 1), 256, G1_SMEM_BYTES>>>(
        bo, nullptr, nullptr, out, 1);
}